// round 7
// baseline (speedup 1.0000x reference)
#include <cuda_runtime.h>
#include <cuda_bf16.h>
#include <cuda_fp16.h>
#include <math.h>
#include <stdint.h>

// Problem constants
#define DIMC   1152
#define NH     8
#define KVH    2
#define HD     144
#define BSZ    4
#define SEQ    2048
#define MROWS  (BSZ*SEQ)          // 8192
#define KVOUT  (2*KVH*HD)         // 576
#define K2DIM  (DIMC/2)           // 576
#define KP     72                 // pairs per head row
#define TPH    (SEQ/2)            // seq pairs for V^T

// ---------------- scratch (device globals) ----------------------------------
__device__ float g_kv  [(size_t)MROWS * KVOUT];

__device__ uint32_t g_xh [(size_t)MROWS * K2DIM];
__device__ uint32_t g_xl [(size_t)MROWS * K2DIM];
__device__ uint32_t g_wqh[(size_t)DIMC  * K2DIM];
__device__ uint32_t g_wql[(size_t)DIMC  * K2DIM];
__device__ uint32_t g_wkh[(size_t)KVOUT * K2DIM];
__device__ uint32_t g_wkl[(size_t)KVOUT * K2DIM];
__device__ uint32_t g_woh[(size_t)DIMC  * K2DIM];
__device__ uint32_t g_wol[(size_t)DIMC  * K2DIM];
__device__ uint32_t g_ah [(size_t)MROWS * K2DIM];   // attn out hi (bf16)
__device__ uint32_t g_al [(size_t)MROWS * K2DIM];   // attn out lo (bf16)

// attention operands
__device__ uint32_t g_qh[(size_t)BSZ*NH *SEQ*KP];   // bf16 pairs
__device__ uint32_t g_ql[(size_t)BSZ*NH *SEQ*KP];
__device__ uint32_t g_kh[(size_t)BSZ*KVH*SEQ*KP];
__device__ uint32_t g_kl[(size_t)BSZ*KVH*SEQ*KP];
__device__ uint32_t g_vh[(size_t)BSZ*KVH*HD*TPH];   // V^T fp16 hi, pairs along s
__device__ uint32_t g_vl[(size_t)BSZ*KVH*HD*TPH];   // V^T fp16 lo

// ---------------- helpers ----------------------------------------------------
__device__ __forceinline__ uint32_t smem_u32(const void* p) {
    uint32_t a;
    asm("{ .reg .u64 t; cvta.to.shared.u64 t, %1; cvt.u32.u64 %0, t; }"
        : "=r"(a) : "l"(p));
    return a;
}

__device__ __forceinline__ void split2(float x, float y, uint32_t& hi, uint32_t& lo)
{
    __nv_bfloat162 h = __floats2bfloat162_rn(x, y);
    float hx = __bfloat162float(h.x), hy = __bfloat162float(h.y);
    __nv_bfloat162 l = __floats2bfloat162_rn(x - hx, y - hy);
    hi = *reinterpret_cast<uint32_t*>(&h);
    lo = *reinterpret_cast<uint32_t*>(&l);
}

__device__ __forceinline__ void split2h(float x, float y, uint32_t& hi, uint32_t& lo)
{
    __half2 h = __floats2half2_rn(x, y);
    float2 hf = __half22float2(h);
    __half2 l = __floats2half2_rn(x - hf.x, y - hf.y);
    hi = *reinterpret_cast<uint32_t*>(&h);
    lo = *reinterpret_cast<uint32_t*>(&l);
}

__device__ __forceinline__ void mma16816(float* c, const uint32_t* a, const uint32_t* b)
{
    asm volatile(
        "mma.sync.aligned.m16n8k16.row.col.f32.bf16.bf16.f32 "
        "{%0,%1,%2,%3}, {%4,%5,%6,%7}, {%8,%9}, {%0,%1,%2,%3};\n"
        : "+f"(c[0]), "+f"(c[1]), "+f"(c[2]), "+f"(c[3])
        : "r"(a[0]), "r"(a[1]), "r"(a[2]), "r"(a[3]), "r"(b[0]), "r"(b[1]));
}

__device__ __forceinline__ void mma16816h(float* c, const uint32_t* a, const uint32_t* b)
{
    asm volatile(
        "mma.sync.aligned.m16n8k16.row.col.f32.f16.f16.f32 "
        "{%0,%1,%2,%3}, {%4,%5,%6,%7}, {%8,%9}, {%0,%1,%2,%3};\n"
        : "+f"(c[0]), "+f"(c[1]), "+f"(c[2]), "+f"(c[3])
        : "r"(a[0]), "r"(a[1]), "r"(a[2]), "r"(a[3]), "r"(b[0]), "r"(b[1]));
}

__device__ __forceinline__ void ldsm4(uint32_t& r0, uint32_t& r1, uint32_t& r2,
                                      uint32_t& r3, uint32_t a)
{
    asm volatile("ldmatrix.sync.aligned.m8n8.x4.shared.b16 {%0,%1,%2,%3}, [%4];"
                 : "=r"(r0), "=r"(r1), "=r"(r2), "=r"(r3) : "r"(a));
}

#define CP_ASYNC16(sa, gp) \
    asm volatile("cp.async.cg.shared.global [%0], [%1], 16;" :: "r"(sa), "l"(gp))
#define CP_COMMIT() asm volatile("cp.async.commit_group;" ::: "memory")
#define CP_WAIT1()  asm volatile("cp.async.wait_group 1;" ::: "memory")
#define CP_WAIT0()  asm volatile("cp.async.wait_group 0;" ::: "memory")

// ---------------- fp32 -> (hi, lo) packed bf16x2 ----------------------------
__global__ void split_bf16(const float* __restrict__ src,
                           uint32_t* __restrict__ hi, uint32_t* __restrict__ lo,
                           int n2)
{
    int i = blockIdx.x * blockDim.x + threadIdx.x;
    if (i >= n2) return;
    float2 v = ((const float2*)src)[i];
    split2(v.x, v.y, hi[i], lo[i]);
}

// ---------------- split-bf16 GEMM (ldmatrix + cp.async) ---------------------
// MODE 0: C = A@B^T + bias (fp32 store)
// MODE 1: Q projection: rope + scale + bf16-split -> qh/ql [b*NH+h][s][KP]
#define GB_ROWB 80
#define GB_ARR  (128 * GB_ROWB)
#define GB_BUF  (4 * GB_ARR)
#define GB_SMEM (2 * GB_BUF)          // 81920 B

template <int MODE>
__global__ __launch_bounds__(256, 2)
void gemm_ldsm(const uint32_t* __restrict__ Ahg, const uint32_t* __restrict__ Alg,
               const uint32_t* __restrict__ Bhg, const uint32_t* __restrict__ Blg,
               const float* __restrict__ bias, float* __restrict__ C,
               int M, int N, int K2,
               const float* __restrict__ fc, const float* __restrict__ fs,
               uint32_t* __restrict__ qho, uint32_t* __restrict__ qlo)
{
    extern __shared__ char smem[];
    const uint32_t sbase = smem_u32(smem);
    const int tid = threadIdx.x;
    const int warp = tid >> 5, lane = tid & 31;
    const int wm = (warp & 1) * 64;
    const int wn = (warp >> 1) * 32;
    const int m0 = blockIdx.y * 128;
    const int n0 = blockIdx.x * 128;
    const int nch = K2 / 16;

    const int srow = tid >> 2;
    const int schk = tid & 3;
    const int br0 = (n0 + srow     < N) ? n0 + srow      : N - 1;
    const int br1 = (n0 + srow + 64 < N) ? n0 + srow + 64 : N - 1;

    float acc[4][4][4];
#pragma unroll
    for (int i = 0; i < 4; i++)
#pragma unroll
        for (int j = 0; j < 4; j++)
#pragma unroll
            for (int t = 0; t < 4; t++) acc[i][j][t] = 0.f;

    const int lrow = lane & 15;
    const int lch = lane >> 4;

#define GB_ISSUE(ch) do { \
    const int _buf = (ch) & 1; \
    const uint32_t _sb = sbase + _buf * GB_BUF; \
    const size_t _kc = (size_t)(ch) * 16 + schk * 4; \
    uint32_t _so0 = _sb + srow * GB_ROWB + schk * 16; \
    uint32_t _so1 = _sb + (srow + 64) * GB_ROWB + schk * 16; \
    CP_ASYNC16(_so0,              Ahg + (size_t)(m0 + srow) * K2 + _kc); \
    CP_ASYNC16(_so1,              Ahg + (size_t)(m0 + srow + 64) * K2 + _kc); \
    CP_ASYNC16(_so0 + GB_ARR,     Alg + (size_t)(m0 + srow) * K2 + _kc); \
    CP_ASYNC16(_so1 + GB_ARR,     Alg + (size_t)(m0 + srow + 64) * K2 + _kc); \
    CP_ASYNC16(_so0 + 2*GB_ARR,   Bhg + (size_t)br0 * K2 + _kc); \
    CP_ASYNC16(_so1 + 2*GB_ARR,   Bhg + (size_t)br1 * K2 + _kc); \
    CP_ASYNC16(_so0 + 3*GB_ARR,   Blg + (size_t)br0 * K2 + _kc); \
    CP_ASYNC16(_so1 + 3*GB_ARR,   Blg + (size_t)br1 * K2 + _kc); \
} while (0)

    GB_ISSUE(0); CP_COMMIT();

    for (int ch = 0; ch < nch; ch++) {
        if (ch + 1 < nch) { GB_ISSUE(ch + 1); CP_COMMIT(); CP_WAIT1(); }
        else              { CP_WAIT0(); }
        __syncthreads();

        const uint32_t sb = sbase + (ch & 1) * GB_BUF;
        const uint32_t aH = sb + (wm + lrow) * GB_ROWB + lch * 16;
        const uint32_t aL = aH + GB_ARR;
        const uint32_t bH = sb + 2 * GB_ARR + (wn + lrow) * GB_ROWB + lch * 16;
        const uint32_t bL = bH + GB_ARR;

#pragma unroll
        for (int kk = 0; kk < 2; kk++) {
            uint32_t bh[4][2], bl[4][2];
#pragma unroll
            for (int jj = 0; jj < 2; jj++) {
                uint32_t r0, r1, r2, r3;
                ldsm4(r0, r1, r2, r3, bH + jj * (16 * GB_ROWB) + kk * 32);
                bh[2*jj][0] = r0; bh[2*jj][1] = r2;
                bh[2*jj+1][0] = r1; bh[2*jj+1][1] = r3;
                ldsm4(r0, r1, r2, r3, bL + jj * (16 * GB_ROWB) + kk * 32);
                bl[2*jj][0] = r0; bl[2*jj][1] = r2;
                bl[2*jj+1][0] = r1; bl[2*jj+1][1] = r3;
            }
#pragma unroll
            for (int i = 0; i < 4; i++) {
                uint32_t ah[4], al[4];
                ldsm4(ah[0], ah[1], ah[2], ah[3], aH + i * (16 * GB_ROWB) + kk * 32);
                ldsm4(al[0], al[1], al[2], al[3], aL + i * (16 * GB_ROWB) + kk * 32);
#pragma unroll
                for (int j = 0; j < 4; j++) {
                    mma16816(acc[i][j], ah, bh[j]);
                    mma16816(acc[i][j], ah, bl[j]);
                    mma16816(acc[i][j], al, bh[j]);
                }
            }
        }
        __syncthreads();
    }

    const int lr = lane >> 2, lc = lane & 3;
    if (MODE == 0) {
#pragma unroll
        for (int i = 0; i < 4; i++) {
            int r0 = m0 + wm + i * 16 + lr;
#pragma unroll
            for (int j = 0; j < 4; j++) {
                int c0 = n0 + wn + j * 8 + lc * 2;
                if (c0 < N) {
                    float2 bb = *(const float2*)&bias[c0];
                    *(float2*)&C[(size_t)r0 * N + c0] =
                        make_float2(acc[i][j][0] + bb.x, acc[i][j][1] + bb.y);
                    *(float2*)&C[(size_t)(r0 + 8) * N + c0] =
                        make_float2(acc[i][j][2] + bb.x, acc[i][j][3] + bb.y);
                }
            }
        }
    } else {
        // fused rope + scale + bf16 split for Q
        const float scale = 0.083333333333333329f;
#pragma unroll
        for (int i = 0; i < 4; i++) {
            int r0 = m0 + wm + i * 16 + lr;
            int s0 = r0 & (SEQ - 1), b0 = r0 >> 11;
            int s1 = (r0 + 8) & (SEQ - 1);
#pragma unroll
            for (int j = 0; j < 4; j++) {
                int c0 = n0 + wn + j * 8 + lc * 2;
                int h = c0 / HD;
                int ip = (c0 - h * HD) >> 1;
                float2 bb = *(const float2*)&bias[c0];
                // row r0
                {
                    float q0 = acc[i][j][0] + bb.x, q1 = acc[i][j][1] + bb.y;
                    float cc = fc[s0 * KP + ip], sn = fs[s0 * KP + ip];
                    uint32_t H, L;
                    split2((q0 * cc - q1 * sn) * scale,
                           (q0 * sn + q1 * cc) * scale, H, L);
                    size_t o = ((size_t)(b0 * NH + h) * SEQ + s0) * KP + ip;
                    qho[o] = H; qlo[o] = L;
                }
                // row r0 + 8
                {
                    float q0 = acc[i][j][2] + bb.x, q1 = acc[i][j][3] + bb.y;
                    float cc = fc[s1 * KP + ip], sn = fs[s1 * KP + ip];
                    uint32_t H, L;
                    split2((q0 * cc - q1 * sn) * scale,
                           (q0 * sn + q1 * cc) * scale, H, L);
                    size_t o = ((size_t)(b0 * NH + h) * SEQ + s1) * KP + ip;
                    qho[o] = H; qlo[o] = L;
                }
            }
        }
    }
#undef GB_ISSUE
}

// ---------------- RoPE K -> split bf16 --------------------------------------
__global__ void rope_k_split(const float* __restrict__ KV,
                             const float* __restrict__ fc, const float* __restrict__ fs,
                             uint32_t* __restrict__ kh, uint32_t* __restrict__ kl)
{
    int idx = blockIdx.x * blockDim.x + threadIdx.x;
    const int total = BSZ * KVH * SEQ * KP;
    if (idx >= total) return;
    int i = idx % KP;
    int s = (idx / KP) % SEQ;
    int kvh = (idx / (KP * SEQ)) % KVH;
    int b = idx / (KP * SEQ * KVH);

    size_t base = (size_t)(b * SEQ + s) * KVOUT + kvh * HD;
    float k0 = KV[base + 2 * i];
    float k1 = KV[base + 2 * i + 1];
    float c = fc[s * KP + i];
    float sn = fs[s * KP + i];
    split2(k0 * c - k1 * sn, k0 * sn + k1 * c, kh[idx], kl[idx]);
}

// V transpose + fp16 split: out [b*KVH+kvh][d][sp], pairs along s.
__global__ void v_trans_split(const float* __restrict__ KV,
                              uint32_t* __restrict__ vh, uint32_t* __restrict__ vl)
{
    __shared__ float tile[64][HD + 1];
    const int st = blockIdx.x;
    const int bk = blockIdx.y;
    const int b = bk / KVH, kvh = bk % KVH;
    const int tid = threadIdx.x;

    const float* src = KV + (size_t)(b * SEQ + st * 64) * KVOUT + KVH * HD + kvh * HD;
    for (int e = tid; e < 64 * HD; e += 256) {
        int r = e / HD, c = e % HD;
        tile[r][c] = src[(size_t)r * KVOUT + c];
    }
    __syncthreads();

    uint32_t* oh = vh + ((size_t)bk * HD) * TPH + st * 32;
    uint32_t* ol = vl + ((size_t)bk * HD) * TPH + st * 32;
    for (int e = tid; e < HD * 32; e += 256) {
        int d = e / 32, sp = e % 32;
        uint32_t h, l;
        split2h(tile[2 * sp][d], tile[2 * sp + 1][d], h, l);
        oh[(size_t)d * TPH + sp] = h;
        ol[(size_t)d * TPH + sp] = l;
    }
}

// ---------------- Flash attention -------------------------------------------
// QK: bf16 3-pass.  PV: fp16 2-pass (P single fp16, V fp16 hi/lo).
// Epilogue writes bf16 hi/lo split directly (feeds O projection).
#define QS 76
#define KS 76
#define VS 36

#define FLASH_SMEM ((2*128*QS + 2*64*KS + 2*HD*VS) * (int)sizeof(uint32_t))

__global__ __launch_bounds__(256, 1)
void flash_mma(const uint32_t* __restrict__ qh, const uint32_t* __restrict__ ql,
               const uint32_t* __restrict__ kh, const uint32_t* __restrict__ kl,
               const uint32_t* __restrict__ vh, const uint32_t* __restrict__ vl,
               uint32_t* __restrict__ oh, uint32_t* __restrict__ ol)
{
    extern __shared__ uint32_t fsm[];
    uint32_t* sQh = fsm;
    uint32_t* sQl = sQh + 128 * QS;
    uint32_t* sKh = sQl + 128 * QS;
    uint32_t* sKl = sKh + 64 * KS;
    uint32_t* sVh = sKl + 64 * KS;
    uint32_t* sVl = sVh + HD * VS;

    const int qt = (gridDim.x - 1) - blockIdx.x;
    const int bh = blockIdx.y;
    const int b = bh >> 3;
    const int h = bh & 7;
    const int kvh = h >> 2;
    const int bk = b * KVH + kvh;

    const int tid = threadIdx.x;
    const int warp = tid >> 5, lane = tid & 31;
    const int lr = lane >> 2, lc = lane & 3;
    const int wm = warp * 16;

    {
        const uint32_t* gqh = qh + ((size_t)bh * SEQ + qt * 128) * KP;
        const uint32_t* gql = ql + ((size_t)bh * SEQ + qt * 128) * KP;
        for (int e = tid; e < 128 * 18; e += 256) {
            int r = e / 18, c = (e % 18) * 4;
            *(uint4*)&sQh[r * QS + c] = *(const uint4*)&gqh[(size_t)r * KP + c];
            *(uint4*)&sQl[r * QS + c] = *(const uint4*)&gql[(size_t)r * KP + c];
        }
    }

    float o[18][4];
#pragma unroll
    for (int n = 0; n < 18; n++)
#pragma unroll
        for (int t = 0; t < 4; t++) o[n][t] = 0.f;
    float m0 = -1e30f, m1 = -1e30f, l0 = 0.f, l1 = 0.f;

    const int ktmax = 2 * qt + 1;
    const int qrow0 = qt * 128 + wm;

    for (int kt = 0; kt <= ktmax; kt++) {
        __syncthreads();
        {
            const uint32_t* gkh = kh + ((size_t)bk * SEQ + kt * 64) * KP;
            const uint32_t* gkl = kl + ((size_t)bk * SEQ + kt * 64) * KP;
            for (int e = tid; e < 64 * 18; e += 256) {
                int r = e / 18, c = (e % 18) * 4;
                *(uint4*)&sKh[r * KS + c] = *(const uint4*)&gkh[(size_t)r * KP + c];
                *(uint4*)&sKl[r * KS + c] = *(const uint4*)&gkl[(size_t)r * KP + c];
            }
            const uint32_t* gvh = vh + (size_t)bk * HD * TPH + kt * 32;
            const uint32_t* gvl = vl + (size_t)bk * HD * TPH + kt * 32;
            for (int e = tid; e < HD * 8; e += 256) {
                int r = e / 8, c = (e % 8) * 4;
                *(uint4*)&sVh[r * VS + c] = *(const uint4*)&gvh[(size_t)r * TPH + c];
                *(uint4*)&sVl[r * VS + c] = *(const uint4*)&gvl[(size_t)r * TPH + c];
            }
        }
        __syncthreads();

        float sfr[8][4];
#pragma unroll
        for (int j = 0; j < 8; j++)
#pragma unroll
            for (int t = 0; t < 4; t++) sfr[j][t] = 0.f;

#pragma unroll
        for (int kc = 0; kc < 9; kc++) {
            uint32_t ah[4], al[4];
            int ra = (wm + lr) * QS + kc * 8 + lc;
            int rb = (wm + lr + 8) * QS + kc * 8 + lc;
            ah[0] = sQh[ra];     ah[1] = sQh[rb];
            ah[2] = sQh[ra + 4]; ah[3] = sQh[rb + 4];
            al[0] = sQl[ra];     al[1] = sQl[rb];
            al[2] = sQl[ra + 4]; al[3] = sQl[rb + 4];
#pragma unroll
            for (int j = 0; j < 8; j++) {
                int rk = (j * 8 + lr) * KS + kc * 8 + lc;
                uint32_t bh2[2] = { sKh[rk], sKh[rk + 4] };
                uint32_t bl2[2] = { sKl[rk], sKl[rk + 4] };
                mma16816(sfr[j], ah, bh2);
                mma16816(sfr[j], ah, bl2);
                mma16816(sfr[j], al, bh2);
            }
        }

        if (kt * 64 + 63 > qrow0) {
            int key0 = kt * 64;
#pragma unroll
            for (int j = 0; j < 8; j++) {
                int kc0 = key0 + j * 8 + 2 * lc;
                if (kc0     > qrow0 + lr)     sfr[j][0] = -1e9f;
                if (kc0 + 1 > qrow0 + lr)     sfr[j][1] = -1e9f;
                if (kc0     > qrow0 + lr + 8) sfr[j][2] = -1e9f;
                if (kc0 + 1 > qrow0 + lr + 8) sfr[j][3] = -1e9f;
            }
        }

        float mx0 = -1e30f, mx1 = -1e30f;
#pragma unroll
        for (int j = 0; j < 8; j++) {
            mx0 = fmaxf(mx0, fmaxf(sfr[j][0], sfr[j][1]));
            mx1 = fmaxf(mx1, fmaxf(sfr[j][2], sfr[j][3]));
        }
#pragma unroll
        for (int off = 1; off < 4; off <<= 1) {
            mx0 = fmaxf(mx0, __shfl_xor_sync(0xffffffffu, mx0, off));
            mx1 = fmaxf(mx1, __shfl_xor_sync(0xffffffffu, mx1, off));
        }
        float mn0 = fmaxf(m0, mx0), mn1 = fmaxf(m1, mx1);
        float c0 = __expf(m0 - mn0), c1 = __expf(m1 - mn1);
        m0 = mn0; m1 = mn1;

        float s0 = 0.f, s1 = 0.f;
#pragma unroll
        for (int j = 0; j < 8; j++) {
            sfr[j][0] = __expf(sfr[j][0] - m0);
            sfr[j][1] = __expf(sfr[j][1] - m0);
            sfr[j][2] = __expf(sfr[j][2] - m1);
            sfr[j][3] = __expf(sfr[j][3] - m1);
            s0 += sfr[j][0] + sfr[j][1];
            s1 += sfr[j][2] + sfr[j][3];
        }
#pragma unroll
        for (int off = 1; off < 4; off <<= 1) {
            s0 += __shfl_xor_sync(0xffffffffu, s0, off);
            s1 += __shfl_xor_sync(0xffffffffu, s1, off);
        }
        l0 = l0 * c0 + s0;
        l1 = l1 * c1 + s1;

#pragma unroll
        for (int n = 0; n < 18; n++) {
            o[n][0] *= c0; o[n][1] *= c0;
            o[n][2] *= c1; o[n][3] *= c1;
        }

        // P -> single fp16 fragments
        uint32_t ph01[8], ph23[8];
#pragma unroll
        for (int j = 0; j < 8; j++) {
            __half2 p0 = __floats2half2_rn(sfr[j][0], sfr[j][1]);
            __half2 p1 = __floats2half2_rn(sfr[j][2], sfr[j][3]);
            ph01[j] = *reinterpret_cast<uint32_t*>(&p0);
            ph23[j] = *reinterpret_cast<uint32_t*>(&p1);
        }

        // O += P (V_hi + V_lo)  -- fp16 2-pass
#pragma unroll
        for (int kc = 0; kc < 4; kc++) {
            uint32_t pa[4] = { ph01[2*kc], ph23[2*kc], ph01[2*kc+1], ph23[2*kc+1] };
#pragma unroll
            for (int n = 0; n < 18; n++) {
                int rv = (n * 8 + lr) * VS + kc * 8 + lc;
                uint32_t bh2[2] = { sVh[rv], sVh[rv + 4] };
                uint32_t bl2[2] = { sVl[rv], sVl[rv + 4] };
                mma16816h(o[n], pa, bh2);
                mma16816h(o[n], pa, bl2);
            }
        }
    }

    // epilogue: normalize + bf16 split -> oh/ol [row][K2DIM]
    float inv0 = 1.f / l0, inv1 = 1.f / l1;
    int r0 = qt * 128 + wm + lr;
    size_t row0 = (size_t)(b * SEQ + r0) * K2DIM + h * KP;
    size_t row1 = (size_t)(b * SEQ + r0 + 8) * K2DIM + h * KP;
#pragma unroll
    for (int n = 0; n < 18; n++) {
        int cp = (n * 8 + 2 * lc) >> 1;       // pair index within head
        uint32_t H, L;
        split2(o[n][0] * inv0, o[n][1] * inv0, H, L);
        oh[row0 + cp] = H; ol[row0 + cp] = L;
        split2(o[n][2] * inv1, o[n][3] * inv1, H, L);
        oh[row1 + cp] = H; ol[row1 + cp] = L;
    }
}

// ---------------- launcher --------------------------------------------------
extern "C" void kernel_launch(void* const* d_in, const int* in_sizes, int n_in,
                              void* d_out, int out_size)
{
    const float* x   = (const float*)d_in[0];
    const float* wq  = (const float*)d_in[1];
    const float* bq  = (const float*)d_in[2];
    const float* wkv = (const float*)d_in[3];
    const float* bkv = (const float*)d_in[4];
    const float* wo  = (const float*)d_in[5];
    const float* bo  = (const float*)d_in[6];
    const float* fc  = (const float*)d_in[7];
    const float* fs  = (const float*)d_in[8];
    float* out = (float*)d_out;

    float *gkv;
    uint32_t *xh, *xl, *wqh, *wql, *wkh, *wkl, *woh, *wol, *ah, *al;
    uint32_t *qh, *ql, *kh, *kl, *vh, *vl;
    cudaGetSymbolAddress((void**)&gkv, g_kv);
    cudaGetSymbolAddress((void**)&xh,  g_xh);
    cudaGetSymbolAddress((void**)&xl,  g_xl);
    cudaGetSymbolAddress((void**)&wqh, g_wqh);
    cudaGetSymbolAddress((void**)&wql, g_wql);
    cudaGetSymbolAddress((void**)&wkh, g_wkh);
    cudaGetSymbolAddress((void**)&wkl, g_wkl);
    cudaGetSymbolAddress((void**)&woh, g_woh);
    cudaGetSymbolAddress((void**)&wol, g_wol);
    cudaGetSymbolAddress((void**)&ah,  g_ah);
    cudaGetSymbolAddress((void**)&al,  g_al);
    cudaGetSymbolAddress((void**)&qh,  g_qh);
    cudaGetSymbolAddress((void**)&ql,  g_ql);
    cudaGetSymbolAddress((void**)&kh,  g_kh);
    cudaGetSymbolAddress((void**)&kl,  g_kl);
    cudaGetSymbolAddress((void**)&vh,  g_vh);
    cudaGetSymbolAddress((void**)&vl,  g_vl);

    cudaFuncSetAttribute(flash_mma, cudaFuncAttributeMaxDynamicSharedMemorySize,
                         FLASH_SMEM);
    cudaFuncSetAttribute(gemm_ldsm<0>, cudaFuncAttributeMaxDynamicSharedMemorySize,
                         GB_SMEM);
    cudaFuncSetAttribute(gemm_ldsm<1>, cudaFuncAttributeMaxDynamicSharedMemorySize,
                         GB_SMEM);

    // split GEMM inputs (bf16 hi/lo)
    {
        int nx = MROWS * K2DIM;
        split_bf16<<<(nx + 255) / 256, 256>>>(x, xh, xl, nx);
        int nq = DIMC * K2DIM;
        split_bf16<<<(nq + 255) / 256, 256>>>(wq, wqh, wql, nq);
        int nk = KVOUT * K2DIM;
        split_bf16<<<(nk + 255) / 256, 256>>>(wkv, wkh, wkl, nk);
        split_bf16<<<(nq + 255) / 256, 256>>>(wo, woh, wol, nq);
    }

    // Q projection with fused rope+split
    gemm_ldsm<1><<<dim3(DIMC / 128, MROWS / 128), 256, GB_SMEM>>>(
        xh, xl, wqh, wql, bq, nullptr, MROWS, DIMC, K2DIM, fc, fs, qh, ql);
    // KV projection (plain)
    gemm_ldsm<0><<<dim3((KVOUT + 127) / 128, MROWS / 128), 256, GB_SMEM>>>(
        xh, xl, wkh, wkl, bkv, gkv, MROWS, KVOUT, K2DIM, nullptr, nullptr, nullptr, nullptr);

    // K rope + split, V transpose + fp16 split
    {
        int tk = BSZ * KVH * SEQ * KP;
        rope_k_split<<<(tk + 255) / 256, 256>>>(gkv, fc, fs, kh, kl);
        v_trans_split<<<dim3(SEQ / 64, BSZ * KVH), 256>>>(gkv, vh, vl);
    }

    // attention (writes bf16 hi/lo split directly)
    flash_mma<<<dim3(SEQ / 128, BSZ * NH), 256, FLASH_SMEM>>>(
        qh, ql, kh, kl, vh, vl, ah, al);

    // output projection
    gemm_ldsm<0><<<dim3(DIMC / 128, MROWS / 128), 256, GB_SMEM>>>(
        ah, al, woh, wol, bo, out, MROWS, DIMC, K2DIM, nullptr, nullptr, nullptr, nullptr);
}

// round 8
// speedup vs baseline: 1.4357x; 1.4357x over previous
#include <cuda_runtime.h>
#include <cuda_bf16.h>
#include <cuda_fp16.h>
#include <math.h>
#include <stdint.h>

// Problem constants
#define DIMC   1152
#define NH     8
#define KVH    2
#define HD     144
#define BSZ    4
#define SEQ    2048
#define MROWS  (BSZ*SEQ)          // 8192
#define KVOUT  (2*KVH*HD)         // 576
#define K2DIM  (DIMC/2)           // 576
#define KP     72                 // pairs per head row
#define TPH    (SEQ/2)            // seq pairs for V^T

// ---------------- scratch (device globals) ----------------------------------
__device__ float g_q   [(size_t)MROWS * DIMC];
__device__ float g_kv  [(size_t)MROWS * KVOUT];
__device__ float g_attn[(size_t)MROWS * DIMC];

__device__ uint32_t g_xh [(size_t)MROWS * K2DIM];
__device__ uint32_t g_xl [(size_t)MROWS * K2DIM];
__device__ uint32_t g_wqh[(size_t)DIMC  * K2DIM];
__device__ uint32_t g_wql[(size_t)DIMC  * K2DIM];
__device__ uint32_t g_wkh[(size_t)KVOUT * K2DIM];
__device__ uint32_t g_wkl[(size_t)KVOUT * K2DIM];
__device__ uint32_t g_woh[(size_t)DIMC  * K2DIM];
__device__ uint32_t g_wol[(size_t)DIMC  * K2DIM];
__device__ uint32_t g_ah [(size_t)MROWS * K2DIM];
__device__ uint32_t g_al [(size_t)MROWS * K2DIM];

// attention operands
__device__ uint32_t g_qh[(size_t)BSZ*NH *SEQ*KP];   // bf16 pairs
__device__ uint32_t g_ql[(size_t)BSZ*NH *SEQ*KP];
__device__ uint32_t g_kh[(size_t)BSZ*KVH*SEQ*KP];
__device__ uint32_t g_kl[(size_t)BSZ*KVH*SEQ*KP];
__device__ uint32_t g_vh[(size_t)BSZ*KVH*HD*TPH];   // V^T fp16 hi, pairs along s
__device__ uint32_t g_vl[(size_t)BSZ*KVH*HD*TPH];   // V^T fp16 lo

// ---------------- helpers ----------------------------------------------------
__device__ __forceinline__ uint32_t smem_u32(const void* p) {
    uint32_t a;
    asm("{ .reg .u64 t; cvta.to.shared.u64 t, %1; cvt.u32.u64 %0, t; }"
        : "=r"(a) : "l"(p));
    return a;
}

__device__ __forceinline__ void split2(float x, float y, uint32_t& hi, uint32_t& lo)
{
    __nv_bfloat162 h = __floats2bfloat162_rn(x, y);
    float hx = __bfloat162float(h.x), hy = __bfloat162float(h.y);
    __nv_bfloat162 l = __floats2bfloat162_rn(x - hx, y - hy);
    hi = *reinterpret_cast<uint32_t*>(&h);
    lo = *reinterpret_cast<uint32_t*>(&l);
}

__device__ __forceinline__ void split2h(float x, float y, uint32_t& hi, uint32_t& lo)
{
    __half2 h = __floats2half2_rn(x, y);
    float2 hf = __half22float2(h);
    __half2 l = __floats2half2_rn(x - hf.x, y - hf.y);
    hi = *reinterpret_cast<uint32_t*>(&h);
    lo = *reinterpret_cast<uint32_t*>(&l);
}

__device__ __forceinline__ void mma16816(float* c, const uint32_t* a, const uint32_t* b)
{
    asm volatile(
        "mma.sync.aligned.m16n8k16.row.col.f32.bf16.bf16.f32 "
        "{%0,%1,%2,%3}, {%4,%5,%6,%7}, {%8,%9}, {%0,%1,%2,%3};\n"
        : "+f"(c[0]), "+f"(c[1]), "+f"(c[2]), "+f"(c[3])
        : "r"(a[0]), "r"(a[1]), "r"(a[2]), "r"(a[3]), "r"(b[0]), "r"(b[1]));
}

__device__ __forceinline__ void mma16816h(float* c, const uint32_t* a, const uint32_t* b)
{
    asm volatile(
        "mma.sync.aligned.m16n8k16.row.col.f32.f16.f16.f32 "
        "{%0,%1,%2,%3}, {%4,%5,%6,%7}, {%8,%9}, {%0,%1,%2,%3};\n"
        : "+f"(c[0]), "+f"(c[1]), "+f"(c[2]), "+f"(c[3])
        : "r"(a[0]), "r"(a[1]), "r"(a[2]), "r"(a[3]), "r"(b[0]), "r"(b[1]));
}

__device__ __forceinline__ void ldsm4(uint32_t& r0, uint32_t& r1, uint32_t& r2,
                                      uint32_t& r3, uint32_t a)
{
    asm volatile("ldmatrix.sync.aligned.m8n8.x4.shared.b16 {%0,%1,%2,%3}, [%4];"
                 : "=r"(r0), "=r"(r1), "=r"(r2), "=r"(r3) : "r"(a));
}

#define CP_ASYNC16(sa, gp) \
    asm volatile("cp.async.cg.shared.global [%0], [%1], 16;" :: "r"(sa), "l"(gp))
#define CP_COMMIT() asm volatile("cp.async.commit_group;" ::: "memory")
#define CP_WAIT1()  asm volatile("cp.async.wait_group 1;" ::: "memory")
#define CP_WAIT0()  asm volatile("cp.async.wait_group 0;" ::: "memory")

// ---------------- fp32 -> (hi, lo) packed bf16x2 ----------------------------
__global__ void split_bf16(const float* __restrict__ src,
                           uint32_t* __restrict__ hi, uint32_t* __restrict__ lo,
                           int n2)
{
    int i = blockIdx.x * blockDim.x + threadIdx.x;
    if (i >= n2) return;
    float2 v = ((const float2*)src)[i];
    split2(v.x, v.y, hi[i], lo[i]);
}

// ---------------- split-bf16 GEMM (ldmatrix + cp.async pipeline) -------------
#define GB_ROWB 80
#define GB_ARR  (128 * GB_ROWB)
#define GB_BUF  (4 * GB_ARR)
#define GB_SMEM (2 * GB_BUF)          // 81920 B

__global__ __launch_bounds__(256, 2)
void gemm_ldsm(const uint32_t* __restrict__ Ahg, const uint32_t* __restrict__ Alg,
               const uint32_t* __restrict__ Bhg, const uint32_t* __restrict__ Blg,
               const float* __restrict__ bias, float* __restrict__ C,
               int M, int N, int K2)
{
    extern __shared__ char smem[];
    const uint32_t sbase = smem_u32(smem);
    const int tid = threadIdx.x;
    const int warp = tid >> 5, lane = tid & 31;
    const int wm = (warp & 1) * 64;
    const int wn = (warp >> 1) * 32;
    const int m0 = blockIdx.y * 128;
    const int n0 = blockIdx.x * 128;
    const int nch = K2 / 16;

    const int srow = tid >> 2;
    const int schk = tid & 3;
    const int br0 = (n0 + srow     < N) ? n0 + srow      : N - 1;
    const int br1 = (n0 + srow + 64 < N) ? n0 + srow + 64 : N - 1;

    float acc[4][4][4];
#pragma unroll
    for (int i = 0; i < 4; i++)
#pragma unroll
        for (int j = 0; j < 4; j++)
#pragma unroll
            for (int t = 0; t < 4; t++) acc[i][j][t] = 0.f;

    const int lrow = lane & 15;
    const int lch = lane >> 4;

#define GB_ISSUE(ch) do { \
    const int _buf = (ch) & 1; \
    const uint32_t _sb = sbase + _buf * GB_BUF; \
    const size_t _kc = (size_t)(ch) * 16 + schk * 4; \
    uint32_t _so0 = _sb + srow * GB_ROWB + schk * 16; \
    uint32_t _so1 = _sb + (srow + 64) * GB_ROWB + schk * 16; \
    CP_ASYNC16(_so0,              Ahg + (size_t)(m0 + srow) * K2 + _kc); \
    CP_ASYNC16(_so1,              Ahg + (size_t)(m0 + srow + 64) * K2 + _kc); \
    CP_ASYNC16(_so0 + GB_ARR,     Alg + (size_t)(m0 + srow) * K2 + _kc); \
    CP_ASYNC16(_so1 + GB_ARR,     Alg + (size_t)(m0 + srow + 64) * K2 + _kc); \
    CP_ASYNC16(_so0 + 2*GB_ARR,   Bhg + (size_t)br0 * K2 + _kc); \
    CP_ASYNC16(_so1 + 2*GB_ARR,   Bhg + (size_t)br1 * K2 + _kc); \
    CP_ASYNC16(_so0 + 3*GB_ARR,   Blg + (size_t)br0 * K2 + _kc); \
    CP_ASYNC16(_so1 + 3*GB_ARR,   Blg + (size_t)br1 * K2 + _kc); \
} while (0)

    GB_ISSUE(0); CP_COMMIT();

    for (int ch = 0; ch < nch; ch++) {
        if (ch + 1 < nch) { GB_ISSUE(ch + 1); CP_COMMIT(); CP_WAIT1(); }
        else              { CP_WAIT0(); }
        __syncthreads();

        const uint32_t sb = sbase + (ch & 1) * GB_BUF;
        const uint32_t aH = sb + (wm + lrow) * GB_ROWB + lch * 16;
        const uint32_t aL = aH + GB_ARR;
        const uint32_t bH = sb + 2 * GB_ARR + (wn + lrow) * GB_ROWB + lch * 16;
        const uint32_t bL = bH + GB_ARR;

#pragma unroll
        for (int kk = 0; kk < 2; kk++) {
            uint32_t bh[4][2], bl[4][2];
#pragma unroll
            for (int jj = 0; jj < 2; jj++) {
                uint32_t r0, r1, r2, r3;
                ldsm4(r0, r1, r2, r3, bH + jj * (16 * GB_ROWB) + kk * 32);
                bh[2*jj][0] = r0; bh[2*jj][1] = r2;
                bh[2*jj+1][0] = r1; bh[2*jj+1][1] = r3;
                ldsm4(r0, r1, r2, r3, bL + jj * (16 * GB_ROWB) + kk * 32);
                bl[2*jj][0] = r0; bl[2*jj][1] = r2;
                bl[2*jj+1][0] = r1; bl[2*jj+1][1] = r3;
            }
#pragma unroll
            for (int i = 0; i < 4; i++) {
                uint32_t ah[4], al[4];
                ldsm4(ah[0], ah[1], ah[2], ah[3], aH + i * (16 * GB_ROWB) + kk * 32);
                ldsm4(al[0], al[1], al[2], al[3], aL + i * (16 * GB_ROWB) + kk * 32);
#pragma unroll
                for (int j = 0; j < 4; j++) {
                    mma16816(acc[i][j], ah, bh[j]);
                    mma16816(acc[i][j], ah, bl[j]);
                    mma16816(acc[i][j], al, bh[j]);
                }
            }
        }
        __syncthreads();
    }

    const int lr = lane >> 2, lc = lane & 3;
#pragma unroll
    for (int i = 0; i < 4; i++) {
        int r0 = m0 + wm + i * 16 + lr;
#pragma unroll
        for (int j = 0; j < 4; j++) {
            int c0 = n0 + wn + j * 8 + lc * 2;
            if (c0 < N) {
                float2 bb = *(const float2*)&bias[c0];
                *(float2*)&C[(size_t)r0 * N + c0] =
                    make_float2(acc[i][j][0] + bb.x, acc[i][j][1] + bb.y);
                *(float2*)&C[(size_t)(r0 + 8) * N + c0] =
                    make_float2(acc[i][j][2] + bb.x, acc[i][j][3] + bb.y);
            }
        }
    }
#undef GB_ISSUE
}

// ---------------- RoPE -> split bf16 ----------------------------------------
__global__ void rope_q_split(const float* __restrict__ Q,
                             const float* __restrict__ fc, const float* __restrict__ fs,
                             uint32_t* __restrict__ qh, uint32_t* __restrict__ ql)
{
    int idx = blockIdx.x * blockDim.x + threadIdx.x;
    const int total = BSZ * NH * SEQ * KP;
    if (idx >= total) return;
    int i = idx % KP;
    int s = (idx / KP) % SEQ;
    int h = (idx / (KP * SEQ)) % NH;
    int b = idx / (KP * SEQ * NH);

    size_t base = (size_t)(b * SEQ + s) * DIMC + h * HD;
    float q0 = Q[base + 2 * i];
    float q1 = Q[base + 2 * i + 1];
    float c = fc[s * KP + i];
    float sn = fs[s * KP + i];
    const float scale = 0.083333333333333329f;
    float y0 = (q0 * c - q1 * sn) * scale;
    float y1 = (q0 * sn + q1 * c) * scale;
    split2(y0, y1, qh[idx], ql[idx]);
}

__global__ void rope_k_split(const float* __restrict__ KV,
                             const float* __restrict__ fc, const float* __restrict__ fs,
                             uint32_t* __restrict__ kh, uint32_t* __restrict__ kl)
{
    int idx = blockIdx.x * blockDim.x + threadIdx.x;
    const int total = BSZ * KVH * SEQ * KP;
    if (idx >= total) return;
    int i = idx % KP;
    int s = (idx / KP) % SEQ;
    int kvh = (idx / (KP * SEQ)) % KVH;
    int b = idx / (KP * SEQ * KVH);

    size_t base = (size_t)(b * SEQ + s) * KVOUT + kvh * HD;
    float k0 = KV[base + 2 * i];
    float k1 = KV[base + 2 * i + 1];
    float c = fc[s * KP + i];
    float sn = fs[s * KP + i];
    split2(k0 * c - k1 * sn, k0 * sn + k1 * c, kh[idx], kl[idx]);
}

// V transpose + fp16 split: out [b*KVH+kvh][d][sp], pairs along s.
__global__ void v_trans_split(const float* __restrict__ KV,
                              uint32_t* __restrict__ vh, uint32_t* __restrict__ vl)
{
    __shared__ float tile[64][HD + 1];
    const int st = blockIdx.x;
    const int bk = blockIdx.y;
    const int b = bk / KVH, kvh = bk % KVH;
    const int tid = threadIdx.x;

    const float* src = KV + (size_t)(b * SEQ + st * 64) * KVOUT + KVH * HD + kvh * HD;
    for (int e = tid; e < 64 * HD; e += 256) {
        int r = e / HD, c = e % HD;
        tile[r][c] = src[(size_t)r * KVOUT + c];
    }
    __syncthreads();

    uint32_t* oh = vh + ((size_t)bk * HD) * TPH + st * 32;
    uint32_t* ol = vl + ((size_t)bk * HD) * TPH + st * 32;
    for (int e = tid; e < HD * 32; e += 256) {
        int d = e / 32, sp = e % 32;
        uint32_t h, l;
        split2h(tile[2 * sp][d], tile[2 * sp + 1][d], h, l);
        oh[(size_t)d * TPH + sp] = h;
        ol[(size_t)d * TPH + sp] = l;
    }
}

// ---------------- Flash attention -------------------------------------------
// QK: bf16 3-pass.  PV: fp16 2-pass (P single fp16, V fp16 hi/lo).
#define QS 76
#define KS 76
#define VS 36

#define FLASH_SMEM ((2*128*QS + 2*64*KS + 2*HD*VS) * (int)sizeof(uint32_t))

__global__ __launch_bounds__(256, 1)
void flash_mma(const uint32_t* __restrict__ qh, const uint32_t* __restrict__ ql,
               const uint32_t* __restrict__ kh, const uint32_t* __restrict__ kl,
               const uint32_t* __restrict__ vh, const uint32_t* __restrict__ vl,
               float* __restrict__ out)
{
    extern __shared__ uint32_t fsm[];
    uint32_t* sQh = fsm;
    uint32_t* sQl = sQh + 128 * QS;
    uint32_t* sKh = sQl + 128 * QS;
    uint32_t* sKl = sKh + 64 * KS;
    uint32_t* sVh = sKl + 64 * KS;
    uint32_t* sVl = sVh + HD * VS;

    const int qt = (gridDim.x - 1) - blockIdx.x;
    const int bh = blockIdx.y;
    const int b = bh >> 3;
    const int h = bh & 7;
    const int kvh = h >> 2;
    const int bk = b * KVH + kvh;

    const int tid = threadIdx.x;
    const int warp = tid >> 5, lane = tid & 31;
    const int lr = lane >> 2, lc = lane & 3;
    const int wm = warp * 16;

    {
        const uint32_t* gqh = qh + ((size_t)bh * SEQ + qt * 128) * KP;
        const uint32_t* gql = ql + ((size_t)bh * SEQ + qt * 128) * KP;
        for (int e = tid; e < 128 * 18; e += 256) {
            int r = e / 18, c = (e % 18) * 4;
            *(uint4*)&sQh[r * QS + c] = *(const uint4*)&gqh[(size_t)r * KP + c];
            *(uint4*)&sQl[r * QS + c] = *(const uint4*)&gql[(size_t)r * KP + c];
        }
    }

    float o[18][4];
#pragma unroll
    for (int n = 0; n < 18; n++)
#pragma unroll
        for (int t = 0; t < 4; t++) o[n][t] = 0.f;
    float m0 = -1e30f, m1 = -1e30f, l0 = 0.f, l1 = 0.f;

    const int ktmax = 2 * qt + 1;
    const int qrow0 = qt * 128 + wm;

    for (int kt = 0; kt <= ktmax; kt++) {
        __syncthreads();
        {
            const uint32_t* gkh = kh + ((size_t)bk * SEQ + kt * 64) * KP;
            const uint32_t* gkl = kl + ((size_t)bk * SEQ + kt * 64) * KP;
            for (int e = tid; e < 64 * 18; e += 256) {
                int r = e / 18, c = (e % 18) * 4;
                *(uint4*)&sKh[r * KS + c] = *(const uint4*)&gkh[(size_t)r * KP + c];
                *(uint4*)&sKl[r * KS + c] = *(const uint4*)&gkl[(size_t)r * KP + c];
            }
            const uint32_t* gvh = vh + (size_t)bk * HD * TPH + kt * 32;
            const uint32_t* gvl = vl + (size_t)bk * HD * TPH + kt * 32;
            for (int e = tid; e < HD * 8; e += 256) {
                int r = e / 8, c = (e % 8) * 4;
                *(uint4*)&sVh[r * VS + c] = *(const uint4*)&gvh[(size_t)r * TPH + c];
                *(uint4*)&sVl[r * VS + c] = *(const uint4*)&gvl[(size_t)r * TPH + c];
            }
        }
        __syncthreads();

        float sfr[8][4];
#pragma unroll
        for (int j = 0; j < 8; j++)
#pragma unroll
            for (int t = 0; t < 4; t++) sfr[j][t] = 0.f;

#pragma unroll
        for (int kc = 0; kc < 9; kc++) {
            uint32_t ah[4], al[4];
            int ra = (wm + lr) * QS + kc * 8 + lc;
            int rb = (wm + lr + 8) * QS + kc * 8 + lc;
            ah[0] = sQh[ra];     ah[1] = sQh[rb];
            ah[2] = sQh[ra + 4]; ah[3] = sQh[rb + 4];
            al[0] = sQl[ra];     al[1] = sQl[rb];
            al[2] = sQl[ra + 4]; al[3] = sQl[rb + 4];
#pragma unroll
            for (int j = 0; j < 8; j++) {
                int rk = (j * 8 + lr) * KS + kc * 8 + lc;
                uint32_t bh2[2] = { sKh[rk], sKh[rk + 4] };
                uint32_t bl2[2] = { sKl[rk], sKl[rk + 4] };
                mma16816(sfr[j], ah, bh2);
                mma16816(sfr[j], ah, bl2);
                mma16816(sfr[j], al, bh2);
            }
        }

        if (kt * 64 + 63 > qrow0) {
            int key0 = kt * 64;
#pragma unroll
            for (int j = 0; j < 8; j++) {
                int kc0 = key0 + j * 8 + 2 * lc;
                if (kc0     > qrow0 + lr)     sfr[j][0] = -1e9f;
                if (kc0 + 1 > qrow0 + lr)     sfr[j][1] = -1e9f;
                if (kc0     > qrow0 + lr + 8) sfr[j][2] = -1e9f;
                if (kc0 + 1 > qrow0 + lr + 8) sfr[j][3] = -1e9f;
            }
        }

        float mx0 = -1e30f, mx1 = -1e30f;
#pragma unroll
        for (int j = 0; j < 8; j++) {
            mx0 = fmaxf(mx0, fmaxf(sfr[j][0], sfr[j][1]));
            mx1 = fmaxf(mx1, fmaxf(sfr[j][2], sfr[j][3]));
        }
#pragma unroll
        for (int off = 1; off < 4; off <<= 1) {
            mx0 = fmaxf(mx0, __shfl_xor_sync(0xffffffffu, mx0, off));
            mx1 = fmaxf(mx1, __shfl_xor_sync(0xffffffffu, mx1, off));
        }
        float mn0 = fmaxf(m0, mx0), mn1 = fmaxf(m1, mx1);
        float c0 = __expf(m0 - mn0), c1 = __expf(m1 - mn1);
        m0 = mn0; m1 = mn1;

        float s0 = 0.f, s1 = 0.f;
#pragma unroll
        for (int j = 0; j < 8; j++) {
            sfr[j][0] = __expf(sfr[j][0] - m0);
            sfr[j][1] = __expf(sfr[j][1] - m0);
            sfr[j][2] = __expf(sfr[j][2] - m1);
            sfr[j][3] = __expf(sfr[j][3] - m1);
            s0 += sfr[j][0] + sfr[j][1];
            s1 += sfr[j][2] + sfr[j][3];
        }
#pragma unroll
        for (int off = 1; off < 4; off <<= 1) {
            s0 += __shfl_xor_sync(0xffffffffu, s0, off);
            s1 += __shfl_xor_sync(0xffffffffu, s1, off);
        }
        l0 = l0 * c0 + s0;
        l1 = l1 * c1 + s1;

#pragma unroll
        for (int n = 0; n < 18; n++) {
            o[n][0] *= c0; o[n][1] *= c0;
            o[n][2] *= c1; o[n][3] *= c1;
        }

        // P -> single fp16 fragments
        uint32_t ph01[8], ph23[8];
#pragma unroll
        for (int j = 0; j < 8; j++) {
            __half2 p0 = __floats2half2_rn(sfr[j][0], sfr[j][1]);
            __half2 p1 = __floats2half2_rn(sfr[j][2], sfr[j][3]);
            ph01[j] = *reinterpret_cast<uint32_t*>(&p0);
            ph23[j] = *reinterpret_cast<uint32_t*>(&p1);
        }

        // O += P (V_hi + V_lo) -- fp16 2-pass
#pragma unroll
        for (int kc = 0; kc < 4; kc++) {
            uint32_t pa[4] = { ph01[2*kc], ph23[2*kc], ph01[2*kc+1], ph23[2*kc+1] };
#pragma unroll
            for (int n = 0; n < 18; n++) {
                int rv = (n * 8 + lr) * VS + kc * 8 + lc;
                uint32_t bh2[2] = { sVh[rv], sVh[rv + 4] };
                uint32_t bl2[2] = { sVl[rv], sVl[rv + 4] };
                mma16816h(o[n], pa, bh2);
                mma16816h(o[n], pa, bl2);
            }
        }
    }

    float inv0 = 1.f / l0, inv1 = 1.f / l1;
    int r0 = qt * 128 + wm + lr;
    float* orow0 = out + ((size_t)b * SEQ + r0)     * DIMC + h * HD;
    float* orow1 = out + ((size_t)b * SEQ + r0 + 8) * DIMC + h * HD;
#pragma unroll
    for (int n = 0; n < 18; n++) {
        int col = n * 8 + 2 * lc;
        *(float2*)&orow0[col] = make_float2(o[n][0] * inv0, o[n][1] * inv0);
        *(float2*)&orow1[col] = make_float2(o[n][2] * inv1, o[n][3] * inv1);
    }
}

// ---------------- launcher --------------------------------------------------
extern "C" void kernel_launch(void* const* d_in, const int* in_sizes, int n_in,
                              void* d_out, int out_size)
{
    const float* x   = (const float*)d_in[0];
    const float* wq  = (const float*)d_in[1];
    const float* bq  = (const float*)d_in[2];
    const float* wkv = (const float*)d_in[3];
    const float* bkv = (const float*)d_in[4];
    const float* wo  = (const float*)d_in[5];
    const float* bo  = (const float*)d_in[6];
    const float* fc  = (const float*)d_in[7];
    const float* fs  = (const float*)d_in[8];
    float* out = (float*)d_out;

    float *gq, *gkv, *gat;
    uint32_t *xh, *xl, *wqh, *wql, *wkh, *wkl, *woh, *wol, *ah, *al;
    uint32_t *qh, *ql, *kh, *kl, *vh, *vl;
    cudaGetSymbolAddress((void**)&gq,  g_q);
    cudaGetSymbolAddress((void**)&gkv, g_kv);
    cudaGetSymbolAddress((void**)&gat, g_attn);
    cudaGetSymbolAddress((void**)&xh,  g_xh);
    cudaGetSymbolAddress((void**)&xl,  g_xl);
    cudaGetSymbolAddress((void**)&wqh, g_wqh);
    cudaGetSymbolAddress((void**)&wql, g_wql);
    cudaGetSymbolAddress((void**)&wkh, g_wkh);
    cudaGetSymbolAddress((void**)&wkl, g_wkl);
    cudaGetSymbolAddress((void**)&woh, g_woh);
    cudaGetSymbolAddress((void**)&wol, g_wol);
    cudaGetSymbolAddress((void**)&ah,  g_ah);
    cudaGetSymbolAddress((void**)&al,  g_al);
    cudaGetSymbolAddress((void**)&qh,  g_qh);
    cudaGetSymbolAddress((void**)&ql,  g_ql);
    cudaGetSymbolAddress((void**)&kh,  g_kh);
    cudaGetSymbolAddress((void**)&kl,  g_kl);
    cudaGetSymbolAddress((void**)&vh,  g_vh);
    cudaGetSymbolAddress((void**)&vl,  g_vl);

    cudaFuncSetAttribute(flash_mma, cudaFuncAttributeMaxDynamicSharedMemorySize,
                         FLASH_SMEM);
    cudaFuncSetAttribute(gemm_ldsm, cudaFuncAttributeMaxDynamicSharedMemorySize,
                         GB_SMEM);

    // split GEMM inputs
    {
        int nx = MROWS * K2DIM;
        split_bf16<<<(nx + 255) / 256, 256>>>(x, xh, xl, nx);
        int nq = DIMC * K2DIM;
        split_bf16<<<(nq + 255) / 256, 256>>>(wq, wqh, wql, nq);
        int nk = KVOUT * K2DIM;
        split_bf16<<<(nk + 255) / 256, 256>>>(wkv, wkh, wkl, nk);
        split_bf16<<<(nq + 255) / 256, 256>>>(wo, woh, wol, nq);
    }

    // projections
    gemm_ldsm<<<dim3(DIMC / 128, MROWS / 128), 256, GB_SMEM>>>(
        xh, xl, wqh, wql, bq, gq, MROWS, DIMC, K2DIM);
    gemm_ldsm<<<dim3((KVOUT + 127) / 128, MROWS / 128), 256, GB_SMEM>>>(
        xh, xl, wkh, wkl, bkv, gkv, MROWS, KVOUT, K2DIM);

    // RoPE + split + V transpose (fp16)
    {
        int tq = BSZ * NH * SEQ * KP;
        rope_q_split<<<(tq + 255) / 256, 256>>>(gq, fc, fs, qh, ql);
        int tk = BSZ * KVH * SEQ * KP;
        rope_k_split<<<(tk + 255) / 256, 256>>>(gkv, fc, fs, kh, kl);
        v_trans_split<<<dim3(SEQ / 64, BSZ * KVH), 256>>>(gkv, vh, vl);
    }

    // attention
    flash_mma<<<dim3(SEQ / 128, BSZ * NH), 256, FLASH_SMEM>>>(
        qh, ql, kh, kl, vh, vl, gat);

    // output projection
    {
        int na = MROWS * K2DIM;
        split_bf16<<<(na + 255) / 256, 256>>>(gat, ah, al, na);
    }
    gemm_ldsm<<<dim3(DIMC / 128, MROWS / 128), 256, GB_SMEM>>>(
        ah, al, woh, wol, bo, out, MROWS, DIMC, K2DIM);
}

// round 9
// speedup vs baseline: 1.5335x; 1.0681x over previous
#include <cuda_runtime.h>
#include <cuda_bf16.h>
#include <cuda_fp16.h>
#include <math.h>
#include <stdint.h>

// Problem constants
#define DIMC   1152
#define NH     8
#define KVH    2
#define HD     144
#define BSZ    4
#define SEQ    2048
#define MROWS  (BSZ*SEQ)          // 8192
#define KVOUT  (2*KVH*HD)         // 576
#define K2DIM  (DIMC/2)           // 576
#define KP     72                 // pairs per head row
#define TPH    (SEQ/2)            // seq pairs for V^T

// ---------------- scratch (device globals) ----------------------------------
__device__ float g_q   [(size_t)MROWS * DIMC];
__device__ float g_kv  [(size_t)MROWS * KVOUT];
__device__ float g_attn[(size_t)MROWS * DIMC];

__device__ uint32_t g_xh [(size_t)MROWS * K2DIM];
__device__ uint32_t g_xl [(size_t)MROWS * K2DIM];
__device__ uint32_t g_wqh[(size_t)DIMC  * K2DIM];
__device__ uint32_t g_wql[(size_t)DIMC  * K2DIM];
__device__ uint32_t g_wkh[(size_t)KVOUT * K2DIM];
__device__ uint32_t g_wkl[(size_t)KVOUT * K2DIM];
__device__ uint32_t g_woh[(size_t)DIMC  * K2DIM];
__device__ uint32_t g_wol[(size_t)DIMC  * K2DIM];
__device__ uint32_t g_ah [(size_t)MROWS * K2DIM];
__device__ uint32_t g_al [(size_t)MROWS * K2DIM];

// attention operands
__device__ uint32_t g_qf[(size_t)BSZ*NH *SEQ*KP];   // Q single fp16 pairs
__device__ uint32_t g_kh[(size_t)BSZ*KVH*SEQ*KP];   // K fp16 hi
__device__ uint32_t g_kl[(size_t)BSZ*KVH*SEQ*KP];   // K fp16 lo
__device__ uint32_t g_vh[(size_t)BSZ*KVH*HD*TPH];   // V^T fp16 hi, pairs along s
__device__ uint32_t g_vl[(size_t)BSZ*KVH*HD*TPH];   // V^T fp16 lo

// ---------------- helpers ----------------------------------------------------
__device__ __forceinline__ uint32_t smem_u32(const void* p) {
    uint32_t a;
    asm("{ .reg .u64 t; cvta.to.shared.u64 t, %1; cvt.u32.u64 %0, t; }"
        : "=r"(a) : "l"(p));
    return a;
}

__device__ __forceinline__ void split2(float x, float y, uint32_t& hi, uint32_t& lo)
{
    __nv_bfloat162 h = __floats2bfloat162_rn(x, y);
    float hx = __bfloat162float(h.x), hy = __bfloat162float(h.y);
    __nv_bfloat162 l = __floats2bfloat162_rn(x - hx, y - hy);
    hi = *reinterpret_cast<uint32_t*>(&h);
    lo = *reinterpret_cast<uint32_t*>(&l);
}

__device__ __forceinline__ void split2h(float x, float y, uint32_t& hi, uint32_t& lo)
{
    __half2 h = __floats2half2_rn(x, y);
    float2 hf = __half22float2(h);
    __half2 l = __floats2half2_rn(x - hf.x, y - hf.y);
    hi = *reinterpret_cast<uint32_t*>(&h);
    lo = *reinterpret_cast<uint32_t*>(&l);
}

__device__ __forceinline__ void mma16816(float* c, const uint32_t* a, const uint32_t* b)
{
    asm volatile(
        "mma.sync.aligned.m16n8k16.row.col.f32.bf16.bf16.f32 "
        "{%0,%1,%2,%3}, {%4,%5,%6,%7}, {%8,%9}, {%0,%1,%2,%3};\n"
        : "+f"(c[0]), "+f"(c[1]), "+f"(c[2]), "+f"(c[3])
        : "r"(a[0]), "r"(a[1]), "r"(a[2]), "r"(a[3]), "r"(b[0]), "r"(b[1]));
}

__device__ __forceinline__ void mma16816h(float* c, const uint32_t* a, const uint32_t* b)
{
    asm volatile(
        "mma.sync.aligned.m16n8k16.row.col.f32.f16.f16.f32 "
        "{%0,%1,%2,%3}, {%4,%5,%6,%7}, {%8,%9}, {%0,%1,%2,%3};\n"
        : "+f"(c[0]), "+f"(c[1]), "+f"(c[2]), "+f"(c[3])
        : "r"(a[0]), "r"(a[1]), "r"(a[2]), "r"(a[3]), "r"(b[0]), "r"(b[1]));
}

__device__ __forceinline__ void ldsm4(uint32_t& r0, uint32_t& r1, uint32_t& r2,
                                      uint32_t& r3, uint32_t a)
{
    asm volatile("ldmatrix.sync.aligned.m8n8.x4.shared.b16 {%0,%1,%2,%3}, [%4];"
                 : "=r"(r0), "=r"(r1), "=r"(r2), "=r"(r3) : "r"(a));
}

#define CP_ASYNC16(sa, gp) \
    asm volatile("cp.async.cg.shared.global [%0], [%1], 16;" :: "r"(sa), "l"(gp))
#define CP_COMMIT() asm volatile("cp.async.commit_group;" ::: "memory")
#define CP_WAIT1()  asm volatile("cp.async.wait_group 1;" ::: "memory")
#define CP_WAIT0()  asm volatile("cp.async.wait_group 0;" ::: "memory")

// ---------------- fp32 -> (hi, lo) packed bf16x2 ----------------------------
__global__ void split_bf16(const float* __restrict__ src,
                           uint32_t* __restrict__ hi, uint32_t* __restrict__ lo,
                           int n2)
{
    int i = blockIdx.x * blockDim.x + threadIdx.x;
    if (i >= n2) return;
    float2 v = ((const float2*)src)[i];
    split2(v.x, v.y, hi[i], lo[i]);
}

// ---------------- split-bf16 GEMM (ldmatrix + cp.async pipeline) -------------
#define GB_ROWB 80
#define GB_ARR  (128 * GB_ROWB)
#define GB_BUF  (4 * GB_ARR)
#define GB_SMEM (2 * GB_BUF)          // 81920 B

__global__ __launch_bounds__(256, 2)
void gemm_ldsm(const uint32_t* __restrict__ Ahg, const uint32_t* __restrict__ Alg,
               const uint32_t* __restrict__ Bhg, const uint32_t* __restrict__ Blg,
               const float* __restrict__ bias, float* __restrict__ C,
               int M, int N, int K2)
{
    extern __shared__ char smem[];
    const uint32_t sbase = smem_u32(smem);
    const int tid = threadIdx.x;
    const int warp = tid >> 5, lane = tid & 31;
    const int wm = (warp & 1) * 64;
    const int wn = (warp >> 1) * 32;
    const int m0 = blockIdx.y * 128;
    const int n0 = blockIdx.x * 128;
    const int nch = K2 / 16;

    const int srow = tid >> 2;
    const int schk = tid & 3;
    const int br0 = (n0 + srow     < N) ? n0 + srow      : N - 1;
    const int br1 = (n0 + srow + 64 < N) ? n0 + srow + 64 : N - 1;

    float acc[4][4][4];
#pragma unroll
    for (int i = 0; i < 4; i++)
#pragma unroll
        for (int j = 0; j < 4; j++)
#pragma unroll
            for (int t = 0; t < 4; t++) acc[i][j][t] = 0.f;

    const int lrow = lane & 15;
    const int lch = lane >> 4;

#define GB_ISSUE(ch) do { \
    const int _buf = (ch) & 1; \
    const uint32_t _sb = sbase + _buf * GB_BUF; \
    const size_t _kc = (size_t)(ch) * 16 + schk * 4; \
    uint32_t _so0 = _sb + srow * GB_ROWB + schk * 16; \
    uint32_t _so1 = _sb + (srow + 64) * GB_ROWB + schk * 16; \
    CP_ASYNC16(_so0,              Ahg + (size_t)(m0 + srow) * K2 + _kc); \
    CP_ASYNC16(_so1,              Ahg + (size_t)(m0 + srow + 64) * K2 + _kc); \
    CP_ASYNC16(_so0 + GB_ARR,     Alg + (size_t)(m0 + srow) * K2 + _kc); \
    CP_ASYNC16(_so1 + GB_ARR,     Alg + (size_t)(m0 + srow + 64) * K2 + _kc); \
    CP_ASYNC16(_so0 + 2*GB_ARR,   Bhg + (size_t)br0 * K2 + _kc); \
    CP_ASYNC16(_so1 + 2*GB_ARR,   Bhg + (size_t)br1 * K2 + _kc); \
    CP_ASYNC16(_so0 + 3*GB_ARR,   Blg + (size_t)br0 * K2 + _kc); \
    CP_ASYNC16(_so1 + 3*GB_ARR,   Blg + (size_t)br1 * K2 + _kc); \
} while (0)

    GB_ISSUE(0); CP_COMMIT();

    for (int ch = 0; ch < nch; ch++) {
        if (ch + 1 < nch) { GB_ISSUE(ch + 1); CP_COMMIT(); CP_WAIT1(); }
        else              { CP_WAIT0(); }
        __syncthreads();

        const uint32_t sb = sbase + (ch & 1) * GB_BUF;
        const uint32_t aH = sb + (wm + lrow) * GB_ROWB + lch * 16;
        const uint32_t aL = aH + GB_ARR;
        const uint32_t bH = sb + 2 * GB_ARR + (wn + lrow) * GB_ROWB + lch * 16;
        const uint32_t bL = bH + GB_ARR;

#pragma unroll
        for (int kk = 0; kk < 2; kk++) {
            uint32_t bh[4][2], bl[4][2];
#pragma unroll
            for (int jj = 0; jj < 2; jj++) {
                uint32_t r0, r1, r2, r3;
                ldsm4(r0, r1, r2, r3, bH + jj * (16 * GB_ROWB) + kk * 32);
                bh[2*jj][0] = r0; bh[2*jj][1] = r2;
                bh[2*jj+1][0] = r1; bh[2*jj+1][1] = r3;
                ldsm4(r0, r1, r2, r3, bL + jj * (16 * GB_ROWB) + kk * 32);
                bl[2*jj][0] = r0; bl[2*jj][1] = r2;
                bl[2*jj+1][0] = r1; bl[2*jj+1][1] = r3;
            }
#pragma unroll
            for (int i = 0; i < 4; i++) {
                uint32_t ah[4], al[4];
                ldsm4(ah[0], ah[1], ah[2], ah[3], aH + i * (16 * GB_ROWB) + kk * 32);
                ldsm4(al[0], al[1], al[2], al[3], aL + i * (16 * GB_ROWB) + kk * 32);
#pragma unroll
                for (int j = 0; j < 4; j++) {
                    mma16816(acc[i][j], ah, bh[j]);
                    mma16816(acc[i][j], ah, bl[j]);
                    mma16816(acc[i][j], al, bh[j]);
                }
            }
        }
        __syncthreads();
    }

    const int lr = lane >> 2, lc = lane & 3;
#pragma unroll
    for (int i = 0; i < 4; i++) {
        int r0 = m0 + wm + i * 16 + lr;
#pragma unroll
        for (int j = 0; j < 4; j++) {
            int c0 = n0 + wn + j * 8 + lc * 2;
            if (c0 < N) {
                float2 bb = *(const float2*)&bias[c0];
                *(float2*)&C[(size_t)r0 * N + c0] =
                    make_float2(acc[i][j][0] + bb.x, acc[i][j][1] + bb.y);
                *(float2*)&C[(size_t)(r0 + 8) * N + c0] =
                    make_float2(acc[i][j][2] + bb.x, acc[i][j][3] + bb.y);
            }
        }
    }
#undef GB_ISSUE
}

// ---------------- RoPE -> fp16 ----------------------------------------------
// Q: single fp16 (pre-scaled).  K: fp16 hi/lo split.
__global__ void rope_q_f16(const float* __restrict__ Q,
                           const float* __restrict__ fc, const float* __restrict__ fs,
                           uint32_t* __restrict__ qf)
{
    int idx = blockIdx.x * blockDim.x + threadIdx.x;
    const int total = BSZ * NH * SEQ * KP;
    if (idx >= total) return;
    int i = idx % KP;
    int s = (idx / KP) % SEQ;
    int h = (idx / (KP * SEQ)) % NH;
    int b = idx / (KP * SEQ * NH);

    size_t base = (size_t)(b * SEQ + s) * DIMC + h * HD;
    float q0 = Q[base + 2 * i];
    float q1 = Q[base + 2 * i + 1];
    float c = fc[s * KP + i];
    float sn = fs[s * KP + i];
    const float scale = 0.083333333333333329f;
    __half2 p = __floats2half2_rn((q0 * c - q1 * sn) * scale,
                                  (q0 * sn + q1 * c) * scale);
    qf[idx] = *reinterpret_cast<uint32_t*>(&p);
}

__global__ void rope_k_split(const float* __restrict__ KV,
                             const float* __restrict__ fc, const float* __restrict__ fs,
                             uint32_t* __restrict__ kh, uint32_t* __restrict__ kl)
{
    int idx = blockIdx.x * blockDim.x + threadIdx.x;
    const int total = BSZ * KVH * SEQ * KP;
    if (idx >= total) return;
    int i = idx % KP;
    int s = (idx / KP) % SEQ;
    int kvh = (idx / (KP * SEQ)) % KVH;
    int b = idx / (KP * SEQ * KVH);

    size_t base = (size_t)(b * SEQ + s) * KVOUT + kvh * HD;
    float k0 = KV[base + 2 * i];
    float k1 = KV[base + 2 * i + 1];
    float c = fc[s * KP + i];
    float sn = fs[s * KP + i];
    split2h(k0 * c - k1 * sn, k0 * sn + k1 * c, kh[idx], kl[idx]);
}

// V transpose + fp16 split: out [b*KVH+kvh][d][sp], pairs along s.
__global__ void v_trans_split(const float* __restrict__ KV,
                              uint32_t* __restrict__ vh, uint32_t* __restrict__ vl)
{
    __shared__ float tile[64][HD + 1];
    const int st = blockIdx.x;
    const int bk = blockIdx.y;
    const int b = bk / KVH, kvh = bk % KVH;
    const int tid = threadIdx.x;

    const float* src = KV + (size_t)(b * SEQ + st * 64) * KVOUT + KVH * HD + kvh * HD;
    for (int e = tid; e < 64 * HD; e += 256) {
        int r = e / HD, c = e % HD;
        tile[r][c] = src[(size_t)r * KVOUT + c];
    }
    __syncthreads();

    uint32_t* oh = vh + ((size_t)bk * HD) * TPH + st * 32;
    uint32_t* ol = vl + ((size_t)bk * HD) * TPH + st * 32;
    for (int e = tid; e < HD * 32; e += 256) {
        int d = e / 32, sp = e % 32;
        uint32_t h, l;
        split2h(tile[2 * sp][d], tile[2 * sp + 1][d], h, l);
        oh[(size_t)d * TPH + sp] = h;
        ol[(size_t)d * TPH + sp] = l;
    }
}

// ---------------- Flash attention -------------------------------------------
// QK: fp16 2-pass (Q single fp16, K fp16 hi/lo).
// PV: fp16 2-pass (P single fp16, V fp16 hi/lo).
#define QS 76
#define KS 76
#define VS 36

#define FLASH_SMEM ((128*QS + 2*64*KS + 2*HD*VS) * (int)sizeof(uint32_t))

__global__ __launch_bounds__(256, 1)
void flash_mma(const uint32_t* __restrict__ qf,
               const uint32_t* __restrict__ kh, const uint32_t* __restrict__ kl,
               const uint32_t* __restrict__ vh, const uint32_t* __restrict__ vl,
               float* __restrict__ out)
{
    extern __shared__ uint32_t fsm[];
    uint32_t* sQ  = fsm;
    uint32_t* sKh = sQ + 128 * QS;
    uint32_t* sKl = sKh + 64 * KS;
    uint32_t* sVh = sKl + 64 * KS;
    uint32_t* sVl = sVh + HD * VS;

    const int qt = (gridDim.x - 1) - blockIdx.x;
    const int bh = blockIdx.y;
    const int b = bh >> 3;
    const int h = bh & 7;
    const int kvh = h >> 2;
    const int bk = b * KVH + kvh;

    const int tid = threadIdx.x;
    const int warp = tid >> 5, lane = tid & 31;
    const int lr = lane >> 2, lc = lane & 3;
    const int wm = warp * 16;

    {
        const uint32_t* gq = qf + ((size_t)bh * SEQ + qt * 128) * KP;
        for (int e = tid; e < 128 * 18; e += 256) {
            int r = e / 18, c = (e % 18) * 4;
            *(uint4*)&sQ[r * QS + c] = *(const uint4*)&gq[(size_t)r * KP + c];
        }
    }

    float o[18][4];
#pragma unroll
    for (int n = 0; n < 18; n++)
#pragma unroll
        for (int t = 0; t < 4; t++) o[n][t] = 0.f;
    float m0 = -1e30f, m1 = -1e30f, l0 = 0.f, l1 = 0.f;

    const int ktmax = 2 * qt + 1;
    const int qrow0 = qt * 128 + wm;

    for (int kt = 0; kt <= ktmax; kt++) {
        __syncthreads();
        {
            const uint32_t* gkh = kh + ((size_t)bk * SEQ + kt * 64) * KP;
            const uint32_t* gkl = kl + ((size_t)bk * SEQ + kt * 64) * KP;
            for (int e = tid; e < 64 * 18; e += 256) {
                int r = e / 18, c = (e % 18) * 4;
                *(uint4*)&sKh[r * KS + c] = *(const uint4*)&gkh[(size_t)r * KP + c];
                *(uint4*)&sKl[r * KS + c] = *(const uint4*)&gkl[(size_t)r * KP + c];
            }
            const uint32_t* gvh = vh + (size_t)bk * HD * TPH + kt * 32;
            const uint32_t* gvl = vl + (size_t)bk * HD * TPH + kt * 32;
            for (int e = tid; e < HD * 8; e += 256) {
                int r = e / 8, c = (e % 8) * 4;
                *(uint4*)&sVh[r * VS + c] = *(const uint4*)&gvh[(size_t)r * TPH + c];
                *(uint4*)&sVl[r * VS + c] = *(const uint4*)&gvl[(size_t)r * TPH + c];
            }
        }
        __syncthreads();

        float sfr[8][4];
#pragma unroll
        for (int j = 0; j < 8; j++)
#pragma unroll
            for (int t = 0; t < 4; t++) sfr[j][t] = 0.f;

#pragma unroll
        for (int kc = 0; kc < 9; kc++) {
            uint32_t ah[4];
            int ra = (wm + lr) * QS + kc * 8 + lc;
            int rb = (wm + lr + 8) * QS + kc * 8 + lc;
            ah[0] = sQ[ra];     ah[1] = sQ[rb];
            ah[2] = sQ[ra + 4]; ah[3] = sQ[rb + 4];
#pragma unroll
            for (int j = 0; j < 8; j++) {
                int rk = (j * 8 + lr) * KS + kc * 8 + lc;
                uint32_t bh2[2] = { sKh[rk], sKh[rk + 4] };
                uint32_t bl2[2] = { sKl[rk], sKl[rk + 4] };
                mma16816h(sfr[j], ah, bh2);
                mma16816h(sfr[j], ah, bl2);
            }
        }

        if (kt * 64 + 63 > qrow0) {
            int key0 = kt * 64;
#pragma unroll
            for (int j = 0; j < 8; j++) {
                int kc0 = key0 + j * 8 + 2 * lc;
                if (kc0     > qrow0 + lr)     sfr[j][0] = -1e9f;
                if (kc0 + 1 > qrow0 + lr)     sfr[j][1] = -1e9f;
                if (kc0     > qrow0 + lr + 8) sfr[j][2] = -1e9f;
                if (kc0 + 1 > qrow0 + lr + 8) sfr[j][3] = -1e9f;
            }
        }

        float mx0 = -1e30f, mx1 = -1e30f;
#pragma unroll
        for (int j = 0; j < 8; j++) {
            mx0 = fmaxf(mx0, fmaxf(sfr[j][0], sfr[j][1]));
            mx1 = fmaxf(mx1, fmaxf(sfr[j][2], sfr[j][3]));
        }
#pragma unroll
        for (int off = 1; off < 4; off <<= 1) {
            mx0 = fmaxf(mx0, __shfl_xor_sync(0xffffffffu, mx0, off));
            mx1 = fmaxf(mx1, __shfl_xor_sync(0xffffffffu, mx1, off));
        }
        float mn0 = fmaxf(m0, mx0), mn1 = fmaxf(m1, mx1);
        float c0 = __expf(m0 - mn0), c1 = __expf(m1 - mn1);
        m0 = mn0; m1 = mn1;

        float s0 = 0.f, s1 = 0.f;
#pragma unroll
        for (int j = 0; j < 8; j++) {
            sfr[j][0] = __expf(sfr[j][0] - m0);
            sfr[j][1] = __expf(sfr[j][1] - m0);
            sfr[j][2] = __expf(sfr[j][2] - m1);
            sfr[j][3] = __expf(sfr[j][3] - m1);
            s0 += sfr[j][0] + sfr[j][1];
            s1 += sfr[j][2] + sfr[j][3];
        }
#pragma unroll
        for (int off = 1; off < 4; off <<= 1) {
            s0 += __shfl_xor_sync(0xffffffffu, s0, off);
            s1 += __shfl_xor_sync(0xffffffffu, s1, off);
        }
        l0 = l0 * c0 + s0;
        l1 = l1 * c1 + s1;

#pragma unroll
        for (int n = 0; n < 18; n++) {
            o[n][0] *= c0; o[n][1] *= c0;
            o[n][2] *= c1; o[n][3] *= c1;
        }

        // P -> single fp16 fragments
        uint32_t ph01[8], ph23[8];
#pragma unroll
        for (int j = 0; j < 8; j++) {
            __half2 p0 = __floats2half2_rn(sfr[j][0], sfr[j][1]);
            __half2 p1 = __floats2half2_rn(sfr[j][2], sfr[j][3]);
            ph01[j] = *reinterpret_cast<uint32_t*>(&p0);
            ph23[j] = *reinterpret_cast<uint32_t*>(&p1);
        }

        // O += P (V_hi + V_lo) -- fp16 2-pass
#pragma unroll
        for (int kc = 0; kc < 4; kc++) {
            uint32_t pa[4] = { ph01[2*kc], ph23[2*kc], ph01[2*kc+1], ph23[2*kc+1] };
#pragma unroll
            for (int n = 0; n < 18; n++) {
                int rv = (n * 8 + lr) * VS + kc * 8 + lc;
                uint32_t bh2[2] = { sVh[rv], sVh[rv + 4] };
                uint32_t bl2[2] = { sVl[rv], sVl[rv + 4] };
                mma16816h(o[n], pa, bh2);
                mma16816h(o[n], pa, bl2);
            }
        }
    }

    float inv0 = 1.f / l0, inv1 = 1.f / l1;
    int r0 = qt * 128 + wm + lr;
    float* orow0 = out + ((size_t)b * SEQ + r0)     * DIMC + h * HD;
    float* orow1 = out + ((size_t)b * SEQ + r0 + 8) * DIMC + h * HD;
#pragma unroll
    for (int n = 0; n < 18; n++) {
        int col = n * 8 + 2 * lc;
        *(float2*)&orow0[col] = make_float2(o[n][0] * inv0, o[n][1] * inv0);
        *(float2*)&orow1[col] = make_float2(o[n][2] * inv1, o[n][3] * inv1);
    }
}

// ---------------- launcher --------------------------------------------------
extern "C" void kernel_launch(void* const* d_in, const int* in_sizes, int n_in,
                              void* d_out, int out_size)
{
    const float* x   = (const float*)d_in[0];
    const float* wq  = (const float*)d_in[1];
    const float* bq  = (const float*)d_in[2];
    const float* wkv = (const float*)d_in[3];
    const float* bkv = (const float*)d_in[4];
    const float* wo  = (const float*)d_in[5];
    const float* bo  = (const float*)d_in[6];
    const float* fc  = (const float*)d_in[7];
    const float* fs  = (const float*)d_in[8];
    float* out = (float*)d_out;

    float *gq, *gkv, *gat;
    uint32_t *xh, *xl, *wqh, *wql, *wkh, *wkl, *woh, *wol, *ah, *al;
    uint32_t *qf, *kh, *kl, *vh, *vl;
    cudaGetSymbolAddress((void**)&gq,  g_q);
    cudaGetSymbolAddress((void**)&gkv, g_kv);
    cudaGetSymbolAddress((void**)&gat, g_attn);
    cudaGetSymbolAddress((void**)&xh,  g_xh);
    cudaGetSymbolAddress((void**)&xl,  g_xl);
    cudaGetSymbolAddress((void**)&wqh, g_wqh);
    cudaGetSymbolAddress((void**)&wql, g_wql);
    cudaGetSymbolAddress((void**)&wkh, g_wkh);
    cudaGetSymbolAddress((void**)&wkl, g_wkl);
    cudaGetSymbolAddress((void**)&woh, g_woh);
    cudaGetSymbolAddress((void**)&wol, g_wol);
    cudaGetSymbolAddress((void**)&ah,  g_ah);
    cudaGetSymbolAddress((void**)&al,  g_al);
    cudaGetSymbolAddress((void**)&qf,  g_qf);
    cudaGetSymbolAddress((void**)&kh,  g_kh);
    cudaGetSymbolAddress((void**)&kl,  g_kl);
    cudaGetSymbolAddress((void**)&vh,  g_vh);
    cudaGetSymbolAddress((void**)&vl,  g_vl);

    cudaFuncSetAttribute(flash_mma, cudaFuncAttributeMaxDynamicSharedMemorySize,
                         FLASH_SMEM);
    cudaFuncSetAttribute(gemm_ldsm, cudaFuncAttributeMaxDynamicSharedMemorySize,
                         GB_SMEM);

    // split GEMM inputs
    {
        int nx = MROWS * K2DIM;
        split_bf16<<<(nx + 255) / 256, 256>>>(x, xh, xl, nx);
        int nq = DIMC * K2DIM;
        split_bf16<<<(nq + 255) / 256, 256>>>(wq, wqh, wql, nq);
        int nk = KVOUT * K2DIM;
        split_bf16<<<(nk + 255) / 256, 256>>>(wkv, wkh, wkl, nk);
        split_bf16<<<(nq + 255) / 256, 256>>>(wo, woh, wol, nq);
    }

    // projections
    gemm_ldsm<<<dim3(DIMC / 128, MROWS / 128), 256, GB_SMEM>>>(
        xh, xl, wqh, wql, bq, gq, MROWS, DIMC, K2DIM);
    gemm_ldsm<<<dim3((KVOUT + 127) / 128, MROWS / 128), 256, GB_SMEM>>>(
        xh, xl, wkh, wkl, bkv, gkv, MROWS, KVOUT, K2DIM);

    // RoPE + fp16 conversion + V transpose
    {
        int tq = BSZ * NH * SEQ * KP;
        rope_q_f16<<<(tq + 255) / 256, 256>>>(gq, fc, fs, qf);
        int tk = BSZ * KVH * SEQ * KP;
        rope_k_split<<<(tk + 255) / 256, 256>>>(gkv, fc, fs, kh, kl);
        v_trans_split<<<dim3(SEQ / 64, BSZ * KVH), 256>>>(gkv, vh, vl);
    }

    // attention
    flash_mma<<<dim3(SEQ / 128, BSZ * NH), 256, FLASH_SMEM>>>(
        qf, kh, kl, vh, vl, gat);

    // output projection
    {
        int na = MROWS * K2DIM;
        split_bf16<<<(na + 255) / 256, 256>>>(gat, ah, al, na);
    }
    gemm_ldsm<<<dim3(DIMC / 128, MROWS / 128), 256, GB_SMEM>>>(
        ah, al, woh, wol, bo, out, MROWS, DIMC, K2DIM);
}

// round 11
// speedup vs baseline: 1.8233x; 1.1890x over previous
#include <cuda_runtime.h>
#include <cuda_bf16.h>
#include <cuda_fp16.h>
#include <math.h>
#include <stdint.h>

// Problem constants
#define DIMC   1152
#define NH     8
#define KVH    2
#define HD     144
#define BSZ    4
#define SEQ    2048
#define MROWS  (BSZ*SEQ)          // 8192
#define KVOUT  (2*KVH*HD)         // 576
#define K2DIM  (DIMC/2)           // 576
#define KP     72                 // pairs per head row
#define TPH    (SEQ/2)            // seq pairs for V^T

// ---------------- scratch (device globals) ----------------------------------
__device__ float g_q   [(size_t)MROWS * DIMC];
__device__ float g_kv  [(size_t)MROWS * KVOUT];
__device__ float g_attn[(size_t)MROWS * DIMC];

// GEMM operands: A single fp16, weights fp16 hi/lo
__device__ uint32_t g_xf [(size_t)MROWS * K2DIM];   // x fp16
__device__ uint32_t g_wqh[(size_t)DIMC  * K2DIM];
__device__ uint32_t g_wql[(size_t)DIMC  * K2DIM];
__device__ uint32_t g_wkh[(size_t)KVOUT * K2DIM];
__device__ uint32_t g_wkl[(size_t)KVOUT * K2DIM];
__device__ uint32_t g_woh[(size_t)DIMC  * K2DIM];
__device__ uint32_t g_wol[(size_t)DIMC  * K2DIM];
__device__ uint32_t g_af [(size_t)MROWS * K2DIM];   // attn out fp16

// attention operands
__device__ uint32_t g_qf[(size_t)BSZ*NH *SEQ*KP];   // Q single fp16 pairs
__device__ uint32_t g_kh[(size_t)BSZ*KVH*SEQ*KP];   // K fp16 hi
__device__ uint32_t g_kl[(size_t)BSZ*KVH*SEQ*KP];   // K fp16 lo
__device__ uint32_t g_vh[(size_t)BSZ*KVH*HD*TPH];   // V^T fp16 hi, pairs along s
__device__ uint32_t g_vl[(size_t)BSZ*KVH*HD*TPH];   // V^T fp16 lo

// ---------------- helpers ----------------------------------------------------
__device__ __forceinline__ uint32_t smem_u32(const void* p) {
    uint32_t a;
    asm("{ .reg .u64 t; cvta.to.shared.u64 t, %1; cvt.u32.u64 %0, t; }"
        : "=r"(a) : "l"(p));
    return a;
}

__device__ __forceinline__ void split2h(float x, float y, uint32_t& hi, uint32_t& lo)
{
    __half2 h = __floats2half2_rn(x, y);
    float2 hf = __half22float2(h);
    __half2 l = __floats2half2_rn(x - hf.x, y - hf.y);
    hi = *reinterpret_cast<uint32_t*>(&h);
    lo = *reinterpret_cast<uint32_t*>(&l);
}

__device__ __forceinline__ void mma16816h(float* c, const uint32_t* a, const uint32_t* b)
{
    asm volatile(
        "mma.sync.aligned.m16n8k16.row.col.f32.f16.f16.f32 "
        "{%0,%1,%2,%3}, {%4,%5,%6,%7}, {%8,%9}, {%0,%1,%2,%3};\n"
        : "+f"(c[0]), "+f"(c[1]), "+f"(c[2]), "+f"(c[3])
        : "r"(a[0]), "r"(a[1]), "r"(a[2]), "r"(a[3]), "r"(b[0]), "r"(b[1]));
}

__device__ __forceinline__ void ldsm4(uint32_t& r0, uint32_t& r1, uint32_t& r2,
                                      uint32_t& r3, uint32_t a)
{
    asm volatile("ldmatrix.sync.aligned.m8n8.x4.shared.b16 {%0,%1,%2,%3}, [%4];"
                 : "=r"(r0), "=r"(r1), "=r"(r2), "=r"(r3) : "r"(a));
}

#define CP_ASYNC16(sa, gp) \
    asm volatile("cp.async.cg.shared.global [%0], [%1], 16;" :: "r"(sa), "l"(gp))
#define CP_COMMIT() asm volatile("cp.async.commit_group;" ::: "memory")
#define CP_WAIT1()  asm volatile("cp.async.wait_group 1;" ::: "memory")
#define CP_WAIT0()  asm volatile("cp.async.wait_group 0;" ::: "memory")

// ---------------- conversion kernels ----------------------------------------
__global__ void conv_f16(const float* __restrict__ src, uint32_t* __restrict__ dst,
                         int n2)
{
    int i = blockIdx.x * blockDim.x + threadIdx.x;
    if (i >= n2) return;
    float2 v = ((const float2*)src)[i];
    __half2 h = __floats2half2_rn(v.x, v.y);
    dst[i] = *reinterpret_cast<uint32_t*>(&h);
}

__global__ void split_f16(const float* __restrict__ src,
                          uint32_t* __restrict__ hi, uint32_t* __restrict__ lo,
                          int n2)
{
    int i = blockIdx.x * blockDim.x + threadIdx.x;
    if (i >= n2) return;
    float2 v = ((const float2*)src)[i];
    split2h(v.x, v.y, hi[i], lo[i]);
}

// ---------------- fp16 2-pass GEMM (ldmatrix + cp.async) --------------------
// C[M,N] = A[M,K]@B[N,K]^T + bias;  A single fp16, B fp16 hi/lo.
// acc = A*Bh + A*Bl  (exact except A's fp16 rounding).
#define GB_ROWB 80
#define GB_ARR  (128 * GB_ROWB)
#define GB_BUF  (3 * GB_ARR)          // A, Bh, Bl
#define GB_SMEM (2 * GB_BUF)          // 61440 B

__global__ __launch_bounds__(256, 2)
void gemm_ldsm(const uint32_t* __restrict__ Ag,
               const uint32_t* __restrict__ Bhg, const uint32_t* __restrict__ Blg,
               const float* __restrict__ bias, float* __restrict__ C,
               int M, int N, int K2)
{
    extern __shared__ char smem[];
    const uint32_t sbase = smem_u32(smem);
    const int tid = threadIdx.x;
    const int warp = tid >> 5, lane = tid & 31;
    const int wm = (warp & 1) * 64;
    const int wn = (warp >> 1) * 32;
    const int m0 = blockIdx.y * 128;
    const int n0 = blockIdx.x * 128;
    const int nch = K2 / 16;

    const int srow = tid >> 2;
    const int schk = tid & 3;
    const int br0 = (n0 + srow     < N) ? n0 + srow      : N - 1;
    const int br1 = (n0 + srow + 64 < N) ? n0 + srow + 64 : N - 1;

    float acc[4][4][4];
#pragma unroll
    for (int i = 0; i < 4; i++)
#pragma unroll
        for (int j = 0; j < 4; j++)
#pragma unroll
            for (int t = 0; t < 4; t++) acc[i][j][t] = 0.f;

    const int lrow = lane & 15;
    const int lch = lane >> 4;

#define GB_ISSUE(ch) do { \
    const int _buf = (ch) & 1; \
    const uint32_t _sb = sbase + _buf * GB_BUF; \
    const size_t _kc = (size_t)(ch) * 16 + schk * 4; \
    uint32_t _so0 = _sb + srow * GB_ROWB + schk * 16; \
    uint32_t _so1 = _sb + (srow + 64) * GB_ROWB + schk * 16; \
    CP_ASYNC16(_so0,              Ag  + (size_t)(m0 + srow) * K2 + _kc); \
    CP_ASYNC16(_so1,              Ag  + (size_t)(m0 + srow + 64) * K2 + _kc); \
    CP_ASYNC16(_so0 + GB_ARR,     Bhg + (size_t)br0 * K2 + _kc); \
    CP_ASYNC16(_so1 + GB_ARR,     Bhg + (size_t)br1 * K2 + _kc); \
    CP_ASYNC16(_so0 + 2*GB_ARR,   Blg + (size_t)br0 * K2 + _kc); \
    CP_ASYNC16(_so1 + 2*GB_ARR,   Blg + (size_t)br1 * K2 + _kc); \
} while (0)

    GB_ISSUE(0); CP_COMMIT();

    for (int ch = 0; ch < nch; ch++) {
        if (ch + 1 < nch) { GB_ISSUE(ch + 1); CP_COMMIT(); CP_WAIT1(); }
        else              { CP_WAIT0(); }
        __syncthreads();

        const uint32_t sb = sbase + (ch & 1) * GB_BUF;
        const uint32_t aA = sb + (wm + lrow) * GB_ROWB + lch * 16;
        const uint32_t bH = sb + GB_ARR + (wn + lrow) * GB_ROWB + lch * 16;
        const uint32_t bL = bH + GB_ARR;

#pragma unroll
        for (int kk = 0; kk < 2; kk++) {
            uint32_t bh[4][2], bl[4][2];
#pragma unroll
            for (int jj = 0; jj < 2; jj++) {
                uint32_t r0, r1, r2, r3;
                ldsm4(r0, r1, r2, r3, bH + jj * (16 * GB_ROWB) + kk * 32);
                bh[2*jj][0] = r0; bh[2*jj][1] = r2;
                bh[2*jj+1][0] = r1; bh[2*jj+1][1] = r3;
                ldsm4(r0, r1, r2, r3, bL + jj * (16 * GB_ROWB) + kk * 32);
                bl[2*jj][0] = r0; bl[2*jj][1] = r2;
                bl[2*jj+1][0] = r1; bl[2*jj+1][1] = r3;
            }
#pragma unroll
            for (int i = 0; i < 4; i++) {
                uint32_t ah[4];
                ldsm4(ah[0], ah[1], ah[2], ah[3], aA + i * (16 * GB_ROWB) + kk * 32);
#pragma unroll
                for (int j = 0; j < 4; j++) {
                    mma16816h(acc[i][j], ah, bh[j]);
                    mma16816h(acc[i][j], ah, bl[j]);
                }
            }
        }
        __syncthreads();
    }

    const int lr = lane >> 2, lc = lane & 3;
#pragma unroll
    for (int i = 0; i < 4; i++) {
        int r0 = m0 + wm + i * 16 + lr;
#pragma unroll
        for (int j = 0; j < 4; j++) {
            int c0 = n0 + wn + j * 8 + lc * 2;
            if (c0 < N) {
                float2 bb = *(const float2*)&bias[c0];
                *(float2*)&C[(size_t)r0 * N + c0] =
                    make_float2(acc[i][j][0] + bb.x, acc[i][j][1] + bb.y);
                *(float2*)&C[(size_t)(r0 + 8) * N + c0] =
                    make_float2(acc[i][j][2] + bb.x, acc[i][j][3] + bb.y);
            }
        }
    }
#undef GB_ISSUE
}

// ---------------- RoPE -> fp16 ----------------------------------------------
__global__ void rope_q_f16(const float* __restrict__ Q,
                           const float* __restrict__ fc, const float* __restrict__ fs,
                           uint32_t* __restrict__ qf)
{
    int idx = blockIdx.x * blockDim.x + threadIdx.x;
    const int total = BSZ * NH * SEQ * KP;
    if (idx >= total) return;
    int i = idx % KP;
    int s = (idx / KP) % SEQ;
    int h = (idx / (KP * SEQ)) % NH;
    int b = idx / (KP * SEQ * NH);

    size_t base = (size_t)(b * SEQ + s) * DIMC + h * HD;
    float q0 = Q[base + 2 * i];
    float q1 = Q[base + 2 * i + 1];
    float c = fc[s * KP + i];
    float sn = fs[s * KP + i];
    const float scale = 0.083333333333333329f;
    __half2 p = __floats2half2_rn((q0 * c - q1 * sn) * scale,
                                  (q0 * sn + q1 * c) * scale);
    qf[idx] = *reinterpret_cast<uint32_t*>(&p);
}

__global__ void rope_k_split(const float* __restrict__ KV,
                             const float* __restrict__ fc, const float* __restrict__ fs,
                             uint32_t* __restrict__ kh, uint32_t* __restrict__ kl)
{
    int idx = blockIdx.x * blockDim.x + threadIdx.x;
    const int total = BSZ * KVH * SEQ * KP;
    if (idx >= total) return;
    int i = idx % KP;
    int s = (idx / KP) % SEQ;
    int kvh = (idx / (KP * SEQ)) % KVH;
    int b = idx / (KP * SEQ * KVH);

    size_t base = (size_t)(b * SEQ + s) * KVOUT + kvh * HD;
    float k0 = KV[base + 2 * i];
    float k1 = KV[base + 2 * i + 1];
    float c = fc[s * KP + i];
    float sn = fs[s * KP + i];
    split2h(k0 * c - k1 * sn, k0 * sn + k1 * c, kh[idx], kl[idx]);
}

// V transpose + fp16 split: out [b*KVH+kvh][d][sp], pairs along s.
__global__ void v_trans_split(const float* __restrict__ KV,
                              uint32_t* __restrict__ vh, uint32_t* __restrict__ vl)
{
    __shared__ float tile[64][HD + 1];
    const int st = blockIdx.x;
    const int bk = blockIdx.y;
    const int b = bk / KVH, kvh = bk % KVH;
    const int tid = threadIdx.x;

    const float* src = KV + (size_t)(b * SEQ + st * 64) * KVOUT + KVH * HD + kvh * HD;
    for (int e = tid; e < 64 * HD; e += 256) {
        int r = e / HD, c = e % HD;
        tile[r][c] = src[(size_t)r * KVOUT + c];
    }
    __syncthreads();

    uint32_t* oh = vh + ((size_t)bk * HD) * TPH + st * 32;
    uint32_t* ol = vl + ((size_t)bk * HD) * TPH + st * 32;
    for (int e = tid; e < HD * 32; e += 256) {
        int d = e / 32, sp = e % 32;
        uint32_t h, l;
        split2h(tile[2 * sp][d], tile[2 * sp + 1][d], h, l);
        oh[(size_t)d * TPH + sp] = h;
        ol[(size_t)d * TPH + sp] = l;
    }
}

// ---------------- Flash attention -------------------------------------------
// QK: fp16 2-pass (Q single fp16, K fp16 hi/lo).
// PV: fp16 2-pass (P single fp16, V fp16 hi/lo).
#define QS 76
#define KS 76
#define VS 36

#define FLASH_SMEM ((128*QS + 2*64*KS + 2*HD*VS) * (int)sizeof(uint32_t))

__global__ __launch_bounds__(256, 1)
void flash_mma(const uint32_t* __restrict__ qf,
               const uint32_t* __restrict__ kh, const uint32_t* __restrict__ kl,
               const uint32_t* __restrict__ vh, const uint32_t* __restrict__ vl,
               float* __restrict__ out)
{
    extern __shared__ uint32_t fsm[];
    uint32_t* sQ  = fsm;
    uint32_t* sKh = sQ + 128 * QS;
    uint32_t* sKl = sKh + 64 * KS;
    uint32_t* sVh = sKl + 64 * KS;
    uint32_t* sVl = sVh + HD * VS;

    const int qt = (gridDim.x - 1) - blockIdx.x;
    const int bh = blockIdx.y;
    const int b = bh >> 3;
    const int h = bh & 7;
    const int kvh = h >> 2;
    const int bk = b * KVH + kvh;

    const int tid = threadIdx.x;
    const int warp = tid >> 5, lane = tid & 31;
    const int lr = lane >> 2, lc = lane & 3;
    const int wm = warp * 16;

    {
        const uint32_t* gq = qf + ((size_t)bh * SEQ + qt * 128) * KP;
        for (int e = tid; e < 128 * 18; e += 256) {
            int r = e / 18, c = (e % 18) * 4;
            *(uint4*)&sQ[r * QS + c] = *(const uint4*)&gq[(size_t)r * KP + c];
        }
    }

    float o[18][4];
#pragma unroll
    for (int n = 0; n < 18; n++)
#pragma unroll
        for (int t = 0; t < 4; t++) o[n][t] = 0.f;
    float m0 = -1e30f, m1 = -1e30f, l0 = 0.f, l1 = 0.f;

    const int ktmax = 2 * qt + 1;
    const int qrow0 = qt * 128 + wm;

    for (int kt = 0; kt <= ktmax; kt++) {
        __syncthreads();
        {
            const uint32_t* gkh = kh + ((size_t)bk * SEQ + kt * 64) * KP;
            const uint32_t* gkl = kl + ((size_t)bk * SEQ + kt * 64) * KP;
            for (int e = tid; e < 64 * 18; e += 256) {
                int r = e / 18, c = (e % 18) * 4;
                *(uint4*)&sKh[r * KS + c] = *(const uint4*)&gkh[(size_t)r * KP + c];
                *(uint4*)&sKl[r * KS + c] = *(const uint4*)&gkl[(size_t)r * KP + c];
            }
            const uint32_t* gvh = vh + (size_t)bk * HD * TPH + kt * 32;
            const uint32_t* gvl = vl + (size_t)bk * HD * TPH + kt * 32;
            for (int e = tid; e < HD * 8; e += 256) {
                int r = e / 8, c = (e % 8) * 4;
                *(uint4*)&sVh[r * VS + c] = *(const uint4*)&gvh[(size_t)r * TPH + c];
                *(uint4*)&sVl[r * VS + c] = *(const uint4*)&gvl[(size_t)r * TPH + c];
            }
        }
        __syncthreads();

        float sfr[8][4];
#pragma unroll
        for (int j = 0; j < 8; j++)
#pragma unroll
            for (int t = 0; t < 4; t++) sfr[j][t] = 0.f;

#pragma unroll
        for (int kc = 0; kc < 9; kc++) {
            uint32_t ah[4];
            int ra = (wm + lr) * QS + kc * 8 + lc;
            int rb = (wm + lr + 8) * QS + kc * 8 + lc;
            ah[0] = sQ[ra];     ah[1] = sQ[rb];
            ah[2] = sQ[ra + 4]; ah[3] = sQ[rb + 4];
#pragma unroll
            for (int j = 0; j < 8; j++) {
                int rk = (j * 8 + lr) * KS + kc * 8 + lc;
                uint32_t bh2[2] = { sKh[rk], sKh[rk + 4] };
                uint32_t bl2[2] = { sKl[rk], sKl[rk + 4] };
                mma16816h(sfr[j], ah, bh2);
                mma16816h(sfr[j], ah, bl2);
            }
        }

        if (kt * 64 + 63 > qrow0) {
            int key0 = kt * 64;
#pragma unroll
            for (int j = 0; j < 8; j++) {
                int kc0 = key0 + j * 8 + 2 * lc;
                if (kc0     > qrow0 + lr)     sfr[j][0] = -1e9f;
                if (kc0 + 1 > qrow0 + lr)     sfr[j][1] = -1e9f;
                if (kc0     > qrow0 + lr + 8) sfr[j][2] = -1e9f;
                if (kc0 + 1 > qrow0 + lr + 8) sfr[j][3] = -1e9f;
            }
        }

        float mx0 = -1e30f, mx1 = -1e30f;
#pragma unroll
        for (int j = 0; j < 8; j++) {
            mx0 = fmaxf(mx0, fmaxf(sfr[j][0], sfr[j][1]));
            mx1 = fmaxf(mx1, fmaxf(sfr[j][2], sfr[j][3]));
        }
#pragma unroll
        for (int off = 1; off < 4; off <<= 1) {
            mx0 = fmaxf(mx0, __shfl_xor_sync(0xffffffffu, mx0, off));
            mx1 = fmaxf(mx1, __shfl_xor_sync(0xffffffffu, mx1, off));
        }
        float mn0 = fmaxf(m0, mx0), mn1 = fmaxf(m1, mx1);
        float c0 = __expf(m0 - mn0), c1 = __expf(m1 - mn1);
        m0 = mn0; m1 = mn1;

        float s0 = 0.f, s1 = 0.f;
#pragma unroll
        for (int j = 0; j < 8; j++) {
            sfr[j][0] = __expf(sfr[j][0] - m0);
            sfr[j][1] = __expf(sfr[j][1] - m0);
            sfr[j][2] = __expf(sfr[j][2] - m1);
            sfr[j][3] = __expf(sfr[j][3] - m1);
            s0 += sfr[j][0] + sfr[j][1];
            s1 += sfr[j][2] + sfr[j][3];
        }
#pragma unroll
        for (int off = 1; off < 4; off <<= 1) {
            s0 += __shfl_xor_sync(0xffffffffu, s0, off);
            s1 += __shfl_xor_sync(0xffffffffu, s1, off);
        }
        l0 = l0 * c0 + s0;
        l1 = l1 * c1 + s1;

#pragma unroll
        for (int n = 0; n < 18; n++) {
            o[n][0] *= c0; o[n][1] *= c0;
            o[n][2] *= c1; o[n][3] *= c1;
        }

        // P -> single fp16 fragments
        uint32_t ph01[8], ph23[8];
#pragma unroll
        for (int j = 0; j < 8; j++) {
            __half2 p0 = __floats2half2_rn(sfr[j][0], sfr[j][1]);
            __half2 p1 = __floats2half2_rn(sfr[j][2], sfr[j][3]);
            ph01[j] = *reinterpret_cast<uint32_t*>(&p0);
            ph23[j] = *reinterpret_cast<uint32_t*>(&p1);
        }

        // O += P (V_hi + V_lo) -- fp16 2-pass
#pragma unroll
        for (int kc = 0; kc < 4; kc++) {
            uint32_t pa[4] = { ph01[2*kc], ph23[2*kc], ph01[2*kc+1], ph23[2*kc+1] };
#pragma unroll
            for (int n = 0; n < 18; n++) {
                int rv = (n * 8 + lr) * VS + kc * 8 + lc;
                uint32_t bh2[2] = { sVh[rv], sVh[rv + 4] };
                uint32_t bl2[2] = { sVl[rv], sVl[rv + 4] };
                mma16816h(o[n], pa, bh2);
                mma16816h(o[n], pa, bl2);
            }
        }
    }

    float inv0 = 1.f / l0, inv1 = 1.f / l1;
    int r0 = qt * 128 + wm + lr;
    float* orow0 = out + ((size_t)b * SEQ + r0)     * DIMC + h * HD;
    float* orow1 = out + ((size_t)b * SEQ + r0 + 8) * DIMC + h * HD;
#pragma unroll
    for (int n = 0; n < 18; n++) {
        int col = n * 8 + 2 * lc;
        *(float2*)&orow0[col] = make_float2(o[n][0] * inv0, o[n][1] * inv0);
        *(float2*)&orow1[col] = make_float2(o[n][2] * inv1, o[n][3] * inv1);
    }
}

// ---------------- launcher --------------------------------------------------
extern "C" void kernel_launch(void* const* d_in, const int* in_sizes, int n_in,
                              void* d_out, int out_size)
{
    const float* x   = (const float*)d_in[0];
    const float* wq  = (const float*)d_in[1];
    const float* bq  = (const float*)d_in[2];
    const float* wkv = (const float*)d_in[3];
    const float* bkv = (const float*)d_in[4];
    const float* wo  = (const float*)d_in[5];
    const float* bo  = (const float*)d_in[6];
    const float* fc  = (const float*)d_in[7];
    const float* fs  = (const float*)d_in[8];
    float* out = (float*)d_out;

    float *gq, *gkv, *gat;
    uint32_t *xf, *wqh, *wql, *wkh, *wkl, *woh, *wol, *af;
    uint32_t *qf, *kh, *kl, *vh, *vl;
    cudaGetSymbolAddress((void**)&gq,  g_q);
    cudaGetSymbolAddress((void**)&gkv, g_kv);
    cudaGetSymbolAddress((void**)&gat, g_attn);
    cudaGetSymbolAddress((void**)&xf,  g_xf);
    cudaGetSymbolAddress((void**)&wqh, g_wqh);
    cudaGetSymbolAddress((void**)&wql, g_wql);
    cudaGetSymbolAddress((void**)&wkh, g_wkh);
    cudaGetSymbolAddress((void**)&wkl, g_wkl);
    cudaGetSymbolAddress((void**)&woh, g_woh);
    cudaGetSymbolAddress((void**)&wol, g_wol);
    cudaGetSymbolAddress((void**)&af,  g_af);
    cudaGetSymbolAddress((void**)&qf,  g_qf);
    cudaGetSymbolAddress((void**)&kh,  g_kh);
    cudaGetSymbolAddress((void**)&kl,  g_kl);
    cudaGetSymbolAddress((void**)&vh,  g_vh);
    cudaGetSymbolAddress((void**)&vl,  g_vl);

    cudaFuncSetAttribute(flash_mma, cudaFuncAttributeMaxDynamicSharedMemorySize,
                         FLASH_SMEM);
    cudaFuncSetAttribute(gemm_ldsm, cudaFuncAttributeMaxDynamicSharedMemorySize,
                         GB_SMEM);

    // prepare GEMM operands
    {
        int nx = MROWS * K2DIM;
        conv_f16<<<(nx + 255) / 256, 256>>>(x, xf, nx);
        int nq = DIMC * K2DIM;
        split_f16<<<(nq + 255) / 256, 256>>>(wq, wqh, wql, nq);
        int nk = KVOUT * K2DIM;
        split_f16<<<(nk + 255) / 256, 256>>>(wkv, wkh, wkl, nk);
        split_f16<<<(nq + 255) / 256, 256>>>(wo, woh, wol, nq);
    }

    // projections (fp16 2-pass)
    gemm_ldsm<<<dim3(DIMC / 128, MROWS / 128), 256, GB_SMEM>>>(
        xf, wqh, wql, bq, gq, MROWS, DIMC, K2DIM);
    gemm_ldsm<<<dim3((KVOUT + 127) / 128, MROWS / 128), 256, GB_SMEM>>>(
        xf, wkh, wkl, bkv, gkv, MROWS, KVOUT, K2DIM);

    // RoPE + fp16 conversion + V transpose
    {
        int tq = BSZ * NH * SEQ * KP;
        rope_q_f16<<<(tq + 255) / 256, 256>>>(gq, fc, fs, qf);
        int tk = BSZ * KVH * SEQ * KP;
        rope_k_split<<<(tk + 255) / 256, 256>>>(gkv, fc, fs, kh, kl);
        v_trans_split<<<dim3(SEQ / 64, BSZ * KVH), 256>>>(gkv, vh, vl);
    }

    // attention
    flash_mma<<<dim3(SEQ / 128, BSZ * NH), 256, FLASH_SMEM>>>(
        qf, kh, kl, vh, vl, gat);

    // output projection
    {
        int na = MROWS * K2DIM;
        conv_f16<<<(na + 255) / 256, 256>>>(gat, af, na);
    }
    gemm_ldsm<<<dim3(DIMC / 128, MROWS / 128), 256, GB_SMEM>>>(
        af, woh, wol, bo, out, MROWS, DIMC, K2DIM);
}

// round 12
// speedup vs baseline: 2.0441x; 1.1211x over previous
#include <cuda_runtime.h>
#include <cuda_bf16.h>
#include <cuda_fp16.h>
#include <math.h>
#include <stdint.h>

// Problem constants
#define DIMC   1152
#define NH     8
#define KVH    2
#define HD     144
#define BSZ    4
#define SEQ    2048
#define MROWS  (BSZ*SEQ)          // 8192
#define KVOUT  (2*KVH*HD)         // 576
#define NQKV   (DIMC + KVOUT)     // 1728 combined projection width
#define K2DIM  (DIMC/2)           // 576
#define KP     72                 // pairs per head row
#define TPH    (SEQ/2)            // seq pairs for V^T

// ---------------- scratch (device globals) ----------------------------------
__device__ float g_qkv [(size_t)MROWS * NQKV];      // fused Q|KV projection out
__device__ float g_attn[(size_t)MROWS * DIMC];

// GEMM operands: A single fp16, weights fp16 hi/lo
__device__ uint32_t g_xf [(size_t)MROWS * K2DIM];   // x fp16
__device__ uint32_t g_wch[(size_t)NQKV  * K2DIM];   // combined Wq|Wkv hi
__device__ uint32_t g_wcl[(size_t)NQKV  * K2DIM];   // combined Wq|Wkv lo
__device__ float    g_bc [NQKV];                    // combined bias
__device__ uint32_t g_woh[(size_t)DIMC  * K2DIM];
__device__ uint32_t g_wol[(size_t)DIMC  * K2DIM];
__device__ uint32_t g_af [(size_t)MROWS * K2DIM];   // attn out fp16

// attention operands
__device__ uint32_t g_qf[(size_t)BSZ*NH *SEQ*KP];   // Q single fp16 pairs
__device__ uint32_t g_kf[(size_t)BSZ*KVH*SEQ*KP];   // K single fp16 pairs
__device__ uint32_t g_vh[(size_t)BSZ*KVH*HD*TPH];   // V^T fp16 hi, pairs along s
__device__ uint32_t g_vl[(size_t)BSZ*KVH*HD*TPH];   // V^T fp16 lo

// ---------------- helpers ----------------------------------------------------
__device__ __forceinline__ uint32_t smem_u32(const void* p) {
    uint32_t a;
    asm("{ .reg .u64 t; cvta.to.shared.u64 t, %1; cvt.u32.u64 %0, t; }"
        : "=r"(a) : "l"(p));
    return a;
}

__device__ __forceinline__ void split2h(float x, float y, uint32_t& hi, uint32_t& lo)
{
    __half2 h = __floats2half2_rn(x, y);
    float2 hf = __half22float2(h);
    __half2 l = __floats2half2_rn(x - hf.x, y - hf.y);
    hi = *reinterpret_cast<uint32_t*>(&h);
    lo = *reinterpret_cast<uint32_t*>(&l);
}

__device__ __forceinline__ void mma16816h(float* c, const uint32_t* a, const uint32_t* b)
{
    asm volatile(
        "mma.sync.aligned.m16n8k16.row.col.f32.f16.f16.f32 "
        "{%0,%1,%2,%3}, {%4,%5,%6,%7}, {%8,%9}, {%0,%1,%2,%3};\n"
        : "+f"(c[0]), "+f"(c[1]), "+f"(c[2]), "+f"(c[3])
        : "r"(a[0]), "r"(a[1]), "r"(a[2]), "r"(a[3]), "r"(b[0]), "r"(b[1]));
}

__device__ __forceinline__ void ldsm4(uint32_t& r0, uint32_t& r1, uint32_t& r2,
                                      uint32_t& r3, uint32_t a)
{
    asm volatile("ldmatrix.sync.aligned.m8n8.x4.shared.b16 {%0,%1,%2,%3}, [%4];"
                 : "=r"(r0), "=r"(r1), "=r"(r2), "=r"(r3) : "r"(a));
}

#define CP_ASYNC16(sa, gp) \
    asm volatile("cp.async.cg.shared.global [%0], [%1], 16;" :: "r"(sa), "l"(gp))
#define CP_COMMIT() asm volatile("cp.async.commit_group;" ::: "memory")
#define CP_WAIT1()  asm volatile("cp.async.wait_group 1;" ::: "memory")
#define CP_WAIT0()  asm volatile("cp.async.wait_group 0;" ::: "memory")

// ---------------- conversion kernels ----------------------------------------
__global__ void conv_f16(const float* __restrict__ src, uint32_t* __restrict__ dst,
                         int n2)
{
    int i = blockIdx.x * blockDim.x + threadIdx.x;
    if (i >= n2) return;
    float2 v = ((const float2*)src)[i];
    __half2 h = __floats2half2_rn(v.x, v.y);
    dst[i] = *reinterpret_cast<uint32_t*>(&h);
}

__global__ void split_f16(const float* __restrict__ src,
                          uint32_t* __restrict__ hi, uint32_t* __restrict__ lo,
                          int n2)
{
    int i = blockIdx.x * blockDim.x + threadIdx.x;
    if (i >= n2) return;
    float2 v = ((const float2*)src)[i];
    split2h(v.x, v.y, hi[i], lo[i]);
}

__global__ void concat_bias(const float* __restrict__ bq, const float* __restrict__ bkv,
                            float* __restrict__ bc)
{
    int i = blockIdx.x * blockDim.x + threadIdx.x;
    if (i < DIMC) bc[i] = bq[i];
    else if (i < NQKV) bc[i] = bkv[i - DIMC];
}

// ---------------- fp16 2-pass GEMM (ldmatrix + cp.async) --------------------
// C[M,N] = A[M,K]@B[N,K]^T + bias;  A single fp16, B fp16 hi/lo.
#define GB_ROWB 80
#define GB_ARR  (128 * GB_ROWB)
#define GB_BUF  (3 * GB_ARR)          // A, Bh, Bl
#define GB_SMEM (2 * GB_BUF)          // 61440 B

__global__ __launch_bounds__(256, 2)
void gemm_ldsm(const uint32_t* __restrict__ Ag,
               const uint32_t* __restrict__ Bhg, const uint32_t* __restrict__ Blg,
               const float* __restrict__ bias, float* __restrict__ C,
               int M, int N, int K2)
{
    extern __shared__ char smem[];
    const uint32_t sbase = smem_u32(smem);
    const int tid = threadIdx.x;
    const int warp = tid >> 5, lane = tid & 31;
    const int wm = (warp & 1) * 64;
    const int wn = (warp >> 1) * 32;
    const int m0 = blockIdx.y * 128;
    const int n0 = blockIdx.x * 128;
    const int nch = K2 / 16;

    const int srow = tid >> 2;
    const int schk = tid & 3;
    const int br0 = (n0 + srow     < N) ? n0 + srow      : N - 1;
    const int br1 = (n0 + srow + 64 < N) ? n0 + srow + 64 : N - 1;

    float acc[4][4][4];
#pragma unroll
    for (int i = 0; i < 4; i++)
#pragma unroll
        for (int j = 0; j < 4; j++)
#pragma unroll
            for (int t = 0; t < 4; t++) acc[i][j][t] = 0.f;

    const int lrow = lane & 15;
    const int lch = lane >> 4;

#define GB_ISSUE(ch) do { \
    const int _buf = (ch) & 1; \
    const uint32_t _sb = sbase + _buf * GB_BUF; \
    const size_t _kc = (size_t)(ch) * 16 + schk * 4; \
    uint32_t _so0 = _sb + srow * GB_ROWB + schk * 16; \
    uint32_t _so1 = _sb + (srow + 64) * GB_ROWB + schk * 16; \
    CP_ASYNC16(_so0,              Ag  + (size_t)(m0 + srow) * K2 + _kc); \
    CP_ASYNC16(_so1,              Ag  + (size_t)(m0 + srow + 64) * K2 + _kc); \
    CP_ASYNC16(_so0 + GB_ARR,     Bhg + (size_t)br0 * K2 + _kc); \
    CP_ASYNC16(_so1 + GB_ARR,     Bhg + (size_t)br1 * K2 + _kc); \
    CP_ASYNC16(_so0 + 2*GB_ARR,   Blg + (size_t)br0 * K2 + _kc); \
    CP_ASYNC16(_so1 + 2*GB_ARR,   Blg + (size_t)br1 * K2 + _kc); \
} while (0)

    GB_ISSUE(0); CP_COMMIT();

    for (int ch = 0; ch < nch; ch++) {
        if (ch + 1 < nch) { GB_ISSUE(ch + 1); CP_COMMIT(); CP_WAIT1(); }
        else              { CP_WAIT0(); }
        __syncthreads();

        const uint32_t sb = sbase + (ch & 1) * GB_BUF;
        const uint32_t aA = sb + (wm + lrow) * GB_ROWB + lch * 16;
        const uint32_t bH = sb + GB_ARR + (wn + lrow) * GB_ROWB + lch * 16;
        const uint32_t bL = bH + GB_ARR;

#pragma unroll
        for (int kk = 0; kk < 2; kk++) {
            uint32_t bh[4][2], bl[4][2];
#pragma unroll
            for (int jj = 0; jj < 2; jj++) {
                uint32_t r0, r1, r2, r3;
                ldsm4(r0, r1, r2, r3, bH + jj * (16 * GB_ROWB) + kk * 32);
                bh[2*jj][0] = r0; bh[2*jj][1] = r2;
                bh[2*jj+1][0] = r1; bh[2*jj+1][1] = r3;
                ldsm4(r0, r1, r2, r3, bL + jj * (16 * GB_ROWB) + kk * 32);
                bl[2*jj][0] = r0; bl[2*jj][1] = r2;
                bl[2*jj+1][0] = r1; bl[2*jj+1][1] = r3;
            }
#pragma unroll
            for (int i = 0; i < 4; i++) {
                uint32_t ah[4];
                ldsm4(ah[0], ah[1], ah[2], ah[3], aA + i * (16 * GB_ROWB) + kk * 32);
#pragma unroll
                for (int j = 0; j < 4; j++) {
                    mma16816h(acc[i][j], ah, bh[j]);
                    mma16816h(acc[i][j], ah, bl[j]);
                }
            }
        }
        __syncthreads();
    }

    const int lr = lane >> 2, lc = lane & 3;
#pragma unroll
    for (int i = 0; i < 4; i++) {
        int r0 = m0 + wm + i * 16 + lr;
#pragma unroll
        for (int j = 0; j < 4; j++) {
            int c0 = n0 + wn + j * 8 + lc * 2;
            if (c0 < N) {
                float2 bb = *(const float2*)&bias[c0];
                *(float2*)&C[(size_t)r0 * N + c0] =
                    make_float2(acc[i][j][0] + bb.x, acc[i][j][1] + bb.y);
                *(float2*)&C[(size_t)(r0 + 8) * N + c0] =
                    make_float2(acc[i][j][2] + bb.x, acc[i][j][3] + bb.y);
            }
        }
    }
#undef GB_ISSUE
}

// ---------------- RoPE -> fp16 (reads fused g_qkv, stride NQKV) -------------
__global__ void rope_q_f16(const float* __restrict__ QKV,
                           const float* __restrict__ fc, const float* __restrict__ fs,
                           uint32_t* __restrict__ qf)
{
    int idx = blockIdx.x * blockDim.x + threadIdx.x;
    const int total = BSZ * NH * SEQ * KP;
    if (idx >= total) return;
    int i = idx % KP;
    int s = (idx / KP) % SEQ;
    int h = (idx / (KP * SEQ)) % NH;
    int b = idx / (KP * SEQ * NH);

    size_t base = (size_t)(b * SEQ + s) * NQKV + h * HD;
    float q0 = QKV[base + 2 * i];
    float q1 = QKV[base + 2 * i + 1];
    float c = fc[s * KP + i];
    float sn = fs[s * KP + i];
    const float scale = 0.083333333333333329f;
    __half2 p = __floats2half2_rn((q0 * c - q1 * sn) * scale,
                                  (q0 * sn + q1 * c) * scale);
    qf[idx] = *reinterpret_cast<uint32_t*>(&p);
}

__global__ void rope_k_f16(const float* __restrict__ QKV,
                           const float* __restrict__ fc, const float* __restrict__ fs,
                           uint32_t* __restrict__ kf)
{
    int idx = blockIdx.x * blockDim.x + threadIdx.x;
    const int total = BSZ * KVH * SEQ * KP;
    if (idx >= total) return;
    int i = idx % KP;
    int s = (idx / KP) % SEQ;
    int kvh = (idx / (KP * SEQ)) % KVH;
    int b = idx / (KP * SEQ * KVH);

    size_t base = (size_t)(b * SEQ + s) * NQKV + DIMC + kvh * HD;
    float k0 = QKV[base + 2 * i];
    float k1 = QKV[base + 2 * i + 1];
    float c = fc[s * KP + i];
    float sn = fs[s * KP + i];
    __half2 p = __floats2half2_rn(k0 * c - k1 * sn, k0 * sn + k1 * c);
    kf[idx] = *reinterpret_cast<uint32_t*>(&p);
}

// V transpose + fp16 split: out [b*KVH+kvh][d][sp], pairs along s.
__global__ void v_trans_split(const float* __restrict__ QKV,
                              uint32_t* __restrict__ vh, uint32_t* __restrict__ vl)
{
    __shared__ float tile[64][HD + 1];
    const int st = blockIdx.x;
    const int bk = blockIdx.y;
    const int b = bk / KVH, kvh = bk % KVH;
    const int tid = threadIdx.x;

    const float* src = QKV + (size_t)(b * SEQ + st * 64) * NQKV
                           + DIMC + KVH * HD + kvh * HD;
    for (int e = tid; e < 64 * HD; e += 256) {
        int r = e / HD, c = e % HD;
        tile[r][c] = src[(size_t)r * NQKV + c];
    }
    __syncthreads();

    uint32_t* oh = vh + ((size_t)bk * HD) * TPH + st * 32;
    uint32_t* ol = vl + ((size_t)bk * HD) * TPH + st * 32;
    for (int e = tid; e < HD * 32; e += 256) {
        int d = e / 32, sp = e % 32;
        uint32_t h, l;
        split2h(tile[2 * sp][d], tile[2 * sp + 1][d], h, l);
        oh[(size_t)d * TPH + sp] = h;
        ol[(size_t)d * TPH + sp] = l;
    }
}

// ---------------- Flash attention -------------------------------------------
// QK: fp16 1-pass (Q and K single fp16).
// PV: fp16 2-pass (P single fp16, V fp16 hi/lo).
#define QS 76
#define KS 76
#define VS 36

#define FLASH_SMEM ((128*QS + 64*KS + 2*HD*VS) * (int)sizeof(uint32_t))

__global__ __launch_bounds__(256, 1)
void flash_mma(const uint32_t* __restrict__ qf, const uint32_t* __restrict__ kf,
               const uint32_t* __restrict__ vh, const uint32_t* __restrict__ vl,
               float* __restrict__ out)
{
    extern __shared__ uint32_t fsm[];
    uint32_t* sQ  = fsm;
    uint32_t* sK  = sQ + 128 * QS;
    uint32_t* sVh = sK + 64 * KS;
    uint32_t* sVl = sVh + HD * VS;

    const int qt = (gridDim.x - 1) - blockIdx.x;
    const int bh = blockIdx.y;
    const int b = bh >> 3;
    const int h = bh & 7;
    const int kvh = h >> 2;
    const int bk = b * KVH + kvh;

    const int tid = threadIdx.x;
    const int warp = tid >> 5, lane = tid & 31;
    const int lr = lane >> 2, lc = lane & 3;
    const int wm = warp * 16;

    {
        const uint32_t* gq = qf + ((size_t)bh * SEQ + qt * 128) * KP;
        for (int e = tid; e < 128 * 18; e += 256) {
            int r = e / 18, c = (e % 18) * 4;
            *(uint4*)&sQ[r * QS + c] = *(const uint4*)&gq[(size_t)r * KP + c];
        }
    }

    float o[18][4];
#pragma unroll
    for (int n = 0; n < 18; n++)
#pragma unroll
        for (int t = 0; t < 4; t++) o[n][t] = 0.f;
    float m0 = -1e30f, m1 = -1e30f, l0 = 0.f, l1 = 0.f;

    const int ktmax = 2 * qt + 1;
    const int qrow0 = qt * 128 + wm;

    for (int kt = 0; kt <= ktmax; kt++) {
        __syncthreads();
        {
            const uint32_t* gk = kf + ((size_t)bk * SEQ + kt * 64) * KP;
            for (int e = tid; e < 64 * 18; e += 256) {
                int r = e / 18, c = (e % 18) * 4;
                *(uint4*)&sK[r * KS + c] = *(const uint4*)&gk[(size_t)r * KP + c];
            }
            const uint32_t* gvh = vh + (size_t)bk * HD * TPH + kt * 32;
            const uint32_t* gvl = vl + (size_t)bk * HD * TPH + kt * 32;
            for (int e = tid; e < HD * 8; e += 256) {
                int r = e / 8, c = (e % 8) * 4;
                *(uint4*)&sVh[r * VS + c] = *(const uint4*)&gvh[(size_t)r * TPH + c];
                *(uint4*)&sVl[r * VS + c] = *(const uint4*)&gvl[(size_t)r * TPH + c];
            }
        }
        __syncthreads();

        float sfr[8][4];
#pragma unroll
        for (int j = 0; j < 8; j++)
#pragma unroll
            for (int t = 0; t < 4; t++) sfr[j][t] = 0.f;

#pragma unroll
        for (int kc = 0; kc < 9; kc++) {
            uint32_t ah[4];
            int ra = (wm + lr) * QS + kc * 8 + lc;
            int rb = (wm + lr + 8) * QS + kc * 8 + lc;
            ah[0] = sQ[ra];     ah[1] = sQ[rb];
            ah[2] = sQ[ra + 4]; ah[3] = sQ[rb + 4];
#pragma unroll
            for (int j = 0; j < 8; j++) {
                int rk = (j * 8 + lr) * KS + kc * 8 + lc;
                uint32_t bh2[2] = { sK[rk], sK[rk + 4] };
                mma16816h(sfr[j], ah, bh2);
            }
        }

        if (kt * 64 + 63 > qrow0) {
            int key0 = kt * 64;
#pragma unroll
            for (int j = 0; j < 8; j++) {
                int kc0 = key0 + j * 8 + 2 * lc;
                if (kc0     > qrow0 + lr)     sfr[j][0] = -1e9f;
                if (kc0 + 1 > qrow0 + lr)     sfr[j][1] = -1e9f;
                if (kc0     > qrow0 + lr + 8) sfr[j][2] = -1e9f;
                if (kc0 + 1 > qrow0 + lr + 8) sfr[j][3] = -1e9f;
            }
        }

        float mx0 = -1e30f, mx1 = -1e30f;
#pragma unroll
        for (int j = 0; j < 8; j++) {
            mx0 = fmaxf(mx0, fmaxf(sfr[j][0], sfr[j][1]));
            mx1 = fmaxf(mx1, fmaxf(sfr[j][2], sfr[j][3]));
        }
#pragma unroll
        for (int off = 1; off < 4; off <<= 1) {
            mx0 = fmaxf(mx0, __shfl_xor_sync(0xffffffffu, mx0, off));
            mx1 = fmaxf(mx1, __shfl_xor_sync(0xffffffffu, mx1, off));
        }
        float mn0 = fmaxf(m0, mx0), mn1 = fmaxf(m1, mx1);
        float c0 = __expf(m0 - mn0), c1 = __expf(m1 - mn1);
        m0 = mn0; m1 = mn1;

        float s0 = 0.f, s1 = 0.f;
#pragma unroll
        for (int j = 0; j < 8; j++) {
            sfr[j][0] = __expf(sfr[j][0] - m0);
            sfr[j][1] = __expf(sfr[j][1] - m0);
            sfr[j][2] = __expf(sfr[j][2] - m1);
            sfr[j][3] = __expf(sfr[j][3] - m1);
            s0 += sfr[j][0] + sfr[j][1];
            s1 += sfr[j][2] + sfr[j][3];
        }
#pragma unroll
        for (int off = 1; off < 4; off <<= 1) {
            s0 += __shfl_xor_sync(0xffffffffu, s0, off);
            s1 += __shfl_xor_sync(0xffffffffu, s1, off);
        }
        l0 = l0 * c0 + s0;
        l1 = l1 * c1 + s1;

#pragma unroll
        for (int n = 0; n < 18; n++) {
            o[n][0] *= c0; o[n][1] *= c0;
            o[n][2] *= c1; o[n][3] *= c1;
        }

        // P -> single fp16 fragments
        uint32_t ph01[8], ph23[8];
#pragma unroll
        for (int j = 0; j < 8; j++) {
            __half2 p0 = __floats2half2_rn(sfr[j][0], sfr[j][1]);
            __half2 p1 = __floats2half2_rn(sfr[j][2], sfr[j][3]);
            ph01[j] = *reinterpret_cast<uint32_t*>(&p0);
            ph23[j] = *reinterpret_cast<uint32_t*>(&p1);
        }

        // O += P (V_hi + V_lo) -- fp16 2-pass
#pragma unroll
        for (int kc = 0; kc < 4; kc++) {
            uint32_t pa[4] = { ph01[2*kc], ph23[2*kc], ph01[2*kc+1], ph23[2*kc+1] };
#pragma unroll
            for (int n = 0; n < 18; n++) {
                int rv = (n * 8 + lr) * VS + kc * 8 + lc;
                uint32_t bh2[2] = { sVh[rv], sVh[rv + 4] };
                uint32_t bl2[2] = { sVl[rv], sVl[rv + 4] };
                mma16816h(o[n], pa, bh2);
                mma16816h(o[n], pa, bl2);
            }
        }
    }

    float inv0 = 1.f / l0, inv1 = 1.f / l1;
    int r0 = qt * 128 + wm + lr;
    float* orow0 = out + ((size_t)b * SEQ + r0)     * DIMC + h * HD;
    float* orow1 = out + ((size_t)b * SEQ + r0 + 8) * DIMC + h * HD;
#pragma unroll
    for (int n = 0; n < 18; n++) {
        int col = n * 8 + 2 * lc;
        *(float2*)&orow0[col] = make_float2(o[n][0] * inv0, o[n][1] * inv0);
        *(float2*)&orow1[col] = make_float2(o[n][2] * inv1, o[n][3] * inv1);
    }
}

// ---------------- launcher --------------------------------------------------
extern "C" void kernel_launch(void* const* d_in, const int* in_sizes, int n_in,
                              void* d_out, int out_size)
{
    const float* x   = (const float*)d_in[0];
    const float* wq  = (const float*)d_in[1];
    const float* bq  = (const float*)d_in[2];
    const float* wkv = (const float*)d_in[3];
    const float* bkv = (const float*)d_in[4];
    const float* wo  = (const float*)d_in[5];
    const float* bo  = (const float*)d_in[6];
    const float* fc  = (const float*)d_in[7];
    const float* fs  = (const float*)d_in[8];
    float* out = (float*)d_out;

    float *gqkv, *gat, *bc;
    uint32_t *xf, *wch, *wcl, *woh, *wol, *af;
    uint32_t *qf, *kf, *vh, *vl;
    cudaGetSymbolAddress((void**)&gqkv, g_qkv);
    cudaGetSymbolAddress((void**)&gat,  g_attn);
    cudaGetSymbolAddress((void**)&bc,   g_bc);
    cudaGetSymbolAddress((void**)&xf,   g_xf);
    cudaGetSymbolAddress((void**)&wch,  g_wch);
    cudaGetSymbolAddress((void**)&wcl,  g_wcl);
    cudaGetSymbolAddress((void**)&woh,  g_woh);
    cudaGetSymbolAddress((void**)&wol,  g_wol);
    cudaGetSymbolAddress((void**)&af,   g_af);
    cudaGetSymbolAddress((void**)&qf,   g_qf);
    cudaGetSymbolAddress((void**)&kf,   g_kf);
    cudaGetSymbolAddress((void**)&vh,   g_vh);
    cudaGetSymbolAddress((void**)&vl,   g_vl);

    cudaFuncSetAttribute(flash_mma, cudaFuncAttributeMaxDynamicSharedMemorySize,
                         FLASH_SMEM);
    cudaFuncSetAttribute(gemm_ldsm, cudaFuncAttributeMaxDynamicSharedMemorySize,
                         GB_SMEM);

    // prepare GEMM operands
    {
        int nx = MROWS * K2DIM;
        conv_f16<<<(nx + 255) / 256, 256>>>(x, xf, nx);
        int nq = DIMC * K2DIM;
        split_f16<<<(nq + 255) / 256, 256>>>(wq, wch, wcl, nq);
        int nk = KVOUT * K2DIM;
        split_f16<<<(nk + 255) / 256, 256>>>(wkv, wch + (size_t)DIMC * K2DIM,
                                             wcl + (size_t)DIMC * K2DIM, nk);
        split_f16<<<(nq + 255) / 256, 256>>>(wo, woh, wol, nq);
        concat_bias<<<(NQKV + 255) / 256, 256>>>(bq, bkv, bc);
    }

    // fused Q|KV projection (N = 1728)
    gemm_ldsm<<<dim3((NQKV + 127) / 128, MROWS / 128), 256, GB_SMEM>>>(
        xf, wch, wcl, bc, gqkv, MROWS, NQKV, K2DIM);

    // RoPE + fp16 conversion + V transpose (read fused buffer)
    {
        int tq = BSZ * NH * SEQ * KP;
        rope_q_f16<<<(tq + 255) / 256, 256>>>(gqkv, fc, fs, qf);
        int tk = BSZ * KVH * SEQ * KP;
        rope_k_f16<<<(tk + 255) / 256, 256>>>(gqkv, fc, fs, kf);
        v_trans_split<<<dim3(SEQ / 64, BSZ * KVH), 256>>>(gqkv, vh, vl);
    }

    // attention (QK 1-pass fp16, PV 2-pass fp16)
    flash_mma<<<dim3(SEQ / 128, BSZ * NH), 256, FLASH_SMEM>>>(
        qf, kf, vh, vl, gat);

    // output projection
    {
        int na = MROWS * K2DIM;
        conv_f16<<<(na + 255) / 256, 256>>>(gat, af, na);
    }
    gemm_ldsm<<<dim3(DIMC / 128, MROWS / 128), 256, GB_SMEM>>>(
        af, woh, wol, bo, out, MROWS, DIMC, K2DIM);
}

// round 13
// speedup vs baseline: 2.1876x; 1.0702x over previous
#include <cuda_runtime.h>
#include <cuda_bf16.h>
#include <cuda_fp16.h>
#include <math.h>
#include <stdint.h>

// Problem constants
#define DIMC   1152
#define NH     8
#define KVH    2
#define HD     144
#define BSZ    4
#define SEQ    2048
#define MROWS  (BSZ*SEQ)          // 8192
#define KVOUT  (2*KVH*HD)         // 576
#define NQKV   (DIMC + KVOUT)     // 1728 combined projection width
#define K2DIM  (DIMC/2)           // 576
#define KP     72                 // pairs per head row
#define TPH    (SEQ/2)            // seq pairs for V^T

// ---------------- scratch (device globals) ----------------------------------
__device__ float g_qkv [(size_t)MROWS * NQKV];      // fused Q|KV projection out
__device__ float g_attn[(size_t)MROWS * DIMC];

// GEMM operands: A single fp16, weights fp16 hi/lo
__device__ uint32_t g_xf [(size_t)MROWS * K2DIM];   // x fp16
__device__ uint32_t g_wch[(size_t)NQKV  * K2DIM];   // combined Wq|Wkv hi
__device__ uint32_t g_wcl[(size_t)NQKV  * K2DIM];   // combined Wq|Wkv lo
__device__ float    g_bc [NQKV];                    // combined bias
__device__ uint32_t g_woh[(size_t)DIMC  * K2DIM];
__device__ uint32_t g_wol[(size_t)DIMC  * K2DIM];
__device__ uint32_t g_af [(size_t)MROWS * K2DIM];   // attn out fp16

// attention operands
__device__ uint32_t g_qf[(size_t)BSZ*NH *SEQ*KP];   // Q single fp16 pairs
__device__ uint32_t g_kf[(size_t)BSZ*KVH*SEQ*KP];   // K single fp16 pairs
__device__ uint32_t g_vf[(size_t)BSZ*KVH*HD*TPH];   // V^T single fp16, pairs along s

// ---------------- helpers ----------------------------------------------------
__device__ __forceinline__ uint32_t smem_u32(const void* p) {
    uint32_t a;
    asm("{ .reg .u64 t; cvta.to.shared.u64 t, %1; cvt.u32.u64 %0, t; }"
        : "=r"(a) : "l"(p));
    return a;
}

__device__ __forceinline__ void split2h(float x, float y, uint32_t& hi, uint32_t& lo)
{
    __half2 h = __floats2half2_rn(x, y);
    float2 hf = __half22float2(h);
    __half2 l = __floats2half2_rn(x - hf.x, y - hf.y);
    hi = *reinterpret_cast<uint32_t*>(&h);
    lo = *reinterpret_cast<uint32_t*>(&l);
}

__device__ __forceinline__ void mma16816h(float* c, const uint32_t* a, const uint32_t* b)
{
    asm volatile(
        "mma.sync.aligned.m16n8k16.row.col.f32.f16.f16.f32 "
        "{%0,%1,%2,%3}, {%4,%5,%6,%7}, {%8,%9}, {%0,%1,%2,%3};\n"
        : "+f"(c[0]), "+f"(c[1]), "+f"(c[2]), "+f"(c[3])
        : "r"(a[0]), "r"(a[1]), "r"(a[2]), "r"(a[3]), "r"(b[0]), "r"(b[1]));
}

__device__ __forceinline__ void ldsm4(uint32_t& r0, uint32_t& r1, uint32_t& r2,
                                      uint32_t& r3, uint32_t a)
{
    asm volatile("ldmatrix.sync.aligned.m8n8.x4.shared.b16 {%0,%1,%2,%3}, [%4];"
                 : "=r"(r0), "=r"(r1), "=r"(r2), "=r"(r3) : "r"(a));
}

#define CP_ASYNC16(sa, gp) \
    asm volatile("cp.async.cg.shared.global [%0], [%1], 16;" :: "r"(sa), "l"(gp))
#define CP_COMMIT() asm volatile("cp.async.commit_group;" ::: "memory")
#define CP_WAIT1()  asm volatile("cp.async.wait_group 1;" ::: "memory")
#define CP_WAIT0()  asm volatile("cp.async.wait_group 0;" ::: "memory")

// ---------------- conversion kernels ----------------------------------------
__global__ void conv_f16(const float* __restrict__ src, uint32_t* __restrict__ dst,
                         int n2)
{
    int i = blockIdx.x * blockDim.x + threadIdx.x;
    if (i >= n2) return;
    float2 v = ((const float2*)src)[i];
    __half2 h = __floats2half2_rn(v.x, v.y);
    dst[i] = *reinterpret_cast<uint32_t*>(&h);
}

__global__ void split_f16(const float* __restrict__ src,
                          uint32_t* __restrict__ hi, uint32_t* __restrict__ lo,
                          int n2)
{
    int i = blockIdx.x * blockDim.x + threadIdx.x;
    if (i >= n2) return;
    float2 v = ((const float2*)src)[i];
    split2h(v.x, v.y, hi[i], lo[i]);
}

__global__ void concat_bias(const float* __restrict__ bq, const float* __restrict__ bkv,
                            float* __restrict__ bc)
{
    int i = blockIdx.x * blockDim.x + threadIdx.x;
    if (i < DIMC) bc[i] = bq[i];
    else if (i < NQKV) bc[i] = bkv[i - DIMC];
}

// ---------------- fp16 2-pass GEMM (ldmatrix + cp.async) --------------------
// C[M,N] = A[M,K]@B[N,K]^T + bias;  A single fp16, B fp16 hi/lo.
#define GB_ROWB 80
#define GB_ARR  (128 * GB_ROWB)
#define GB_BUF  (3 * GB_ARR)          // A, Bh, Bl
#define GB_SMEM (2 * GB_BUF)          // 61440 B

__global__ __launch_bounds__(256, 2)
void gemm_ldsm(const uint32_t* __restrict__ Ag,
               const uint32_t* __restrict__ Bhg, const uint32_t* __restrict__ Blg,
               const float* __restrict__ bias, float* __restrict__ C,
               int M, int N, int K2)
{
    extern __shared__ char smem[];
    const uint32_t sbase = smem_u32(smem);
    const int tid = threadIdx.x;
    const int warp = tid >> 5, lane = tid & 31;
    const int wm = (warp & 1) * 64;
    const int wn = (warp >> 1) * 32;
    const int m0 = blockIdx.y * 128;
    const int n0 = blockIdx.x * 128;
    const int nch = K2 / 16;

    const int srow = tid >> 2;
    const int schk = tid & 3;
    const int br0 = (n0 + srow     < N) ? n0 + srow      : N - 1;
    const int br1 = (n0 + srow + 64 < N) ? n0 + srow + 64 : N - 1;

    float acc[4][4][4];
#pragma unroll
    for (int i = 0; i < 4; i++)
#pragma unroll
        for (int j = 0; j < 4; j++)
#pragma unroll
            for (int t = 0; t < 4; t++) acc[i][j][t] = 0.f;

    const int lrow = lane & 15;
    const int lch = lane >> 4;

#define GB_ISSUE(ch) do { \
    const int _buf = (ch) & 1; \
    const uint32_t _sb = sbase + _buf * GB_BUF; \
    const size_t _kc = (size_t)(ch) * 16 + schk * 4; \
    uint32_t _so0 = _sb + srow * GB_ROWB + schk * 16; \
    uint32_t _so1 = _sb + (srow + 64) * GB_ROWB + schk * 16; \
    CP_ASYNC16(_so0,              Ag  + (size_t)(m0 + srow) * K2 + _kc); \
    CP_ASYNC16(_so1,              Ag  + (size_t)(m0 + srow + 64) * K2 + _kc); \
    CP_ASYNC16(_so0 + GB_ARR,     Bhg + (size_t)br0 * K2 + _kc); \
    CP_ASYNC16(_so1 + GB_ARR,     Bhg + (size_t)br1 * K2 + _kc); \
    CP_ASYNC16(_so0 + 2*GB_ARR,   Blg + (size_t)br0 * K2 + _kc); \
    CP_ASYNC16(_so1 + 2*GB_ARR,   Blg + (size_t)br1 * K2 + _kc); \
} while (0)

    GB_ISSUE(0); CP_COMMIT();

    for (int ch = 0; ch < nch; ch++) {
        if (ch + 1 < nch) { GB_ISSUE(ch + 1); CP_COMMIT(); CP_WAIT1(); }
        else              { CP_WAIT0(); }
        __syncthreads();

        const uint32_t sb = sbase + (ch & 1) * GB_BUF;
        const uint32_t aA = sb + (wm + lrow) * GB_ROWB + lch * 16;
        const uint32_t bH = sb + GB_ARR + (wn + lrow) * GB_ROWB + lch * 16;
        const uint32_t bL = bH + GB_ARR;

#pragma unroll
        for (int kk = 0; kk < 2; kk++) {
            uint32_t bh[4][2], bl[4][2];
#pragma unroll
            for (int jj = 0; jj < 2; jj++) {
                uint32_t r0, r1, r2, r3;
                ldsm4(r0, r1, r2, r3, bH + jj * (16 * GB_ROWB) + kk * 32);
                bh[2*jj][0] = r0; bh[2*jj][1] = r2;
                bh[2*jj+1][0] = r1; bh[2*jj+1][1] = r3;
                ldsm4(r0, r1, r2, r3, bL + jj * (16 * GB_ROWB) + kk * 32);
                bl[2*jj][0] = r0; bl[2*jj][1] = r2;
                bl[2*jj+1][0] = r1; bl[2*jj+1][1] = r3;
            }
#pragma unroll
            for (int i = 0; i < 4; i++) {
                uint32_t ah[4];
                ldsm4(ah[0], ah[1], ah[2], ah[3], aA + i * (16 * GB_ROWB) + kk * 32);
#pragma unroll
                for (int j = 0; j < 4; j++) {
                    mma16816h(acc[i][j], ah, bh[j]);
                    mma16816h(acc[i][j], ah, bl[j]);
                }
            }
        }
        __syncthreads();
    }

    const int lr = lane >> 2, lc = lane & 3;
#pragma unroll
    for (int i = 0; i < 4; i++) {
        int r0 = m0 + wm + i * 16 + lr;
#pragma unroll
        for (int j = 0; j < 4; j++) {
            int c0 = n0 + wn + j * 8 + lc * 2;
            if (c0 < N) {
                float2 bb = *(const float2*)&bias[c0];
                *(float2*)&C[(size_t)r0 * N + c0] =
                    make_float2(acc[i][j][0] + bb.x, acc[i][j][1] + bb.y);
                *(float2*)&C[(size_t)(r0 + 8) * N + c0] =
                    make_float2(acc[i][j][2] + bb.x, acc[i][j][3] + bb.y);
            }
        }
    }
#undef GB_ISSUE
}

// ---------------- RoPE -> fp16 (reads fused g_qkv, stride NQKV) -------------
__global__ void rope_q_f16(const float* __restrict__ QKV,
                           const float* __restrict__ fc, const float* __restrict__ fs,
                           uint32_t* __restrict__ qf)
{
    int idx = blockIdx.x * blockDim.x + threadIdx.x;
    const int total = BSZ * NH * SEQ * KP;
    if (idx >= total) return;
    int i = idx % KP;
    int s = (idx / KP) % SEQ;
    int h = (idx / (KP * SEQ)) % NH;
    int b = idx / (KP * SEQ * NH);

    size_t base = (size_t)(b * SEQ + s) * NQKV + h * HD;
    float q0 = QKV[base + 2 * i];
    float q1 = QKV[base + 2 * i + 1];
    float c = fc[s * KP + i];
    float sn = fs[s * KP + i];
    const float scale = 0.083333333333333329f;
    __half2 p = __floats2half2_rn((q0 * c - q1 * sn) * scale,
                                  (q0 * sn + q1 * c) * scale);
    qf[idx] = *reinterpret_cast<uint32_t*>(&p);
}

__global__ void rope_k_f16(const float* __restrict__ QKV,
                           const float* __restrict__ fc, const float* __restrict__ fs,
                           uint32_t* __restrict__ kf)
{
    int idx = blockIdx.x * blockDim.x + threadIdx.x;
    const int total = BSZ * KVH * SEQ * KP;
    if (idx >= total) return;
    int i = idx % KP;
    int s = (idx / KP) % SEQ;
    int kvh = (idx / (KP * SEQ)) % KVH;
    int b = idx / (KP * SEQ * KVH);

    size_t base = (size_t)(b * SEQ + s) * NQKV + DIMC + kvh * HD;
    float k0 = QKV[base + 2 * i];
    float k1 = QKV[base + 2 * i + 1];
    float c = fc[s * KP + i];
    float sn = fs[s * KP + i];
    __half2 p = __floats2half2_rn(k0 * c - k1 * sn, k0 * sn + k1 * c);
    kf[idx] = *reinterpret_cast<uint32_t*>(&p);
}

// V transpose + single fp16: out [b*KVH+kvh][d][sp], pairs along s.
__global__ void v_trans_f16(const float* __restrict__ QKV,
                            uint32_t* __restrict__ vf)
{
    __shared__ float tile[64][HD + 1];
    const int st = blockIdx.x;
    const int bk = blockIdx.y;
    const int b = bk / KVH, kvh = bk % KVH;
    const int tid = threadIdx.x;

    const float* src = QKV + (size_t)(b * SEQ + st * 64) * NQKV
                           + DIMC + KVH * HD + kvh * HD;
    for (int e = tid; e < 64 * HD; e += 256) {
        int r = e / HD, c = e % HD;
        tile[r][c] = src[(size_t)r * NQKV + c];
    }
    __syncthreads();

    uint32_t* ov = vf + ((size_t)bk * HD) * TPH + st * 32;
    for (int e = tid; e < HD * 32; e += 256) {
        int d = e / 32, sp = e % 32;
        __half2 p = __floats2half2_rn(tile[2 * sp][d], tile[2 * sp + 1][d]);
        ov[(size_t)d * TPH + sp] = *reinterpret_cast<uint32_t*>(&p);
    }
}

// ---------------- Flash attention -------------------------------------------
// QK: fp16 1-pass.  PV: fp16 1-pass.
#define QS 76
#define KS 76
#define VS 36

#define FLASH_SMEM ((128*QS + 64*KS + HD*VS) * (int)sizeof(uint32_t))

__global__ __launch_bounds__(256, 1)
void flash_mma(const uint32_t* __restrict__ qf, const uint32_t* __restrict__ kf,
               const uint32_t* __restrict__ vf,
               float* __restrict__ out)
{
    extern __shared__ uint32_t fsm[];
    uint32_t* sQ  = fsm;
    uint32_t* sK  = sQ + 128 * QS;
    uint32_t* sV  = sK + 64 * KS;

    const int qt = (gridDim.x - 1) - blockIdx.x;
    const int bh = blockIdx.y;
    const int b = bh >> 3;
    const int h = bh & 7;
    const int kvh = h >> 2;
    const int bk = b * KVH + kvh;

    const int tid = threadIdx.x;
    const int warp = tid >> 5, lane = tid & 31;
    const int lr = lane >> 2, lc = lane & 3;
    const int wm = warp * 16;

    {
        const uint32_t* gq = qf + ((size_t)bh * SEQ + qt * 128) * KP;
        for (int e = tid; e < 128 * 18; e += 256) {
            int r = e / 18, c = (e % 18) * 4;
            *(uint4*)&sQ[r * QS + c] = *(const uint4*)&gq[(size_t)r * KP + c];
        }
    }

    float o[18][4];
#pragma unroll
    for (int n = 0; n < 18; n++)
#pragma unroll
        for (int t = 0; t < 4; t++) o[n][t] = 0.f;
    float m0 = -1e30f, m1 = -1e30f, l0 = 0.f, l1 = 0.f;

    const int ktmax = 2 * qt + 1;
    const int qrow0 = qt * 128 + wm;

    for (int kt = 0; kt <= ktmax; kt++) {
        __syncthreads();
        {
            const uint32_t* gk = kf + ((size_t)bk * SEQ + kt * 64) * KP;
            for (int e = tid; e < 64 * 18; e += 256) {
                int r = e / 18, c = (e % 18) * 4;
                *(uint4*)&sK[r * KS + c] = *(const uint4*)&gk[(size_t)r * KP + c];
            }
            const uint32_t* gv = vf + (size_t)bk * HD * TPH + kt * 32;
            for (int e = tid; e < HD * 8; e += 256) {
                int r = e / 8, c = (e % 8) * 4;
                *(uint4*)&sV[r * VS + c] = *(const uint4*)&gv[(size_t)r * TPH + c];
            }
        }
        __syncthreads();

        float sfr[8][4];
#pragma unroll
        for (int j = 0; j < 8; j++)
#pragma unroll
            for (int t = 0; t < 4; t++) sfr[j][t] = 0.f;

#pragma unroll
        for (int kc = 0; kc < 9; kc++) {
            uint32_t ah[4];
            int ra = (wm + lr) * QS + kc * 8 + lc;
            int rb = (wm + lr + 8) * QS + kc * 8 + lc;
            ah[0] = sQ[ra];     ah[1] = sQ[rb];
            ah[2] = sQ[ra + 4]; ah[3] = sQ[rb + 4];
#pragma unroll
            for (int j = 0; j < 8; j++) {
                int rk = (j * 8 + lr) * KS + kc * 8 + lc;
                uint32_t bh2[2] = { sK[rk], sK[rk + 4] };
                mma16816h(sfr[j], ah, bh2);
            }
        }

        if (kt * 64 + 63 > qrow0) {
            int key0 = kt * 64;
#pragma unroll
            for (int j = 0; j < 8; j++) {
                int kc0 = key0 + j * 8 + 2 * lc;
                if (kc0     > qrow0 + lr)     sfr[j][0] = -1e9f;
                if (kc0 + 1 > qrow0 + lr)     sfr[j][1] = -1e9f;
                if (kc0     > qrow0 + lr + 8) sfr[j][2] = -1e9f;
                if (kc0 + 1 > qrow0 + lr + 8) sfr[j][3] = -1e9f;
            }
        }

        float mx0 = -1e30f, mx1 = -1e30f;
#pragma unroll
        for (int j = 0; j < 8; j++) {
            mx0 = fmaxf(mx0, fmaxf(sfr[j][0], sfr[j][1]));
            mx1 = fmaxf(mx1, fmaxf(sfr[j][2], sfr[j][3]));
        }
#pragma unroll
        for (int off = 1; off < 4; off <<= 1) {
            mx0 = fmaxf(mx0, __shfl_xor_sync(0xffffffffu, mx0, off));
            mx1 = fmaxf(mx1, __shfl_xor_sync(0xffffffffu, mx1, off));
        }
        float mn0 = fmaxf(m0, mx0), mn1 = fmaxf(m1, mx1);
        float c0 = __expf(m0 - mn0), c1 = __expf(m1 - mn1);
        m0 = mn0; m1 = mn1;

        float s0 = 0.f, s1 = 0.f;
#pragma unroll
        for (int j = 0; j < 8; j++) {
            sfr[j][0] = __expf(sfr[j][0] - m0);
            sfr[j][1] = __expf(sfr[j][1] - m0);
            sfr[j][2] = __expf(sfr[j][2] - m1);
            sfr[j][3] = __expf(sfr[j][3] - m1);
            s0 += sfr[j][0] + sfr[j][1];
            s1 += sfr[j][2] + sfr[j][3];
        }
#pragma unroll
        for (int off = 1; off < 4; off <<= 1) {
            s0 += __shfl_xor_sync(0xffffffffu, s0, off);
            s1 += __shfl_xor_sync(0xffffffffu, s1, off);
        }
        l0 = l0 * c0 + s0;
        l1 = l1 * c1 + s1;

#pragma unroll
        for (int n = 0; n < 18; n++) {
            o[n][0] *= c0; o[n][1] *= c0;
            o[n][2] *= c1; o[n][3] *= c1;
        }

        // P -> single fp16 fragments
        uint32_t ph01[8], ph23[8];
#pragma unroll
        for (int j = 0; j < 8; j++) {
            __half2 p0 = __floats2half2_rn(sfr[j][0], sfr[j][1]);
            __half2 p1 = __floats2half2_rn(sfr[j][2], sfr[j][3]);
            ph01[j] = *reinterpret_cast<uint32_t*>(&p0);
            ph23[j] = *reinterpret_cast<uint32_t*>(&p1);
        }

        // O += P V  -- fp16 1-pass
#pragma unroll
        for (int kc = 0; kc < 4; kc++) {
            uint32_t pa[4] = { ph01[2*kc], ph23[2*kc], ph01[2*kc+1], ph23[2*kc+1] };
#pragma unroll
            for (int n = 0; n < 18; n++) {
                int rv = (n * 8 + lr) * VS + kc * 8 + lc;
                uint32_t bv[2] = { sV[rv], sV[rv + 4] };
                mma16816h(o[n], pa, bv);
            }
        }
    }

    float inv0 = 1.f / l0, inv1 = 1.f / l1;
    int r0 = qt * 128 + wm + lr;
    float* orow0 = out + ((size_t)b * SEQ + r0)     * DIMC + h * HD;
    float* orow1 = out + ((size_t)b * SEQ + r0 + 8) * DIMC + h * HD;
#pragma unroll
    for (int n = 0; n < 18; n++) {
        int col = n * 8 + 2 * lc;
        *(float2*)&orow0[col] = make_float2(o[n][0] * inv0, o[n][1] * inv0);
        *(float2*)&orow1[col] = make_float2(o[n][2] * inv1, o[n][3] * inv1);
    }
}

// ---------------- launcher --------------------------------------------------
extern "C" void kernel_launch(void* const* d_in, const int* in_sizes, int n_in,
                              void* d_out, int out_size)
{
    const float* x   = (const float*)d_in[0];
    const float* wq  = (const float*)d_in[1];
    const float* bq  = (const float*)d_in[2];
    const float* wkv = (const float*)d_in[3];
    const float* bkv = (const float*)d_in[4];
    const float* wo  = (const float*)d_in[5];
    const float* bo  = (const float*)d_in[6];
    const float* fc  = (const float*)d_in[7];
    const float* fs  = (const float*)d_in[8];
    float* out = (float*)d_out;

    float *gqkv, *gat, *bc;
    uint32_t *xf, *wch, *wcl, *woh, *wol, *af;
    uint32_t *qf, *kf, *vf;
    cudaGetSymbolAddress((void**)&gqkv, g_qkv);
    cudaGetSymbolAddress((void**)&gat,  g_attn);
    cudaGetSymbolAddress((void**)&bc,   g_bc);
    cudaGetSymbolAddress((void**)&xf,   g_xf);
    cudaGetSymbolAddress((void**)&wch,  g_wch);
    cudaGetSymbolAddress((void**)&wcl,  g_wcl);
    cudaGetSymbolAddress((void**)&woh,  g_woh);
    cudaGetSymbolAddress((void**)&wol,  g_wol);
    cudaGetSymbolAddress((void**)&af,   g_af);
    cudaGetSymbolAddress((void**)&qf,   g_qf);
    cudaGetSymbolAddress((void**)&kf,   g_kf);
    cudaGetSymbolAddress((void**)&vf,   g_vf);

    cudaFuncSetAttribute(flash_mma, cudaFuncAttributeMaxDynamicSharedMemorySize,
                         FLASH_SMEM);
    cudaFuncSetAttribute(gemm_ldsm, cudaFuncAttributeMaxDynamicSharedMemorySize,
                         GB_SMEM);

    // prepare GEMM operands
    {
        int nx = MROWS * K2DIM;
        conv_f16<<<(nx + 255) / 256, 256>>>(x, xf, nx);
        int nq = DIMC * K2DIM;
        split_f16<<<(nq + 255) / 256, 256>>>(wq, wch, wcl, nq);
        int nk = KVOUT * K2DIM;
        split_f16<<<(nk + 255) / 256, 256>>>(wkv, wch + (size_t)DIMC * K2DIM,
                                             wcl + (size_t)DIMC * K2DIM, nk);
        split_f16<<<(nq + 255) / 256, 256>>>(wo, woh, wol, nq);
        concat_bias<<<(NQKV + 255) / 256, 256>>>(bq, bkv, bc);
    }

    // fused Q|KV projection (N = 1728)
    gemm_ldsm<<<dim3((NQKV + 127) / 128, MROWS / 128), 256, GB_SMEM>>>(
        xf, wch, wcl, bc, gqkv, MROWS, NQKV, K2DIM);

    // RoPE + fp16 conversion + V transpose (read fused buffer)
    {
        int tq = BSZ * NH * SEQ * KP;
        rope_q_f16<<<(tq + 255) / 256, 256>>>(gqkv, fc, fs, qf);
        int tk = BSZ * KVH * SEQ * KP;
        rope_k_f16<<<(tk + 255) / 256, 256>>>(gqkv, fc, fs, kf);
        v_trans_f16<<<dim3(SEQ / 64, BSZ * KVH), 256>>>(gqkv, vf);
    }

    // attention (QK 1-pass fp16, PV 1-pass fp16)
    flash_mma<<<dim3(SEQ / 128, BSZ * NH), 256, FLASH_SMEM>>>(
        qf, kf, vf, gat);

    // output projection
    {
        int na = MROWS * K2DIM;
        conv_f16<<<(na + 255) / 256, 256>>>(gat, af, na);
    }
    gemm_ldsm<<<dim3(DIMC / 128, MROWS / 128), 256, GB_SMEM>>>(
        af, woh, wol, bo, out, MROWS, DIMC, K2DIM);
}

// round 15
// speedup vs baseline: 2.7363x; 1.2508x over previous
#include <cuda_runtime.h>
#include <cuda_bf16.h>
#include <cuda_fp16.h>
#include <math.h>
#include <stdint.h>

// Problem constants
#define DIMC   1152
#define NH     8
#define KVH    2
#define HD     144
#define BSZ    4
#define SEQ    2048
#define MROWS  (BSZ*SEQ)          // 8192
#define KVOUT  (2*KVH*HD)         // 576
#define NQKV   (DIMC + KVOUT)     // 1728 combined projection width
#define K2DIM  (DIMC/2)           // 576
#define KP     72                 // pairs per head row
#define TPH    (SEQ/2)            // seq pairs for V^T

// ---------------- scratch (device globals) ----------------------------------
__device__ float g_qkv [(size_t)MROWS * NQKV];      // fused Q|KV projection out
__device__ float g_attn[(size_t)MROWS * DIMC];

// GEMM operands: all single fp16
__device__ uint32_t g_xf [(size_t)MROWS * K2DIM];   // x fp16
__device__ uint32_t g_wc [(size_t)NQKV  * K2DIM];   // combined Wq|Wkv fp16
__device__ float    g_bc [NQKV];                    // combined bias
__device__ uint32_t g_wof[(size_t)DIMC  * K2DIM];   // Wo fp16
__device__ uint32_t g_af [(size_t)MROWS * K2DIM];   // attn out fp16

// attention operands
__device__ uint32_t g_qf[(size_t)BSZ*NH *SEQ*KP];   // Q single fp16 pairs
__device__ uint32_t g_kf[(size_t)BSZ*KVH*SEQ*KP];   // K single fp16 pairs
__device__ uint32_t g_vf[(size_t)BSZ*KVH*HD*TPH];   // V^T single fp16, pairs along s

// ---------------- helpers ----------------------------------------------------
__device__ __forceinline__ uint32_t smem_u32(const void* p) {
    uint32_t a;
    asm("{ .reg .u64 t; cvta.to.shared.u64 t, %1; cvt.u32.u64 %0, t; }"
        : "=r"(a) : "l"(p));
    return a;
}

__device__ __forceinline__ void mma16816h(float* c, const uint32_t* a, const uint32_t* b)
{
    asm volatile(
        "mma.sync.aligned.m16n8k16.row.col.f32.f16.f16.f32 "
        "{%0,%1,%2,%3}, {%4,%5,%6,%7}, {%8,%9}, {%0,%1,%2,%3};\n"
        : "+f"(c[0]), "+f"(c[1]), "+f"(c[2]), "+f"(c[3])
        : "r"(a[0]), "r"(a[1]), "r"(a[2]), "r"(a[3]), "r"(b[0]), "r"(b[1]));
}

__device__ __forceinline__ void ldsm4(uint32_t& r0, uint32_t& r1, uint32_t& r2,
                                      uint32_t& r3, uint32_t a)
{
    asm volatile("ldmatrix.sync.aligned.m8n8.x4.shared.b16 {%0,%1,%2,%3}, [%4];"
                 : "=r"(r0), "=r"(r1), "=r"(r2), "=r"(r3) : "r"(a));
}

#define CP_ASYNC16(sa, gp) \
    asm volatile("cp.async.cg.shared.global [%0], [%1], 16;" :: "r"(sa), "l"(gp))
#define CP_COMMIT() asm volatile("cp.async.commit_group;" ::: "memory")
#define CP_WAIT1()  asm volatile("cp.async.wait_group 1;" ::: "memory")
#define CP_WAIT0()  asm volatile("cp.async.wait_group 0;" ::: "memory")

// ---------------- conversion kernels ----------------------------------------
__global__ void conv_f16(const float* __restrict__ src, uint32_t* __restrict__ dst,
                         int n2)
{
    int i = blockIdx.x * blockDim.x + threadIdx.x;
    if (i >= n2) return;
    float2 v = ((const float2*)src)[i];
    __half2 h = __floats2half2_rn(v.x, v.y);
    dst[i] = *reinterpret_cast<uint32_t*>(&h);
}

__global__ void concat_bias(const float* __restrict__ bq, const float* __restrict__ bkv,
                            float* __restrict__ bc)
{
    int i = blockIdx.x * blockDim.x + threadIdx.x;
    if (i < DIMC) bc[i] = bq[i];
    else if (i < NQKV) bc[i] = bkv[i - DIMC];
}

// ---------------- fp16 1-pass GEMM (ldmatrix + cp.async) --------------------
// C[M,N] = A[M,K]@B[N,K]^T + bias;  A and B single fp16.
#define GB_ROWB 80
#define GB_ARR  (128 * GB_ROWB)
#define GB_BUF  (2 * GB_ARR)          // A, B
#define GB_SMEM (2 * GB_BUF)          // 40960 B

__global__ __launch_bounds__(256, 2)
void gemm_ldsm(const uint32_t* __restrict__ Ag, const uint32_t* __restrict__ Bg,
               const float* __restrict__ bias, float* __restrict__ C,
               int M, int N, int K2)
{
    extern __shared__ char smem[];
    const uint32_t sbase = smem_u32(smem);
    const int tid = threadIdx.x;
    const int warp = tid >> 5, lane = tid & 31;
    const int wm = (warp & 1) * 64;
    const int wn = (warp >> 1) * 32;
    const int m0 = blockIdx.y * 128;
    const int n0 = blockIdx.x * 128;
    const int nch = K2 / 16;

    const int srow = tid >> 2;
    const int schk = tid & 3;
    const int br0 = (n0 + srow     < N) ? n0 + srow      : N - 1;
    const int br1 = (n0 + srow + 64 < N) ? n0 + srow + 64 : N - 1;

    float acc[4][4][4];
#pragma unroll
    for (int i = 0; i < 4; i++)
#pragma unroll
        for (int j = 0; j < 4; j++)
#pragma unroll
            for (int t = 0; t < 4; t++) acc[i][j][t] = 0.f;

    const int lrow = lane & 15;
    const int lch = lane >> 4;

#define GB_ISSUE(ch) do { \
    const int _buf = (ch) & 1; \
    const uint32_t _sb = sbase + _buf * GB_BUF; \
    const size_t _kc = (size_t)(ch) * 16 + schk * 4; \
    uint32_t _so0 = _sb + srow * GB_ROWB + schk * 16; \
    uint32_t _so1 = _sb + (srow + 64) * GB_ROWB + schk * 16; \
    CP_ASYNC16(_so0,            Ag + (size_t)(m0 + srow) * K2 + _kc); \
    CP_ASYNC16(_so1,            Ag + (size_t)(m0 + srow + 64) * K2 + _kc); \
    CP_ASYNC16(_so0 + GB_ARR,   Bg + (size_t)br0 * K2 + _kc); \
    CP_ASYNC16(_so1 + GB_ARR,   Bg + (size_t)br1 * K2 + _kc); \
} while (0)

    GB_ISSUE(0); CP_COMMIT();

    for (int ch = 0; ch < nch; ch++) {
        if (ch + 1 < nch) { GB_ISSUE(ch + 1); CP_COMMIT(); CP_WAIT1(); }
        else              { CP_WAIT0(); }
        __syncthreads();

        const uint32_t sb = sbase + (ch & 1) * GB_BUF;
        const uint32_t aA = sb + (wm + lrow) * GB_ROWB + lch * 16;
        const uint32_t bB = sb + GB_ARR + (wn + lrow) * GB_ROWB + lch * 16;

#pragma unroll
        for (int kk = 0; kk < 2; kk++) {
            uint32_t bb[4][2];
#pragma unroll
            for (int jj = 0; jj < 2; jj++) {
                uint32_t r0, r1, r2, r3;
                ldsm4(r0, r1, r2, r3, bB + jj * (16 * GB_ROWB) + kk * 32);
                bb[2*jj][0] = r0; bb[2*jj][1] = r2;
                bb[2*jj+1][0] = r1; bb[2*jj+1][1] = r3;
            }
#pragma unroll
            for (int i = 0; i < 4; i++) {
                uint32_t ah[4];
                ldsm4(ah[0], ah[1], ah[2], ah[3], aA + i * (16 * GB_ROWB) + kk * 32);
#pragma unroll
                for (int j = 0; j < 4; j++)
                    mma16816h(acc[i][j], ah, bb[j]);
            }
        }
        __syncthreads();
    }

    const int lr = lane >> 2, lc = lane & 3;
#pragma unroll
    for (int i = 0; i < 4; i++) {
        int r0 = m0 + wm + i * 16 + lr;
#pragma unroll
        for (int j = 0; j < 4; j++) {
            int c0 = n0 + wn + j * 8 + lc * 2;
            if (c0 < N) {
                float2 bb = *(const float2*)&bias[c0];
                *(float2*)&C[(size_t)r0 * N + c0] =
                    make_float2(acc[i][j][0] + bb.x, acc[i][j][1] + bb.y);
                *(float2*)&C[(size_t)(r0 + 8) * N + c0] =
                    make_float2(acc[i][j][2] + bb.x, acc[i][j][3] + bb.y);
            }
        }
    }
#undef GB_ISSUE
}

// ---------------- RoPE -> fp16 (reads fused g_qkv, stride NQKV) -------------
__global__ void rope_q_f16(const float* __restrict__ QKV,
                           const float* __restrict__ fc, const float* __restrict__ fs,
                           uint32_t* __restrict__ qf)
{
    int idx = blockIdx.x * blockDim.x + threadIdx.x;
    const int total = BSZ * NH * SEQ * KP;
    if (idx >= total) return;
    int i = idx % KP;
    int s = (idx / KP) % SEQ;
    int h = (idx / (KP * SEQ)) % NH;
    int b = idx / (KP * SEQ * NH);

    size_t base = (size_t)(b * SEQ + s) * NQKV + h * HD;
    float q0 = QKV[base + 2 * i];
    float q1 = QKV[base + 2 * i + 1];
    float c = fc[s * KP + i];
    float sn = fs[s * KP + i];
    const float scale = 0.083333333333333329f;
    __half2 p = __floats2half2_rn((q0 * c - q1 * sn) * scale,
                                  (q0 * sn + q1 * c) * scale);
    qf[idx] = *reinterpret_cast<uint32_t*>(&p);
}

__global__ void rope_k_f16(const float* __restrict__ QKV,
                           const float* __restrict__ fc, const float* __restrict__ fs,
                           uint32_t* __restrict__ kf)
{
    int idx = blockIdx.x * blockDim.x + threadIdx.x;
    const int total = BSZ * KVH * SEQ * KP;
    if (idx >= total) return;
    int i = idx % KP;
    int s = (idx / KP) % SEQ;
    int kvh = (idx / (KP * SEQ)) % KVH;
    int b = idx / (KP * SEQ * KVH);

    size_t base = (size_t)(b * SEQ + s) * NQKV + DIMC + kvh * HD;
    float k0 = QKV[base + 2 * i];
    float k1 = QKV[base + 2 * i + 1];
    float c = fc[s * KP + i];
    float sn = fs[s * KP + i];
    __half2 p = __floats2half2_rn(k0 * c - k1 * sn, k0 * sn + k1 * c);
    kf[idx] = *reinterpret_cast<uint32_t*>(&p);
}

// V transpose + single fp16: out [b*KVH+kvh][d][sp], pairs along s.
__global__ void v_trans_f16(const float* __restrict__ QKV,
                            uint32_t* __restrict__ vf)
{
    __shared__ float tile[64][HD + 1];
    const int st = blockIdx.x;
    const int bk = blockIdx.y;
    const int b = bk / KVH, kvh = bk % KVH;
    const int tid = threadIdx.x;

    const float* src = QKV + (size_t)(b * SEQ + st * 64) * NQKV
                           + DIMC + KVH * HD + kvh * HD;
    for (int e = tid; e < 64 * HD; e += 256) {
        int r = e / HD, c = e % HD;
        tile[r][c] = src[(size_t)r * NQKV + c];
    }
    __syncthreads();

    uint32_t* ov = vf + ((size_t)bk * HD) * TPH + st * 32;
    for (int e = tid; e < HD * 32; e += 256) {
        int d = e / 32, sp = e % 32;
        __half2 p = __floats2half2_rn(tile[2 * sp][d], tile[2 * sp + 1][d]);
        ov[(size_t)d * TPH + sp] = *reinterpret_cast<uint32_t*>(&p);
    }
}

// ---------------- Flash attention -------------------------------------------
// QK: fp16 1-pass.  PV: fp16 1-pass.
#define QS 76
#define KS 76
#define VS 36

#define FLASH_SMEM ((128*QS + 64*KS + HD*VS) * (int)sizeof(uint32_t))

__global__ __launch_bounds__(256, 1)
void flash_mma(const uint32_t* __restrict__ qf, const uint32_t* __restrict__ kf,
               const uint32_t* __restrict__ vf,
               float* __restrict__ out)
{
    extern __shared__ uint32_t fsm[];
    uint32_t* sQ  = fsm;
    uint32_t* sK  = sQ + 128 * QS;
    uint32_t* sV  = sK + 64 * KS;

    const int qt = (gridDim.x - 1) - blockIdx.x;
    const int bh = blockIdx.y;
    const int b = bh >> 3;
    const int h = bh & 7;
    const int kvh = h >> 2;
    const int bk = b * KVH + kvh;

    const int tid = threadIdx.x;
    const int warp = tid >> 5, lane = tid & 31;
    const int lr = lane >> 2, lc = lane & 3;
    const int wm = warp * 16;

    {
        const uint32_t* gq = qf + ((size_t)bh * SEQ + qt * 128) * KP;
        for (int e = tid; e < 128 * 18; e += 256) {
            int r = e / 18, c = (e % 18) * 4;
            *(uint4*)&sQ[r * QS + c] = *(const uint4*)&gq[(size_t)r * KP + c];
        }
    }

    float o[18][4];
#pragma unroll
    for (int n = 0; n < 18; n++)
#pragma unroll
        for (int t = 0; t < 4; t++) o[n][t] = 0.f;
    float m0 = -1e30f, m1 = -1e30f, l0 = 0.f, l1 = 0.f;

    const int ktmax = 2 * qt + 1;
    const int qrow0 = qt * 128 + wm;

    for (int kt = 0; kt <= ktmax; kt++) {
        __syncthreads();
        {
            const uint32_t* gk = kf + ((size_t)bk * SEQ + kt * 64) * KP;
            for (int e = tid; e < 64 * 18; e += 256) {
                int r = e / 18, c = (e % 18) * 4;
                *(uint4*)&sK[r * KS + c] = *(const uint4*)&gk[(size_t)r * KP + c];
            }
            const uint32_t* gv = vf + (size_t)bk * HD * TPH + kt * 32;
            for (int e = tid; e < HD * 8; e += 256) {
                int r = e / 8, c = (e % 8) * 4;
                *(uint4*)&sV[r * VS + c] = *(const uint4*)&gv[(size_t)r * TPH + c];
            }
        }
        __syncthreads();

        float sfr[8][4];
#pragma unroll
        for (int j = 0; j < 8; j++)
#pragma unroll
            for (int t = 0; t < 4; t++) sfr[j][t] = 0.f;

#pragma unroll
        for (int kc = 0; kc < 9; kc++) {
            uint32_t ah[4];
            int ra = (wm + lr) * QS + kc * 8 + lc;
            int rb = (wm + lr + 8) * QS + kc * 8 + lc;
            ah[0] = sQ[ra];     ah[1] = sQ[rb];
            ah[2] = sQ[ra + 4]; ah[3] = sQ[rb + 4];
#pragma unroll
            for (int j = 0; j < 8; j++) {
                int rk = (j * 8 + lr) * KS + kc * 8 + lc;
                uint32_t bh2[2] = { sK[rk], sK[rk + 4] };
                mma16816h(sfr[j], ah, bh2);
            }
        }

        if (kt * 64 + 63 > qrow0) {
            int key0 = kt * 64;
#pragma unroll
            for (int j = 0; j < 8; j++) {
                int kc0 = key0 + j * 8 + 2 * lc;
                if (kc0     > qrow0 + lr)     sfr[j][0] = -1e9f;
                if (kc0 + 1 > qrow0 + lr)     sfr[j][1] = -1e9f;
                if (kc0     > qrow0 + lr + 8) sfr[j][2] = -1e9f;
                if (kc0 + 1 > qrow0 + lr + 8) sfr[j][3] = -1e9f;
            }
        }

        float mx0 = -1e30f, mx1 = -1e30f;
#pragma unroll
        for (int j = 0; j < 8; j++) {
            mx0 = fmaxf(mx0, fmaxf(sfr[j][0], sfr[j][1]));
            mx1 = fmaxf(mx1, fmaxf(sfr[j][2], sfr[j][3]));
        }
#pragma unroll
        for (int off = 1; off < 4; off <<= 1) {
            mx0 = fmaxf(mx0, __shfl_xor_sync(0xffffffffu, mx0, off));
            mx1 = fmaxf(mx1, __shfl_xor_sync(0xffffffffu, mx1, off));
        }
        float mn0 = fmaxf(m0, mx0), mn1 = fmaxf(m1, mx1);
        float c0 = __expf(m0 - mn0), c1 = __expf(m1 - mn1);
        m0 = mn0; m1 = mn1;

        float s0 = 0.f, s1 = 0.f;
#pragma unroll
        for (int j = 0; j < 8; j++) {
            sfr[j][0] = __expf(sfr[j][0] - m0);
            sfr[j][1] = __expf(sfr[j][1] - m0);
            sfr[j][2] = __expf(sfr[j][2] - m1);
            sfr[j][3] = __expf(sfr[j][3] - m1);
            s0 += sfr[j][0] + sfr[j][1];
            s1 += sfr[j][2] + sfr[j][3];
        }
#pragma unroll
        for (int off = 1; off < 4; off <<= 1) {
            s0 += __shfl_xor_sync(0xffffffffu, s0, off);
            s1 += __shfl_xor_sync(0xffffffffu, s1, off);
        }
        l0 = l0 * c0 + s0;
        l1 = l1 * c1 + s1;

#pragma unroll
        for (int n = 0; n < 18; n++) {
            o[n][0] *= c0; o[n][1] *= c0;
            o[n][2] *= c1; o[n][3] *= c1;
        }

        // P -> single fp16 fragments
        uint32_t ph01[8], ph23[8];
#pragma unroll
        for (int j = 0; j < 8; j++) {
            __half2 p0 = __floats2half2_rn(sfr[j][0], sfr[j][1]);
            __half2 p1 = __floats2half2_rn(sfr[j][2], sfr[j][3]);
            ph01[j] = *reinterpret_cast<uint32_t*>(&p0);
            ph23[j] = *reinterpret_cast<uint32_t*>(&p1);
        }

        // O += P V  -- fp16 1-pass
#pragma unroll
        for (int kc = 0; kc < 4; kc++) {
            uint32_t pa[4] = { ph01[2*kc], ph23[2*kc], ph01[2*kc+1], ph23[2*kc+1] };
#pragma unroll
            for (int n = 0; n < 18; n++) {
                int rv = (n * 8 + lr) * VS + kc * 8 + lc;
                uint32_t bv[2] = { sV[rv], sV[rv + 4] };
                mma16816h(o[n], pa, bv);
            }
        }
    }

    float inv0 = 1.f / l0, inv1 = 1.f / l1;
    int r0 = qt * 128 + wm + lr;
    float* orow0 = out + ((size_t)b * SEQ + r0)     * DIMC + h * HD;
    float* orow1 = out + ((size_t)b * SEQ + r0 + 8) * DIMC + h * HD;
#pragma unroll
    for (int n = 0; n < 18; n++) {
        int col = n * 8 + 2 * lc;
        *(float2*)&orow0[col] = make_float2(o[n][0] * inv0, o[n][1] * inv0);
        *(float2*)&orow1[col] = make_float2(o[n][2] * inv1, o[n][3] * inv1);
    }
}

// ---------------- launcher --------------------------------------------------
extern "C" void kernel_launch(void* const* d_in, const int* in_sizes, int n_in,
                              void* d_out, int out_size)
{
    const float* x   = (const float*)d_in[0];
    const float* wq  = (const float*)d_in[1];
    const float* bq  = (const float*)d_in[2];
    const float* wkv = (const float*)d_in[3];
    const float* bkv = (const float*)d_in[4];
    const float* wo  = (const float*)d_in[5];
    const float* bo  = (const float*)d_in[6];
    const float* fc  = (const float*)d_in[7];
    const float* fs  = (const float*)d_in[8];
    float* out = (float*)d_out;

    float *gqkv, *gat, *bc;
    uint32_t *xf, *wc, *wof, *af;
    uint32_t *qf, *kf, *vf;
    cudaGetSymbolAddress((void**)&gqkv, g_qkv);
    cudaGetSymbolAddress((void**)&gat,  g_attn);
    cudaGetSymbolAddress((void**)&bc,   g_bc);
    cudaGetSymbolAddress((void**)&xf,   g_xf);
    cudaGetSymbolAddress((void**)&wc,   g_wc);
    cudaGetSymbolAddress((void**)&wof,  g_wof);
    cudaGetSymbolAddress((void**)&af,   g_af);
    cudaGetSymbolAddress((void**)&qf,   g_qf);
    cudaGetSymbolAddress((void**)&kf,   g_kf);
    cudaGetSymbolAddress((void**)&vf,   g_vf);

    cudaFuncSetAttribute(flash_mma, cudaFuncAttributeMaxDynamicSharedMemorySize,
                         FLASH_SMEM);
    cudaFuncSetAttribute(gemm_ldsm, cudaFuncAttributeMaxDynamicSharedMemorySize,
                         GB_SMEM);

    // prepare GEMM operands (all fp16)
    {
        int nx = MROWS * K2DIM;
        conv_f16<<<(nx + 255) / 256, 256>>>(x, xf, nx);
        int nq = DIMC * K2DIM;
        conv_f16<<<(nq + 255) / 256, 256>>>(wq, wc, nq);
        int nk = KVOUT * K2DIM;
        conv_f16<<<(nk + 255) / 256, 256>>>(wkv, wc + (size_t)DIMC * K2DIM, nk);
        conv_f16<<<(nq + 255) / 256, 256>>>(wo, wof, nq);
        concat_bias<<<(NQKV + 255) / 256, 256>>>(bq, bkv, bc);
    }

    // fused Q|KV projection (N = 1728, 1-pass fp16)
    gemm_ldsm<<<dim3((NQKV + 127) / 128, MROWS / 128), 256, GB_SMEM>>>(
        xf, wc, bc, gqkv, MROWS, NQKV, K2DIM);

    // RoPE + fp16 conversion + V transpose (read fused buffer)
    {
        int tq = BSZ * NH * SEQ * KP;
        rope_q_f16<<<(tq + 255) / 256, 256>>>(gqkv, fc, fs, qf);
        int tk = BSZ * KVH * SEQ * KP;
        rope_k_f16<<<(tk + 255) / 256, 256>>>(gqkv, fc, fs, kf);
        v_trans_f16<<<dim3(SEQ / 64, BSZ * KVH), 256>>>(gqkv, vf);
    }

    // attention (QK 1-pass fp16, PV 1-pass fp16)
    flash_mma<<<dim3(SEQ / 128, BSZ * NH), 256, FLASH_SMEM>>>(
        qf, kf, vf, gat);

    // output projection (1-pass fp16)
    {
        int na = MROWS * K2DIM;
        conv_f16<<<(na + 255) / 256, 256>>>(gat, af, na);
    }
    gemm_ldsm<<<dim3(DIMC / 128, MROWS / 128), 256, GB_SMEM>>>(
        af, wof, bo, out, MROWS, DIMC, K2DIM);
}

// round 16
// speedup vs baseline: 3.7170x; 1.3584x over previous
#include <cuda_runtime.h>
#include <cuda_bf16.h>
#include <cuda_fp16.h>
#include <math.h>
#include <stdint.h>

// Problem constants
#define DIMC   1152
#define NH     8
#define KVH    2
#define HD     144
#define BSZ    4
#define SEQ    2048
#define MROWS  (BSZ*SEQ)          // 8192
#define KVOUT  (2*KVH*HD)         // 576
#define NQKV   (DIMC + KVOUT)     // 1728
#define K2DIM  (DIMC/2)           // 576
#define KP     72                 // pairs per head row
#define TPH    (SEQ/2)            // seq pairs for V^T

// ---------------- scratch (device globals) ----------------------------------
__device__ float g_qkv [(size_t)MROWS * NQKV];      // fused Q|KV projection out

// GEMM operands: all single fp16
__device__ uint32_t g_xf [(size_t)MROWS * K2DIM];   // x fp16
__device__ uint32_t g_wc [(size_t)NQKV  * K2DIM];   // combined Wq|Wkv fp16
__device__ float    g_bc [NQKV];                    // combined bias
__device__ uint32_t g_wof[(size_t)DIMC  * K2DIM];   // Wo fp16
__device__ uint32_t g_af [(size_t)MROWS * K2DIM];   // attn out fp16 (flash writes)

// attention operands
__device__ uint32_t g_qf[(size_t)BSZ*NH *SEQ*KP];   // Q fp16 pairs
__device__ uint32_t g_kf[(size_t)BSZ*KVH*SEQ*KP];   // K fp16 pairs
__device__ uint32_t g_vf[(size_t)BSZ*KVH*HD*TPH];   // V^T fp16, pairs along s

// ---------------- helpers ----------------------------------------------------
__device__ __forceinline__ uint32_t smem_u32(const void* p) {
    uint32_t a;
    asm("{ .reg .u64 t; cvta.to.shared.u64 t, %1; cvt.u32.u64 %0, t; }"
        : "=r"(a) : "l"(p));
    return a;
}

__device__ __forceinline__ void mma16816h(float* c, const uint32_t* a, const uint32_t* b)
{
    asm volatile(
        "mma.sync.aligned.m16n8k16.row.col.f32.f16.f16.f32 "
        "{%0,%1,%2,%3}, {%4,%5,%6,%7}, {%8,%9}, {%0,%1,%2,%3};\n"
        : "+f"(c[0]), "+f"(c[1]), "+f"(c[2]), "+f"(c[3])
        : "r"(a[0]), "r"(a[1]), "r"(a[2]), "r"(a[3]), "r"(b[0]), "r"(b[1]));
}

__device__ __forceinline__ void ldsm4(uint32_t& r0, uint32_t& r1, uint32_t& r2,
                                      uint32_t& r3, uint32_t a)
{
    asm volatile("ldmatrix.sync.aligned.m8n8.x4.shared.b16 {%0,%1,%2,%3}, [%4];"
                 : "=r"(r0), "=r"(r1), "=r"(r2), "=r"(r3) : "r"(a));
}

#define CP_ASYNC16(sa, gp) \
    asm volatile("cp.async.cg.shared.global [%0], [%1], 16;" :: "r"(sa), "l"(gp))
#define CP_COMMIT() asm volatile("cp.async.commit_group;" ::: "memory")
#define CP_WAIT1()  asm volatile("cp.async.wait_group 1;" ::: "memory")
#define CP_WAIT0()  asm volatile("cp.async.wait_group 0;" ::: "memory")

// ---------------- prep kernels ----------------------------------------------
__global__ void conv_f16(const float* __restrict__ src, uint32_t* __restrict__ dst,
                         int n2)
{
    int i = blockIdx.x * blockDim.x + threadIdx.x;
    if (i >= n2) return;
    float2 v = ((const float2*)src)[i];
    __half2 h = __floats2half2_rn(v.x, v.y);
    dst[i] = *reinterpret_cast<uint32_t*>(&h);
}

// all three weight conversions in one kernel; wc = [wq | wkv] contiguous
__global__ void prep_weights(const float* __restrict__ wq,
                             const float* __restrict__ wkv,
                             const float* __restrict__ wo,
                             uint32_t* __restrict__ wc, uint32_t* __restrict__ wof)
{
    const int nq = DIMC * K2DIM;
    const int nk = KVOUT * K2DIM;
    int i = blockIdx.x * blockDim.x + threadIdx.x;
    float2 v;
    uint32_t* dst;
    if (i < nq) {
        v = ((const float2*)wq)[i];
        dst = wc + i;
    } else if (i < nq + nk) {
        v = ((const float2*)wkv)[i - nq];
        dst = wc + i;
    } else if (i < 2 * nq + nk) {
        v = ((const float2*)wo)[i - nq - nk];
        dst = wof + (i - nq - nk);
    } else return;
    __half2 h = __floats2half2_rn(v.x, v.y);
    *dst = *reinterpret_cast<uint32_t*>(&h);
}

__global__ void concat_bias(const float* __restrict__ bq, const float* __restrict__ bkv,
                            float* __restrict__ bc)
{
    int i = blockIdx.x * blockDim.x + threadIdx.x;
    if (i < DIMC) bc[i] = bq[i];
    else if (i < NQKV) bc[i] = bkv[i - DIMC];
}

// ---------------- fp16 1-pass GEMM (ldmatrix + cp.async) --------------------
#define GB_ROWB 80
#define GB_ARR  (128 * GB_ROWB)
#define GB_BUF  (2 * GB_ARR)          // A, B
#define GB_SMEM (2 * GB_BUF)          // 40960 B

__global__ __launch_bounds__(256, 2)
void gemm_ldsm(const uint32_t* __restrict__ Ag, const uint32_t* __restrict__ Bg,
               const float* __restrict__ bias, float* __restrict__ C,
               int M, int N, int K2)
{
    extern __shared__ char smem[];
    const uint32_t sbase = smem_u32(smem);
    const int tid = threadIdx.x;
    const int warp = tid >> 5, lane = tid & 31;
    const int wm = (warp & 1) * 64;
    const int wn = (warp >> 1) * 32;
    const int m0 = blockIdx.y * 128;
    const int n0 = blockIdx.x * 128;
    const int nch = K2 / 16;

    const int srow = tid >> 2;
    const int schk = tid & 3;
    const int br0 = (n0 + srow     < N) ? n0 + srow      : N - 1;
    const int br1 = (n0 + srow + 64 < N) ? n0 + srow + 64 : N - 1;

    float acc[4][4][4];
#pragma unroll
    for (int i = 0; i < 4; i++)
#pragma unroll
        for (int j = 0; j < 4; j++)
#pragma unroll
            for (int t = 0; t < 4; t++) acc[i][j][t] = 0.f;

    const int lrow = lane & 15;
    const int lch = lane >> 4;

#define GB_ISSUE(ch) do { \
    const int _buf = (ch) & 1; \
    const uint32_t _sb = sbase + _buf * GB_BUF; \
    const size_t _kc = (size_t)(ch) * 16 + schk * 4; \
    uint32_t _so0 = _sb + srow * GB_ROWB + schk * 16; \
    uint32_t _so1 = _sb + (srow + 64) * GB_ROWB + schk * 16; \
    CP_ASYNC16(_so0,            Ag + (size_t)(m0 + srow) * K2 + _kc); \
    CP_ASYNC16(_so1,            Ag + (size_t)(m0 + srow + 64) * K2 + _kc); \
    CP_ASYNC16(_so0 + GB_ARR,   Bg + (size_t)br0 * K2 + _kc); \
    CP_ASYNC16(_so1 + GB_ARR,   Bg + (size_t)br1 * K2 + _kc); \
} while (0)

    GB_ISSUE(0); CP_COMMIT();

    for (int ch = 0; ch < nch; ch++) {
        if (ch + 1 < nch) { GB_ISSUE(ch + 1); CP_COMMIT(); CP_WAIT1(); }
        else              { CP_WAIT0(); }
        __syncthreads();

        const uint32_t sb = sbase + (ch & 1) * GB_BUF;
        const uint32_t aA = sb + (wm + lrow) * GB_ROWB + lch * 16;
        const uint32_t bB = sb + GB_ARR + (wn + lrow) * GB_ROWB + lch * 16;

#pragma unroll
        for (int kk = 0; kk < 2; kk++) {
            uint32_t bb[4][2];
#pragma unroll
            for (int jj = 0; jj < 2; jj++) {
                uint32_t r0, r1, r2, r3;
                ldsm4(r0, r1, r2, r3, bB + jj * (16 * GB_ROWB) + kk * 32);
                bb[2*jj][0] = r0; bb[2*jj][1] = r2;
                bb[2*jj+1][0] = r1; bb[2*jj+1][1] = r3;
            }
#pragma unroll
            for (int i = 0; i < 4; i++) {
                uint32_t ah[4];
                ldsm4(ah[0], ah[1], ah[2], ah[3], aA + i * (16 * GB_ROWB) + kk * 32);
#pragma unroll
                for (int j = 0; j < 4; j++)
                    mma16816h(acc[i][j], ah, bb[j]);
            }
        }
        __syncthreads();
    }

    const int lr = lane >> 2, lc = lane & 3;
#pragma unroll
    for (int i = 0; i < 4; i++) {
        int r0 = m0 + wm + i * 16 + lr;
#pragma unroll
        for (int j = 0; j < 4; j++) {
            int c0 = n0 + wn + j * 8 + lc * 2;
            if (c0 < N) {
                float2 bb = *(const float2*)&bias[c0];
                *(float2*)&C[(size_t)r0 * N + c0] =
                    make_float2(acc[i][j][0] + bb.x, acc[i][j][1] + bb.y);
                *(float2*)&C[(size_t)(r0 + 8) * N + c0] =
                    make_float2(acc[i][j][2] + bb.x, acc[i][j][3] + bb.y);
            }
        }
    }
#undef GB_ISSUE
}

// ---------------- RoPE Q+K merged -> fp16 ------------------------------------
__global__ void rope_qk_f16(const float* __restrict__ QKV,
                            const float* __restrict__ fc, const float* __restrict__ fs,
                            uint32_t* __restrict__ qf, uint32_t* __restrict__ kf)
{
    const int tq = BSZ * NH * SEQ * KP;
    const int tk = BSZ * KVH * SEQ * KP;
    int idx = blockIdx.x * blockDim.x + threadIdx.x;
    if (idx < tq) {
        int i = idx % KP;
        int s = (idx / KP) % SEQ;
        int h = (idx / (KP * SEQ)) % NH;
        int b = idx / (KP * SEQ * NH);
        size_t base = (size_t)(b * SEQ + s) * NQKV + h * HD;
        float q0 = QKV[base + 2 * i];
        float q1 = QKV[base + 2 * i + 1];
        float c = fc[s * KP + i];
        float sn = fs[s * KP + i];
        const float scale = 0.083333333333333329f;
        __half2 p = __floats2half2_rn((q0 * c - q1 * sn) * scale,
                                      (q0 * sn + q1 * c) * scale);
        qf[idx] = *reinterpret_cast<uint32_t*>(&p);
    } else if (idx < tq + tk) {
        int k = idx - tq;
        int i = k % KP;
        int s = (k / KP) % SEQ;
        int kvh = (k / (KP * SEQ)) % KVH;
        int b = k / (KP * SEQ * KVH);
        size_t base = (size_t)(b * SEQ + s) * NQKV + DIMC + kvh * HD;
        float k0 = QKV[base + 2 * i];
        float k1 = QKV[base + 2 * i + 1];
        float c = fc[s * KP + i];
        float sn = fs[s * KP + i];
        __half2 p = __floats2half2_rn(k0 * c - k1 * sn, k0 * sn + k1 * c);
        kf[k] = *reinterpret_cast<uint32_t*>(&p);
    }
}

// V transpose + fp16: out [b*KVH+kvh][d][sp], pairs along s.
__global__ void v_trans_f16(const float* __restrict__ QKV,
                            uint32_t* __restrict__ vf)
{
    __shared__ float tile[64][HD + 1];
    const int st = blockIdx.x;
    const int bk = blockIdx.y;
    const int b = bk / KVH, kvh = bk % KVH;
    const int tid = threadIdx.x;

    const float* src = QKV + (size_t)(b * SEQ + st * 64) * NQKV
                           + DIMC + KVH * HD + kvh * HD;
    for (int e = tid; e < 64 * HD; e += 256) {
        int r = e / HD, c = e % HD;
        tile[r][c] = src[(size_t)r * NQKV + c];
    }
    __syncthreads();

    uint32_t* ov = vf + ((size_t)bk * HD) * TPH + st * 32;
    for (int e = tid; e < HD * 32; e += 256) {
        int d = e / 32, sp = e % 32;
        __half2 p = __floats2half2_rn(tile[2 * sp][d], tile[2 * sp + 1][d]);
        ov[(size_t)d * TPH + sp] = *reinterpret_cast<uint32_t*>(&p);
    }
}

// ---------------- Flash attention (cp.async K/V pipeline) --------------------
// QK 1-pass fp16, PV 1-pass fp16. Epilogue writes fp16 pairs to g_af.
#define QS 76
#define KS 76
#define VS 36
#define FL_KBUF (64 * KS)
#define FL_VBUF (HD * VS)

#define FLASH_SMEM ((128*QS + 2*FL_KBUF + 2*FL_VBUF) * (int)sizeof(uint32_t))

__global__ __launch_bounds__(256, 1)
void flash_mma(const uint32_t* __restrict__ qf, const uint32_t* __restrict__ kf,
               const uint32_t* __restrict__ vf,
               uint32_t* __restrict__ af)
{
    extern __shared__ uint32_t fsm[];
    uint32_t* sQ  = fsm;
    uint32_t* sKb = sQ + 128 * QS;            // two K buffers
    uint32_t* sVb = sKb + 2 * FL_KBUF;        // two V buffers
    const uint32_t sKbA = smem_u32(sKb);
    const uint32_t sVbA = smem_u32(sVb);

    const int qt = (gridDim.x - 1) - blockIdx.x;
    const int bh = blockIdx.y;
    const int b = bh >> 3;
    const int h = bh & 7;
    const int kvh = h >> 2;
    const int bk = b * KVH + kvh;

    const int tid = threadIdx.x;
    const int warp = tid >> 5, lane = tid & 31;
    const int lr = lane >> 2, lc = lane & 3;
    const int wm = warp * 16;

    const uint32_t* gkb = kf + (size_t)bk * SEQ * KP;
    const uint32_t* gvb = vf + (size_t)bk * HD * TPH;

#define FL_ISSUE(kt) do { \
    const uint32_t _kb = sKbA + (((kt) & 1) * FL_KBUF) * 4; \
    const uint32_t _vb = sVbA + (((kt) & 1) * FL_VBUF) * 4; \
    const uint32_t* _gk = gkb + (size_t)(kt) * 64 * KP; \
    for (int e = tid; e < 64 * 18; e += 256) { \
        int r = e / 18, c = (e % 18) * 4; \
        CP_ASYNC16(_kb + (r * KS + c) * 4, _gk + (size_t)r * KP + c); \
    } \
    const uint32_t* _gv = gvb + (size_t)(kt) * 32; \
    for (int e = tid; e < HD * 8; e += 256) { \
        int r = e / 8, c = (e % 8) * 4; \
        CP_ASYNC16(_vb + (r * VS + c) * 4, _gv + (size_t)r * TPH + c); \
    } \
} while (0)

    // Q tile load (plain; overlaps first K/V prefetch)
    FL_ISSUE(0); CP_COMMIT();
    {
        const uint32_t* gq = qf + ((size_t)bh * SEQ + qt * 128) * KP;
        for (int e = tid; e < 128 * 18; e += 256) {
            int r = e / 18, c = (e % 18) * 4;
            *(uint4*)&sQ[r * QS + c] = *(const uint4*)&gq[(size_t)r * KP + c];
        }
    }

    float o[18][4];
#pragma unroll
    for (int n = 0; n < 18; n++)
#pragma unroll
        for (int t = 0; t < 4; t++) o[n][t] = 0.f;
    float m0 = -1e30f, m1 = -1e30f, l0 = 0.f, l1 = 0.f;

    const int ktmax = 2 * qt + 1;
    const int qrow0 = qt * 128 + wm;

    for (int kt = 0; kt <= ktmax; kt++) {
        if (kt < ktmax) { FL_ISSUE(kt + 1); CP_COMMIT(); CP_WAIT1(); }
        else            { CP_WAIT0(); }
        __syncthreads();

        uint32_t* sK = sKb + (kt & 1) * FL_KBUF;
        uint32_t* sV = sVb + (kt & 1) * FL_VBUF;

        float sfr[8][4];
#pragma unroll
        for (int j = 0; j < 8; j++)
#pragma unroll
            for (int t = 0; t < 4; t++) sfr[j][t] = 0.f;

#pragma unroll
        for (int kc = 0; kc < 9; kc++) {
            uint32_t ah[4];
            int ra = (wm + lr) * QS + kc * 8 + lc;
            int rb = (wm + lr + 8) * QS + kc * 8 + lc;
            ah[0] = sQ[ra];     ah[1] = sQ[rb];
            ah[2] = sQ[ra + 4]; ah[3] = sQ[rb + 4];
#pragma unroll
            for (int j = 0; j < 8; j++) {
                int rk = (j * 8 + lr) * KS + kc * 8 + lc;
                uint32_t bh2[2] = { sK[rk], sK[rk + 4] };
                mma16816h(sfr[j], ah, bh2);
            }
        }

        if (kt * 64 + 63 > qrow0) {
            int key0 = kt * 64;
#pragma unroll
            for (int j = 0; j < 8; j++) {
                int kc0 = key0 + j * 8 + 2 * lc;
                if (kc0     > qrow0 + lr)     sfr[j][0] = -1e9f;
                if (kc0 + 1 > qrow0 + lr)     sfr[j][1] = -1e9f;
                if (kc0     > qrow0 + lr + 8) sfr[j][2] = -1e9f;
                if (kc0 + 1 > qrow0 + lr + 8) sfr[j][3] = -1e9f;
            }
        }

        float mx0 = -1e30f, mx1 = -1e30f;
#pragma unroll
        for (int j = 0; j < 8; j++) {
            mx0 = fmaxf(mx0, fmaxf(sfr[j][0], sfr[j][1]));
            mx1 = fmaxf(mx1, fmaxf(sfr[j][2], sfr[j][3]));
        }
#pragma unroll
        for (int off = 1; off < 4; off <<= 1) {
            mx0 = fmaxf(mx0, __shfl_xor_sync(0xffffffffu, mx0, off));
            mx1 = fmaxf(mx1, __shfl_xor_sync(0xffffffffu, mx1, off));
        }
        float mn0 = fmaxf(m0, mx0), mn1 = fmaxf(m1, mx1);
        float c0 = __expf(m0 - mn0), c1 = __expf(m1 - mn1);
        m0 = mn0; m1 = mn1;

        float s0 = 0.f, s1 = 0.f;
#pragma unroll
        for (int j = 0; j < 8; j++) {
            sfr[j][0] = __expf(sfr[j][0] - m0);
            sfr[j][1] = __expf(sfr[j][1] - m0);
            sfr[j][2] = __expf(sfr[j][2] - m1);
            sfr[j][3] = __expf(sfr[j][3] - m1);
            s0 += sfr[j][0] + sfr[j][1];
            s1 += sfr[j][2] + sfr[j][3];
        }
#pragma unroll
        for (int off = 1; off < 4; off <<= 1) {
            s0 += __shfl_xor_sync(0xffffffffu, s0, off);
            s1 += __shfl_xor_sync(0xffffffffu, s1, off);
        }
        l0 = l0 * c0 + s0;
        l1 = l1 * c1 + s1;

#pragma unroll
        for (int n = 0; n < 18; n++) {
            o[n][0] *= c0; o[n][1] *= c0;
            o[n][2] *= c1; o[n][3] *= c1;
        }

        uint32_t ph01[8], ph23[8];
#pragma unroll
        for (int j = 0; j < 8; j++) {
            __half2 p0 = __floats2half2_rn(sfr[j][0], sfr[j][1]);
            __half2 p1 = __floats2half2_rn(sfr[j][2], sfr[j][3]);
            ph01[j] = *reinterpret_cast<uint32_t*>(&p0);
            ph23[j] = *reinterpret_cast<uint32_t*>(&p1);
        }

#pragma unroll
        for (int kc = 0; kc < 4; kc++) {
            uint32_t pa[4] = { ph01[2*kc], ph23[2*kc], ph01[2*kc+1], ph23[2*kc+1] };
#pragma unroll
            for (int n = 0; n < 18; n++) {
                int rv = (n * 8 + lr) * VS + kc * 8 + lc;
                uint32_t bv[2] = { sV[rv], sV[rv + 4] };
                mma16816h(o[n], pa, bv);
            }
        }
        __syncthreads();   // protect buffer (kt&1) before prefetch of kt+2
    }

    // epilogue: normalize, convert to fp16 pairs, store to g_af
    float inv0 = 1.f / l0, inv1 = 1.f / l1;
    int r0 = qt * 128 + wm + lr;
    uint32_t* arow0 = af + (size_t)(b * SEQ + r0)     * K2DIM + h * KP;
    uint32_t* arow1 = af + (size_t)(b * SEQ + r0 + 8) * K2DIM + h * KP;
#pragma unroll
    for (int n = 0; n < 18; n++) {
        int cp = n * 4 + lc;
        __half2 v0 = __floats2half2_rn(o[n][0] * inv0, o[n][1] * inv0);
        __half2 v1 = __floats2half2_rn(o[n][2] * inv1, o[n][3] * inv1);
        arow0[cp] = *reinterpret_cast<uint32_t*>(&v0);
        arow1[cp] = *reinterpret_cast<uint32_t*>(&v1);
    }
#undef FL_ISSUE
}

// ---------------- launcher --------------------------------------------------
extern "C" void kernel_launch(void* const* d_in, const int* in_sizes, int n_in,
                              void* d_out, int out_size)
{
    const float* x   = (const float*)d_in[0];
    const float* wq  = (const float*)d_in[1];
    const float* bq  = (const float*)d_in[2];
    const float* wkv = (const float*)d_in[3];
    const float* bkv = (const float*)d_in[4];
    const float* wo  = (const float*)d_in[5];
    const float* bo  = (const float*)d_in[6];
    const float* fc  = (const float*)d_in[7];
    const float* fs  = (const float*)d_in[8];
    float* out = (float*)d_out;

    float *gqkv, *bc;
    uint32_t *xf, *wc, *wof, *af;
    uint32_t *qf, *kf, *vf;
    cudaGetSymbolAddress((void**)&gqkv, g_qkv);
    cudaGetSymbolAddress((void**)&bc,   g_bc);
    cudaGetSymbolAddress((void**)&xf,   g_xf);
    cudaGetSymbolAddress((void**)&wc,   g_wc);
    cudaGetSymbolAddress((void**)&wof,  g_wof);
    cudaGetSymbolAddress((void**)&af,   g_af);
    cudaGetSymbolAddress((void**)&qf,   g_qf);
    cudaGetSymbolAddress((void**)&kf,   g_kf);
    cudaGetSymbolAddress((void**)&vf,   g_vf);

    cudaFuncSetAttribute(flash_mma, cudaFuncAttributeMaxDynamicSharedMemorySize,
                         FLASH_SMEM);
    cudaFuncSetAttribute(gemm_ldsm, cudaFuncAttributeMaxDynamicSharedMemorySize,
                         GB_SMEM);

    // prep (3 launches)
    {
        int nx = MROWS * K2DIM;
        conv_f16<<<(nx + 255) / 256, 256>>>(x, xf, nx);
        int nw = (2 * DIMC + KVOUT) * K2DIM;
        prep_weights<<<(nw + 255) / 256, 256>>>(wq, wkv, wo, wc, wof);
        concat_bias<<<(NQKV + 255) / 256, 256>>>(bq, bkv, bc);
    }

    // fused Q|KV projection
    gemm_ldsm<<<dim3((NQKV + 127) / 128, MROWS / 128), 256, GB_SMEM>>>(
        xf, wc, bc, gqkv, MROWS, NQKV, K2DIM);

    // RoPE Q+K merged, V transpose
    {
        int t = BSZ * NH * SEQ * KP + BSZ * KVH * SEQ * KP;
        rope_qk_f16<<<(t + 255) / 256, 256>>>(gqkv, fc, fs, qf, kf);
        v_trans_f16<<<dim3(SEQ / 64, BSZ * KVH), 256>>>(gqkv, vf);
    }

    // attention (pipelined; writes fp16 af directly)
    flash_mma<<<dim3(SEQ / 128, BSZ * NH), 256, FLASH_SMEM>>>(qf, kf, vf, af);

    // output projection
    gemm_ldsm<<<dim3(DIMC / 128, MROWS / 128), 256, GB_SMEM>>>(
        af, wof, bo, out, MROWS, DIMC, K2DIM);
}

// round 17
// speedup vs baseline: 3.9579x; 1.0648x over previous
#include <cuda_runtime.h>
#include <cuda_bf16.h>
#include <cuda_fp16.h>
#include <math.h>
#include <stdint.h>

// Problem constants
#define DIMC   1152
#define NH     8
#define KVH    2
#define HD     144
#define BSZ    4
#define SEQ    2048
#define MROWS  (BSZ*SEQ)          // 8192
#define KVOUT  (2*KVH*HD)         // 576
#define NQKV   (DIMC + KVOUT)     // 1728
#define K2DIM  (DIMC/2)           // 576
#define KP     72                 // pairs per head row
#define TPH    (SEQ/2)            // seq pairs for V^T

// ---------------- scratch (device globals) ----------------------------------
__device__ float g_qkv [(size_t)MROWS * NQKV];      // fused Q|KV projection out

// GEMM operands: all single fp16
__device__ uint32_t g_xf [(size_t)MROWS * K2DIM];   // x fp16
__device__ uint32_t g_wc [(size_t)NQKV  * K2DIM];   // combined Wq|Wkv fp16
__device__ float    g_bc [NQKV];                    // combined bias
__device__ uint32_t g_wof[(size_t)DIMC  * K2DIM];   // Wo fp16
__device__ uint32_t g_af [(size_t)MROWS * K2DIM];   // attn out fp16 (flash writes)

// attention operands
__device__ uint32_t g_qf[(size_t)BSZ*NH *SEQ*KP];   // Q fp16 pairs
__device__ uint32_t g_kf[(size_t)BSZ*KVH*SEQ*KP];   // K fp16 pairs
__device__ uint32_t g_vf[(size_t)BSZ*KVH*HD*TPH];   // V^T fp16, pairs along s

// ---------------- helpers ----------------------------------------------------
__device__ __forceinline__ uint32_t smem_u32(const void* p) {
    uint32_t a;
    asm("{ .reg .u64 t; cvta.to.shared.u64 t, %1; cvt.u32.u64 %0, t; }"
        : "=r"(a) : "l"(p));
    return a;
}

__device__ __forceinline__ void mma16816h(float* c, const uint32_t* a, const uint32_t* b)
{
    asm volatile(
        "mma.sync.aligned.m16n8k16.row.col.f32.f16.f16.f32 "
        "{%0,%1,%2,%3}, {%4,%5,%6,%7}, {%8,%9}, {%0,%1,%2,%3};\n"
        : "+f"(c[0]), "+f"(c[1]), "+f"(c[2]), "+f"(c[3])
        : "r"(a[0]), "r"(a[1]), "r"(a[2]), "r"(a[3]), "r"(b[0]), "r"(b[1]));
}

__device__ __forceinline__ void ldsm4(uint32_t& r0, uint32_t& r1, uint32_t& r2,
                                      uint32_t& r3, uint32_t a)
{
    asm volatile("ldmatrix.sync.aligned.m8n8.x4.shared.b16 {%0,%1,%2,%3}, [%4];"
                 : "=r"(r0), "=r"(r1), "=r"(r2), "=r"(r3) : "r"(a));
}

#define CP_ASYNC16(sa, gp) \
    asm volatile("cp.async.cg.shared.global [%0], [%1], 16;" :: "r"(sa), "l"(gp))
#define CP_COMMIT() asm volatile("cp.async.commit_group;" ::: "memory")
#define CP_WAIT1()  asm volatile("cp.async.wait_group 1;" ::: "memory")
#define CP_WAIT0()  asm volatile("cp.async.wait_group 0;" ::: "memory")

// ---------------- prep kernels ----------------------------------------------
__global__ void conv_f16(const float* __restrict__ src, uint32_t* __restrict__ dst,
                         int n2)
{
    int i = blockIdx.x * blockDim.x + threadIdx.x;
    if (i >= n2) return;
    float2 v = ((const float2*)src)[i];
    __half2 h = __floats2half2_rn(v.x, v.y);
    dst[i] = *reinterpret_cast<uint32_t*>(&h);
}

__global__ void prep_weights(const float* __restrict__ wq,
                             const float* __restrict__ wkv,
                             const float* __restrict__ wo,
                             uint32_t* __restrict__ wc, uint32_t* __restrict__ wof)
{
    const int nq = DIMC * K2DIM;
    const int nk = KVOUT * K2DIM;
    int i = blockIdx.x * blockDim.x + threadIdx.x;
    float2 v;
    uint32_t* dst;
    if (i < nq) {
        v = ((const float2*)wq)[i];
        dst = wc + i;
    } else if (i < nq + nk) {
        v = ((const float2*)wkv)[i - nq];
        dst = wc + i;
    } else if (i < 2 * nq + nk) {
        v = ((const float2*)wo)[i - nq - nk];
        dst = wof + (i - nq - nk);
    } else return;
    __half2 h = __floats2half2_rn(v.x, v.y);
    *dst = *reinterpret_cast<uint32_t*>(&h);
}

__global__ void concat_bias(const float* __restrict__ bq, const float* __restrict__ bkv,
                            float* __restrict__ bc)
{
    int i = blockIdx.x * blockDim.x + threadIdx.x;
    if (i < DIMC) bc[i] = bq[i];
    else if (i < NQKV) bc[i] = bkv[i - DIMC];
}

// ---------------- fp16 1-pass GEMM (ldmatrix + cp.async, BK = 64 bf16) ------
#define GB_ROWB 144                   // 128 B data + 16 B pad
#define GB_ARR  (128 * GB_ROWB)       // 18432 B
#define GB_BUF  (2 * GB_ARR)          // A, B  = 36864 B
#define GB_SMEM (2 * GB_BUF)          // 73728 B

__global__ __launch_bounds__(256, 2)
void gemm_ldsm(const uint32_t* __restrict__ Ag, const uint32_t* __restrict__ Bg,
               const float* __restrict__ bias, float* __restrict__ C,
               int M, int N, int K2)
{
    extern __shared__ char smem[];
    const uint32_t sbase = smem_u32(smem);
    const int tid = threadIdx.x;
    const int warp = tid >> 5, lane = tid & 31;
    const int wm = (warp & 1) * 64;
    const int wn = (warp >> 1) * 32;
    const int m0 = blockIdx.y * 128;
    const int n0 = blockIdx.x * 128;
    const int nch = K2 / 32;          // chunks of 64 bf16 = 32 uint32

    // staging: thread -> rows {srow, +32, +64, +96}, 16B chunk = tid&7
    const int srow = tid >> 3;        // 0..31
    const int schk = tid & 7;         // 0..7

    float acc[4][4][4];
#pragma unroll
    for (int i = 0; i < 4; i++)
#pragma unroll
        for (int j = 0; j < 4; j++)
#pragma unroll
            for (int t = 0; t < 4; t++) acc[i][j][t] = 0.f;

    const int lrow = lane & 15;
    const int lch = lane >> 4;

#define GB_ISSUE(ch) do { \
    const uint32_t _sb = sbase + ((ch) & 1) * GB_BUF; \
    const size_t _kc = (size_t)(ch) * 32 + schk * 4; \
    _Pragma("unroll") \
    for (int _r4 = 0; _r4 < 4; _r4++) { \
        const int _r = srow + _r4 * 32; \
        const uint32_t _so = _sb + _r * GB_ROWB + schk * 16; \
        const int _br = (n0 + _r < N) ? n0 + _r : N - 1; \
        CP_ASYNC16(_so,           Ag + (size_t)(m0 + _r) * K2 + _kc); \
        CP_ASYNC16(_so + GB_ARR,  Bg + (size_t)_br * K2 + _kc); \
    } \
} while (0)

    GB_ISSUE(0); CP_COMMIT();

    for (int ch = 0; ch < nch; ch++) {
        if (ch + 1 < nch) { GB_ISSUE(ch + 1); CP_COMMIT(); CP_WAIT1(); }
        else              { CP_WAIT0(); }
        __syncthreads();

        const uint32_t sb = sbase + (ch & 1) * GB_BUF;
        const uint32_t aA = sb + (wm + lrow) * GB_ROWB + lch * 16;
        const uint32_t bB = sb + GB_ARR + (wn + lrow) * GB_ROWB + lch * 16;

#pragma unroll
        for (int kk = 0; kk < 4; kk++) {
            uint32_t bb[4][2];
#pragma unroll
            for (int jj = 0; jj < 2; jj++) {
                uint32_t r0, r1, r2, r3;
                ldsm4(r0, r1, r2, r3, bB + jj * (16 * GB_ROWB) + kk * 32);
                bb[2*jj][0] = r0; bb[2*jj][1] = r2;
                bb[2*jj+1][0] = r1; bb[2*jj+1][1] = r3;
            }
#pragma unroll
            for (int i = 0; i < 4; i++) {
                uint32_t ah[4];
                ldsm4(ah[0], ah[1], ah[2], ah[3], aA + i * (16 * GB_ROWB) + kk * 32);
#pragma unroll
                for (int j = 0; j < 4; j++)
                    mma16816h(acc[i][j], ah, bb[j]);
            }
        }
        __syncthreads();
    }

    const int lr = lane >> 2, lc = lane & 3;
#pragma unroll
    for (int i = 0; i < 4; i++) {
        int r0 = m0 + wm + i * 16 + lr;
#pragma unroll
        for (int j = 0; j < 4; j++) {
            int c0 = n0 + wn + j * 8 + lc * 2;
            if (c0 < N) {
                float2 bb = *(const float2*)&bias[c0];
                *(float2*)&C[(size_t)r0 * N + c0] =
                    make_float2(acc[i][j][0] + bb.x, acc[i][j][1] + bb.y);
                *(float2*)&C[(size_t)(r0 + 8) * N + c0] =
                    make_float2(acc[i][j][2] + bb.x, acc[i][j][3] + bb.y);
            }
        }
    }
#undef GB_ISSUE
}

// ---------------- RoPE Q+K merged -> fp16 ------------------------------------
__global__ void rope_qk_f16(const float* __restrict__ QKV,
                            const float* __restrict__ fc, const float* __restrict__ fs,
                            uint32_t* __restrict__ qf, uint32_t* __restrict__ kf)
{
    const int tq = BSZ * NH * SEQ * KP;
    const int tk = BSZ * KVH * SEQ * KP;
    int idx = blockIdx.x * blockDim.x + threadIdx.x;
    if (idx < tq) {
        int i = idx % KP;
        int s = (idx / KP) % SEQ;
        int h = (idx / (KP * SEQ)) % NH;
        int b = idx / (KP * SEQ * NH);
        size_t base = (size_t)(b * SEQ + s) * NQKV + h * HD;
        float q0 = QKV[base + 2 * i];
        float q1 = QKV[base + 2 * i + 1];
        float c = fc[s * KP + i];
        float sn = fs[s * KP + i];
        const float scale = 0.083333333333333329f;
        __half2 p = __floats2half2_rn((q0 * c - q1 * sn) * scale,
                                      (q0 * sn + q1 * c) * scale);
        qf[idx] = *reinterpret_cast<uint32_t*>(&p);
    } else if (idx < tq + tk) {
        int k = idx - tq;
        int i = k % KP;
        int s = (k / KP) % SEQ;
        int kvh = (k / (KP * SEQ)) % KVH;
        int b = k / (KP * SEQ * KVH);
        size_t base = (size_t)(b * SEQ + s) * NQKV + DIMC + kvh * HD;
        float k0 = QKV[base + 2 * i];
        float k1 = QKV[base + 2 * i + 1];
        float c = fc[s * KP + i];
        float sn = fs[s * KP + i];
        __half2 p = __floats2half2_rn(k0 * c - k1 * sn, k0 * sn + k1 * c);
        kf[k] = *reinterpret_cast<uint32_t*>(&p);
    }
}

// V transpose + fp16: out [b*KVH+kvh][d][sp], pairs along s.
__global__ void v_trans_f16(const float* __restrict__ QKV,
                            uint32_t* __restrict__ vf)
{
    __shared__ float tile[64][HD + 1];
    const int st = blockIdx.x;
    const int bk = blockIdx.y;
    const int b = bk / KVH, kvh = bk % KVH;
    const int tid = threadIdx.x;

    const float* src = QKV + (size_t)(b * SEQ + st * 64) * NQKV
                           + DIMC + KVH * HD + kvh * HD;
    for (int e = tid; e < 64 * HD; e += 256) {
        int r = e / HD, c = e % HD;
        tile[r][c] = src[(size_t)r * NQKV + c];
    }
    __syncthreads();

    uint32_t* ov = vf + ((size_t)bk * HD) * TPH + st * 32;
    for (int e = tid; e < HD * 32; e += 256) {
        int d = e / 32, sp = e % 32;
        __half2 p = __floats2half2_rn(tile[2 * sp][d], tile[2 * sp + 1][d]);
        ov[(size_t)d * TPH + sp] = *reinterpret_cast<uint32_t*>(&p);
    }
}

// ---------------- Flash attention (cp.async K/V pipeline) --------------------
#define QS 76
#define KS 76
#define VS 36
#define FL_KBUF (64 * KS)
#define FL_VBUF (HD * VS)

#define FLASH_SMEM ((128*QS + 2*FL_KBUF + 2*FL_VBUF) * (int)sizeof(uint32_t))

__global__ __launch_bounds__(256, 1)
void flash_mma(const uint32_t* __restrict__ qf, const uint32_t* __restrict__ kf,
               const uint32_t* __restrict__ vf,
               uint32_t* __restrict__ af)
{
    extern __shared__ uint32_t fsm[];
    uint32_t* sQ  = fsm;
    uint32_t* sKb = sQ + 128 * QS;
    uint32_t* sVb = sKb + 2 * FL_KBUF;
    const uint32_t sKbA = smem_u32(sKb);
    const uint32_t sVbA = smem_u32(sVb);

    const int qt = (gridDim.x - 1) - blockIdx.x;
    const int bh = blockIdx.y;
    const int b = bh >> 3;
    const int h = bh & 7;
    const int kvh = h >> 2;
    const int bk = b * KVH + kvh;

    const int tid = threadIdx.x;
    const int warp = tid >> 5, lane = tid & 31;
    const int lr = lane >> 2, lc = lane & 3;
    const int wm = warp * 16;

    const uint32_t* gkb = kf + (size_t)bk * SEQ * KP;
    const uint32_t* gvb = vf + (size_t)bk * HD * TPH;

#define FL_ISSUE(kt) do { \
    const uint32_t _kb = sKbA + (((kt) & 1) * FL_KBUF) * 4; \
    const uint32_t _vb = sVbA + (((kt) & 1) * FL_VBUF) * 4; \
    const uint32_t* _gk = gkb + (size_t)(kt) * 64 * KP; \
    for (int e = tid; e < 64 * 18; e += 256) { \
        int r = e / 18, c = (e % 18) * 4; \
        CP_ASYNC16(_kb + (r * KS + c) * 4, _gk + (size_t)r * KP + c); \
    } \
    const uint32_t* _gv = gvb + (size_t)(kt) * 32; \
    for (int e = tid; e < HD * 8; e += 256) { \
        int r = e / 8, c = (e % 8) * 4; \
        CP_ASYNC16(_vb + (r * VS + c) * 4, _gv + (size_t)r * TPH + c); \
    } \
} while (0)

    FL_ISSUE(0); CP_COMMIT();
    {
        const uint32_t* gq = qf + ((size_t)bh * SEQ + qt * 128) * KP;
        for (int e = tid; e < 128 * 18; e += 256) {
            int r = e / 18, c = (e % 18) * 4;
            *(uint4*)&sQ[r * QS + c] = *(const uint4*)&gq[(size_t)r * KP + c];
        }
    }

    float o[18][4];
#pragma unroll
    for (int n = 0; n < 18; n++)
#pragma unroll
        for (int t = 0; t < 4; t++) o[n][t] = 0.f;
    float m0 = -1e30f, m1 = -1e30f, l0 = 0.f, l1 = 0.f;

    const int ktmax = 2 * qt + 1;
    const int qrow0 = qt * 128 + wm;

    for (int kt = 0; kt <= ktmax; kt++) {
        if (kt < ktmax) { FL_ISSUE(kt + 1); CP_COMMIT(); CP_WAIT1(); }
        else            { CP_WAIT0(); }
        __syncthreads();

        uint32_t* sK = sKb + (kt & 1) * FL_KBUF;
        uint32_t* sV = sVb + (kt & 1) * FL_VBUF;

        float sfr[8][4];
#pragma unroll
        for (int j = 0; j < 8; j++)
#pragma unroll
            for (int t = 0; t < 4; t++) sfr[j][t] = 0.f;

#pragma unroll
        for (int kc = 0; kc < 9; kc++) {
            uint32_t ah[4];
            int ra = (wm + lr) * QS + kc * 8 + lc;
            int rb = (wm + lr + 8) * QS + kc * 8 + lc;
            ah[0] = sQ[ra];     ah[1] = sQ[rb];
            ah[2] = sQ[ra + 4]; ah[3] = sQ[rb + 4];
#pragma unroll
            for (int j = 0; j < 8; j++) {
                int rk = (j * 8 + lr) * KS + kc * 8 + lc;
                uint32_t bh2[2] = { sK[rk], sK[rk + 4] };
                mma16816h(sfr[j], ah, bh2);
            }
        }

        if (kt * 64 + 63 > qrow0) {
            int key0 = kt * 64;
#pragma unroll
            for (int j = 0; j < 8; j++) {
                int kc0 = key0 + j * 8 + 2 * lc;
                if (kc0     > qrow0 + lr)     sfr[j][0] = -1e9f;
                if (kc0 + 1 > qrow0 + lr)     sfr[j][1] = -1e9f;
                if (kc0     > qrow0 + lr + 8) sfr[j][2] = -1e9f;
                if (kc0 + 1 > qrow0 + lr + 8) sfr[j][3] = -1e9f;
            }
        }

        float mx0 = -1e30f, mx1 = -1e30f;
#pragma unroll
        for (int j = 0; j < 8; j++) {
            mx0 = fmaxf(mx0, fmaxf(sfr[j][0], sfr[j][1]));
            mx1 = fmaxf(mx1, fmaxf(sfr[j][2], sfr[j][3]));
        }
#pragma unroll
        for (int off = 1; off < 4; off <<= 1) {
            mx0 = fmaxf(mx0, __shfl_xor_sync(0xffffffffu, mx0, off));
            mx1 = fmaxf(mx1, __shfl_xor_sync(0xffffffffu, mx1, off));
        }
        float mn0 = fmaxf(m0, mx0), mn1 = fmaxf(m1, mx1);
        float c0 = __expf(m0 - mn0), c1 = __expf(m1 - mn1);
        m0 = mn0; m1 = mn1;

        float s0 = 0.f, s1 = 0.f;
#pragma unroll
        for (int j = 0; j < 8; j++) {
            sfr[j][0] = __expf(sfr[j][0] - m0);
            sfr[j][1] = __expf(sfr[j][1] - m0);
            sfr[j][2] = __expf(sfr[j][2] - m1);
            sfr[j][3] = __expf(sfr[j][3] - m1);
            s0 += sfr[j][0] + sfr[j][1];
            s1 += sfr[j][2] + sfr[j][3];
        }
#pragma unroll
        for (int off = 1; off < 4; off <<= 1) {
            s0 += __shfl_xor_sync(0xffffffffu, s0, off);
            s1 += __shfl_xor_sync(0xffffffffu, s1, off);
        }
        l0 = l0 * c0 + s0;
        l1 = l1 * c1 + s1;

#pragma unroll
        for (int n = 0; n < 18; n++) {
            o[n][0] *= c0; o[n][1] *= c0;
            o[n][2] *= c1; o[n][3] *= c1;
        }

        uint32_t ph01[8], ph23[8];
#pragma unroll
        for (int j = 0; j < 8; j++) {
            __half2 p0 = __floats2half2_rn(sfr[j][0], sfr[j][1]);
            __half2 p1 = __floats2half2_rn(sfr[j][2], sfr[j][3]);
            ph01[j] = *reinterpret_cast<uint32_t*>(&p0);
            ph23[j] = *reinterpret_cast<uint32_t*>(&p1);
        }

#pragma unroll
        for (int kc = 0; kc < 4; kc++) {
            uint32_t pa[4] = { ph01[2*kc], ph23[2*kc], ph01[2*kc+1], ph23[2*kc+1] };
#pragma unroll
            for (int n = 0; n < 18; n++) {
                int rv = (n * 8 + lr) * VS + kc * 8 + lc;
                uint32_t bv[2] = { sV[rv], sV[rv + 4] };
                mma16816h(o[n], pa, bv);
            }
        }
        __syncthreads();
    }

    float inv0 = 1.f / l0, inv1 = 1.f / l1;
    int r0 = qt * 128 + wm + lr;
    uint32_t* arow0 = af + (size_t)(b * SEQ + r0)     * K2DIM + h * KP;
    uint32_t* arow1 = af + (size_t)(b * SEQ + r0 + 8) * K2DIM + h * KP;
#pragma unroll
    for (int n = 0; n < 18; n++) {
        int cp = n * 4 + lc;
        __half2 v0 = __floats2half2_rn(o[n][0] * inv0, o[n][1] * inv0);
        __half2 v1 = __floats2half2_rn(o[n][2] * inv1, o[n][3] * inv1);
        arow0[cp] = *reinterpret_cast<uint32_t*>(&v0);
        arow1[cp] = *reinterpret_cast<uint32_t*>(&v1);
    }
#undef FL_ISSUE
}

// ---------------- launcher --------------------------------------------------
extern "C" void kernel_launch(void* const* d_in, const int* in_sizes, int n_in,
                              void* d_out, int out_size)
{
    const float* x   = (const float*)d_in[0];
    const float* wq  = (const float*)d_in[1];
    const float* bq  = (const float*)d_in[2];
    const float* wkv = (const float*)d_in[3];
    const float* bkv = (const float*)d_in[4];
    const float* wo  = (const float*)d_in[5];
    const float* bo  = (const float*)d_in[6];
    const float* fc  = (const float*)d_in[7];
    const float* fs  = (const float*)d_in[8];
    float* out = (float*)d_out;

    float *gqkv, *bc;
    uint32_t *xf, *wc, *wof, *af;
    uint32_t *qf, *kf, *vf;
    cudaGetSymbolAddress((void**)&gqkv, g_qkv);
    cudaGetSymbolAddress((void**)&bc,   g_bc);
    cudaGetSymbolAddress((void**)&xf,   g_xf);
    cudaGetSymbolAddress((void**)&wc,   g_wc);
    cudaGetSymbolAddress((void**)&wof,  g_wof);
    cudaGetSymbolAddress((void**)&af,   g_af);
    cudaGetSymbolAddress((void**)&qf,   g_qf);
    cudaGetSymbolAddress((void**)&kf,   g_kf);
    cudaGetSymbolAddress((void**)&vf,   g_vf);

    cudaFuncSetAttribute(flash_mma, cudaFuncAttributeMaxDynamicSharedMemorySize,
                         FLASH_SMEM);
    cudaFuncSetAttribute(gemm_ldsm, cudaFuncAttributeMaxDynamicSharedMemorySize,
                         GB_SMEM);

    // prep
    {
        int nx = MROWS * K2DIM;
        conv_f16<<<(nx + 255) / 256, 256>>>(x, xf, nx);
        int nw = (2 * DIMC + KVOUT) * K2DIM;
        prep_weights<<<(nw + 255) / 256, 256>>>(wq, wkv, wo, wc, wof);
        concat_bias<<<(NQKV + 255) / 256, 256>>>(bq, bkv, bc);
    }

    // fused Q|KV projection
    gemm_ldsm<<<dim3((NQKV + 127) / 128, MROWS / 128), 256, GB_SMEM>>>(
        xf, wc, bc, gqkv, MROWS, NQKV, K2DIM);

    // RoPE Q+K merged, V transpose
    {
        int t = BSZ * NH * SEQ * KP + BSZ * KVH * SEQ * KP;
        rope_qk_f16<<<(t + 255) / 256, 256>>>(gqkv, fc, fs, qf, kf);
        v_trans_f16<<<dim3(SEQ / 64, BSZ * KVH), 256>>>(gqkv, vf);
    }

    // attention
    flash_mma<<<dim3(SEQ / 128, BSZ * NH), 256, FLASH_SMEM>>>(qf, kf, vf, af);

    // output projection
    gemm_ldsm<<<dim3(DIMC / 128, MROWS / 128), 256, GB_SMEM>>>(
        af, wof, bo, out, MROWS, DIMC, K2DIM);
}